// round 2
// baseline (speedup 1.0000x reference)
#include <cuda_runtime.h>
#include <math.h>

// ---------------------------------------------------------------------------
// Problem constants
// ---------------------------------------------------------------------------
#define BATCH   2
#define SEQ     2048
#define DMODEL  1024
#define HEADS   16
#define DHEAD   64
#define INNER   (HEADS * DHEAD)      // 1024
#define ROWS    (BATCH * SEQ)        // 4096
#define ATTN_EPS 1e-8f

// Scratch (device globals: allowed; runtime alloc is not)
__device__ float g_q  [ROWS * INNER];        // 16 MB
__device__ float g_kv [ROWS * 2 * INNER];    // 32 MB
__device__ float g_att[ROWS * INNER];        // 16 MB

// ---------------------------------------------------------------------------
// SGEMM: C[M,N] = A[M,K] @ B[K,N] (+ bias[N] if bias != nullptr)
// 128x128 block, BK=8, 8x8 microtile, 256 threads.
// ---------------------------------------------------------------------------
__global__ __launch_bounds__(256)
void sgemm_kernel(const float* __restrict__ A, const float* __restrict__ B,
                  const float* __restrict__ bias, float* __restrict__ C,
                  int M, int N, int K)
{
    __shared__ float As[8][132];   // transposed A tile, padded
    __shared__ float Bs[8][128];

    const int tid = threadIdx.x;
    const int tx = tid & 15;            // 0..15 -> 8 cols each
    const int ty = tid >> 4;            // 0..15 -> 8 rows each
    const int blockRow = blockIdx.y * 128;
    const int blockCol = blockIdx.x * 128;

    const int arow = tid >> 1;          // 0..127
    const int acol = (tid & 1) * 4;     // 0 or 4
    const int brow = tid >> 5;          // 0..7
    const int bcol = (tid & 31) * 4;    // 0..124

    float acc[8][8];
    #pragma unroll
    for (int i = 0; i < 8; i++)
        #pragma unroll
        for (int j = 0; j < 8; j++) acc[i][j] = 0.f;

    for (int k0 = 0; k0 < K; k0 += 8) {
        float4 av = *(const float4*)(A + (size_t)(blockRow + arow) * K + k0 + acol);
        float4 bv = *(const float4*)(B + (size_t)(k0 + brow) * N + blockCol + bcol);
        As[acol + 0][arow] = av.x;
        As[acol + 1][arow] = av.y;
        As[acol + 2][arow] = av.z;
        As[acol + 3][arow] = av.w;
        *(float4*)&Bs[brow][bcol] = bv;
        __syncthreads();

        #pragma unroll
        for (int kk = 0; kk < 8; kk++) {
            float rm[8], rn[8];
            *(float4*)&rm[0] = *(const float4*)&As[kk][ty * 8];
            *(float4*)&rm[4] = *(const float4*)&As[kk][ty * 8 + 4];
            *(float4*)&rn[0] = *(const float4*)&Bs[kk][tx * 8];
            *(float4*)&rn[4] = *(const float4*)&Bs[kk][tx * 8 + 4];
            #pragma unroll
            for (int i = 0; i < 8; i++)
                #pragma unroll
                for (int j = 0; j < 8; j++)
                    acc[i][j] += rm[i] * rn[j];
        }
        __syncthreads();
    }

    #pragma unroll
    for (int i = 0; i < 8; i++) {
        const int row = blockRow + ty * 8 + i;
        #pragma unroll
        for (int j4 = 0; j4 < 8; j4 += 4) {
            const int col = blockCol + tx * 8 + j4;
            float4 r;
            r.x = acc[i][j4 + 0];
            r.y = acc[i][j4 + 1];
            r.z = acc[i][j4 + 2];
            r.w = acc[i][j4 + 3];
            if (bias) {
                r.x += bias[col + 0];
                r.y += bias[col + 1];
                r.z += bias[col + 2];
                r.w += bias[col + 3];
            }
            *(float4*)(C + (size_t)row * N + col) = r;
        }
    }
}

// ---------------------------------------------------------------------------
// Flash-style causal attention with UNMASKED row max (matches reference gm):
//   m = running max over raw scores for ALL j; p = exp(s - m) with causal mask;
//   out = (sum p*v) / (sum p + eps)
// Grid: (SEQ/128, BATCH*HEADS). 128 threads: 16x8 thread grid, 8x8 microtiles.
// Br = 128 query rows, Bc = 64 key rows per tile.
// ---------------------------------------------------------------------------
#define ATTN_SMEM_FLOATS (64*128 + 64*64 + 64*64 + 128*65)
#define ATTN_SMEM_BYTES  (ATTN_SMEM_FLOATS * 4)

__global__ __launch_bounds__(128, 2)
void attn_kernel(const float* __restrict__ gq, const float* __restrict__ gkv,
                 float* __restrict__ gout)
{
    extern __shared__ float sm[];
    float* Qst = sm;                 // [64][128]  d-major, swizzled cols
    float* Kst = Qst + 64 * 128;     // [64][64]   d-major, swizzled cols
    float* Vs  = Kst + 64 * 64;      // [64][64]   row-major (j, d)
    float* Ps  = Vs  + 64 * 64;      // [128][65]  P, 3-bit-swapped col layout

    const int tid = threadIdx.x;
    const int tr = tid >> 3;         // 0..15 : owns rows tr*8 .. tr*8+7
    const int tc = tid & 7;          // 0..7  : owns cols tc*8 .. tc*8+7
    const int b  = blockIdx.y >> 4;
    const int h  = blockIdx.y & 15;
    const int qstart = blockIdx.x * 128;

    const float* qbase = gq  + ((size_t)b * SEQ + qstart) * INNER + h * DHEAD;
    const float* kvb   = gkv + (size_t)b * SEQ * (2 * INNER) + h * DHEAD;

    // ---- load Q tile (scaled by Dh^-0.5 = 0.125), transposed + swizzled ----
    #pragma unroll
    for (int it = 0; it < 16; it++) {
        int id  = tid + it * 128;        // 0..2047
        int d4  = id & 15;
        int row = id >> 4;               // 0..127
        float4 v = *(const float4*)(qbase + (size_t)row * INNER + d4 * 4);
        int sw = (d4 & 7) << 3;
        int pr = row ^ sw;
        Qst[(4 * d4 + 0) * 128 + pr] = v.x * 0.125f;
        Qst[(4 * d4 + 1) * 128 + pr] = v.y * 0.125f;
        Qst[(4 * d4 + 2) * 128 + pr] = v.z * 0.125f;
        Qst[(4 * d4 + 3) * 128 + pr] = v.w * 0.125f;
    }

    float o[8][8];
    float m[8], l[8];
    #pragma unroll
    for (int i = 0; i < 8; i++) {
        m[i] = -INFINITY; l[i] = 0.f;
        #pragma unroll
        for (int j = 0; j < 8; j++) o[i][j] = 0.f;
    }

    for (int jt = 0; jt < 32; jt++) {
        const int jstart = jt * 64;
        __syncthreads();   // previous tile's reads of Kst/Vs/Ps done

        // ---- load K (transposed+swizzled) and V (row-major) tiles ----
        #pragma unroll
        for (int it = 0; it < 8; it++) {
            int id = tid + it * 128;     // 0..1023
            int d4 = id & 15;
            int j  = id >> 4;            // 0..63
            const float* src = kvb + (size_t)(jstart + j) * (2 * INNER) + d4 * 4;
            float4 k4 = *(const float4*)(src);
            float4 v4 = *(const float4*)(src + INNER);
            int sw = (d4 & 7) << 3;
            int pj = j ^ sw;
            Kst[(4 * d4 + 0) * 64 + pj] = k4.x;
            Kst[(4 * d4 + 1) * 64 + pj] = k4.y;
            Kst[(4 * d4 + 2) * 64 + pj] = k4.z;
            Kst[(4 * d4 + 3) * 64 + pj] = k4.w;
            *(float4*)(Vs + j * 64 + d4 * 4) = v4;
        }
        __syncthreads();

        // ---- S = Q @ K^T, 8x8 frag per thread ----
        float s[8][8];
        #pragma unroll
        for (int i = 0; i < 8; i++)
            #pragma unroll
            for (int j = 0; j < 8; j++) s[i][j] = 0.f;

        #pragma unroll 4
        for (int d = 0; d < 64; d++) {
            int sw = ((d >> 2) & 7) << 3;
            int qb = (tr * 8) ^ sw;
            int kb = (tc * 8) ^ sw;
            float qv[8], kv[8];
            *(float4*)&qv[0] = *(const float4*)&Qst[d * 128 + qb];
            *(float4*)&qv[4] = *(const float4*)&Qst[d * 128 + qb + 4];
            *(float4*)&kv[0] = *(const float4*)&Kst[d * 64 + kb];
            *(float4*)&kv[4] = *(const float4*)&Kst[d * 64 + kb + 4];
            #pragma unroll
            for (int i = 0; i < 8; i++)
                #pragma unroll
                for (int j = 0; j < 8; j++)
                    s[i][j] += qv[i] * kv[j];
        }

        // ---- online softmax stats (max over raw UNMASKED scores) ----
        float al[8];
        #pragma unroll
        for (int i = 0; i < 8; i++) {
            float mx = s[i][0];
            #pragma unroll
            for (int j = 1; j < 8; j++) mx = fmaxf(mx, s[i][j]);
            #pragma unroll
            for (int off = 1; off < 8; off <<= 1)
                mx = fmaxf(mx, __shfl_xor_sync(0xffffffffu, mx, off));
            float mn = fmaxf(m[i], mx);
            al[i] = __expf(m[i] - mn);
            m[i]  = mn;
        }

        const bool active = (jstart <= qstart + 127);  // uniform over block

        if (active) {
            const int ig0 = qstart + tr * 8;
            const int jg0 = jstart + tc * 8;
            #pragma unroll
            for (int i = 0; i < 8; i++) {
                float r = 0.f;
                #pragma unroll
                for (int j = 0; j < 8; j++) {
                    float p = (jg0 + j <= ig0 + i) ? __expf(s[i][j] - m[i]) : 0.f;
                    s[i][j] = p;
                    r += p;
                }
                #pragma unroll
                for (int off = 1; off < 8; off <<= 1)
                    r += __shfl_xor_sync(0xffffffffu, r, off);
                l[i] = l[i] * al[i] + r;
            }
        } else {
            #pragma unroll
            for (int i = 0; i < 8; i++) l[i] *= al[i];
        }

        #pragma unroll
        for (int i = 0; i < 8; i++)
            #pragma unroll
            for (int j = 0; j < 8; j++)
                o[i][j] *= al[i];

        if (active) {
            // store P frag; physical col = ((c&7)<<3)|(c>>3), c = tc*8+j
            #pragma unroll
            for (int i = 0; i < 8; i++)
                #pragma unroll
                for (int j = 0; j < 8; j++)
                    Ps[(tr * 8 + i) * 65 + (j * 8 + tc)] = s[i][j];
            __syncthreads();

            // ---- O += P @ V ----
            #pragma unroll 2
            for (int jj = 0; jj < 64; jj++) {
                int pj = ((jj & 7) << 3) | (jj >> 3);
                float pv[8];
                #pragma unroll
                for (int i = 0; i < 8; i++)
                    pv[i] = Ps[(tr * 8 + i) * 65 + pj];
                float vv[8];
                *(float4*)&vv[0] = *(const float4*)&Vs[jj * 64 + tc * 8];
                *(float4*)&vv[4] = *(const float4*)&Vs[jj * 64 + tc * 8 + 4];
                #pragma unroll
                for (int i = 0; i < 8; i++)
                    #pragma unroll
                    for (int j = 0; j < 8; j++)
                        o[i][j] += pv[i] * vv[j];
            }
        }
    }

    // ---- epilogue: divide by (l + eps), write (b, n, h*Dh + d) ----
    float* ob = gout + ((size_t)b * SEQ + qstart + tr * 8) * INNER + h * DHEAD + tc * 8;
    #pragma unroll
    for (int i = 0; i < 8; i++) {
        float inv = 1.0f / (l[i] + ATTN_EPS);
        float4 r0, r1;
        r0.x = o[i][0] * inv; r0.y = o[i][1] * inv;
        r0.z = o[i][2] * inv; r0.w = o[i][3] * inv;
        r1.x = o[i][4] * inv; r1.y = o[i][5] * inv;
        r1.z = o[i][6] * inv; r1.w = o[i][7] * inv;
        *(float4*)(ob + (size_t)i * INNER)     = r0;
        *(float4*)(ob + (size_t)i * INNER + 4) = r1;
    }
}

// ---------------------------------------------------------------------------
// Launch
// ---------------------------------------------------------------------------
extern "C" void kernel_launch(void* const* d_in, const int* in_sizes, int n_in,
                              void* d_out, int out_size)
{
    const float* x   = (const float*)d_in[0];
    const float* Wq  = (const float*)d_in[1];
    const float* Wkv = (const float*)d_in[2];
    const float* Wo  = (const float*)d_in[3];
    const float* bo  = (const float*)d_in[4];
    float* out = (float*)d_out;

    float *pq, *pkv, *patt;
    cudaGetSymbolAddress((void**)&pq,   g_q);
    cudaGetSymbolAddress((void**)&pkv,  g_kv);
    cudaGetSymbolAddress((void**)&patt, g_att);

    cudaFuncSetAttribute(attn_kernel,
                         cudaFuncAttributeMaxDynamicSharedMemorySize,
                         ATTN_SMEM_BYTES);

    // q = x @ Wq   (4096x1024 @ 1024x1024)
    sgemm_kernel<<<dim3(INNER / 128, ROWS / 128), 256>>>(
        x, Wq, nullptr, pq, ROWS, INNER, DMODEL);

    // kv = x @ Wkv (4096x1024 @ 1024x2048)
    sgemm_kernel<<<dim3(2 * INNER / 128, ROWS / 128), 256>>>(
        x, Wkv, nullptr, pkv, ROWS, 2 * INNER, DMODEL);

    // attention -> g_att (b, n, h*dh)
    attn_kernel<<<dim3(SEQ / 128, BATCH * HEADS), 128, ATTN_SMEM_BYTES>>>(
        pq, pkv, patt);

    // out = att @ Wo + bo
    sgemm_kernel<<<dim3(DMODEL / 128, ROWS / 128), 256>>>(
        patt, Wo, bo, out, ROWS, DMODEL, INNER);
}

// round 3
// speedup vs baseline: 1.0537x; 1.0537x over previous
#include <cuda_runtime.h>
#include <math.h>

// ---------------------------------------------------------------------------
// Problem constants
// ---------------------------------------------------------------------------
#define BATCH   2
#define SEQ     2048
#define DMODEL  1024
#define HEADS   16
#define DHEAD   64
#define INNER   (HEADS * DHEAD)      // 1024
#define ROWS    (BATCH * SEQ)        // 4096
#define ATTN_EPS 1e-8f

// Scratch (device globals: allowed; runtime alloc is not)
__device__ float g_q  [ROWS * INNER];        // 16 MB
__device__ float g_kv [ROWS * 2 * INNER];    // 32 MB
__device__ float g_att[ROWS * INNER];        // 16 MB

// ---------------------------------------------------------------------------
// SGEMM: C[M,N] = A[M,K] @ B[K,N] (+ bias[N] if bias != nullptr)
// 128x128 block, BK=8, 8x8 microtile, 256 threads.
// ---------------------------------------------------------------------------
__global__ __launch_bounds__(256)
void sgemm_kernel(const float* __restrict__ A, const float* __restrict__ B,
                  const float* __restrict__ bias, float* __restrict__ C,
                  int M, int N, int K)
{
    __shared__ float As[8][132];   // transposed A tile, padded
    __shared__ float Bs[8][128];

    const int tid = threadIdx.x;
    const int tx = tid & 15;            // 0..15 -> 8 cols each
    const int ty = tid >> 4;            // 0..15 -> 8 rows each
    const int blockRow = blockIdx.y * 128;
    const int blockCol = blockIdx.x * 128;

    const int arow = tid >> 1;          // 0..127
    const int acol = (tid & 1) * 4;     // 0 or 4
    const int brow = tid >> 5;          // 0..7
    const int bcol = (tid & 31) * 4;    // 0..124

    float acc[8][8];
    #pragma unroll
    for (int i = 0; i < 8; i++)
        #pragma unroll
        for (int j = 0; j < 8; j++) acc[i][j] = 0.f;

    for (int k0 = 0; k0 < K; k0 += 8) {
        float4 av = *(const float4*)(A + (size_t)(blockRow + arow) * K + k0 + acol);
        float4 bv = *(const float4*)(B + (size_t)(k0 + brow) * N + blockCol + bcol);
        As[acol + 0][arow] = av.x;
        As[acol + 1][arow] = av.y;
        As[acol + 2][arow] = av.z;
        As[acol + 3][arow] = av.w;
        *(float4*)&Bs[brow][bcol] = bv;
        __syncthreads();

        #pragma unroll
        for (int kk = 0; kk < 8; kk++) {
            float rm[8], rn[8];
            *(float4*)&rm[0] = *(const float4*)&As[kk][ty * 8];
            *(float4*)&rm[4] = *(const float4*)&As[kk][ty * 8 + 4];
            *(float4*)&rn[0] = *(const float4*)&Bs[kk][tx * 8];
            *(float4*)&rn[4] = *(const float4*)&Bs[kk][tx * 8 + 4];
            #pragma unroll
            for (int i = 0; i < 8; i++)
                #pragma unroll
                for (int j = 0; j < 8; j++)
                    acc[i][j] += rm[i] * rn[j];
        }
        __syncthreads();
    }

    #pragma unroll
    for (int i = 0; i < 8; i++) {
        const int row = blockRow + ty * 8 + i;
        #pragma unroll
        for (int j4 = 0; j4 < 8; j4 += 4) {
            const int col = blockCol + tx * 8 + j4;
            float4 r;
            r.x = acc[i][j4 + 0];
            r.y = acc[i][j4 + 1];
            r.z = acc[i][j4 + 2];
            r.w = acc[i][j4 + 3];
            if (bias) {
                r.x += bias[col + 0];
                r.y += bias[col + 1];
                r.z += bias[col + 2];
                r.w += bias[col + 3];
            }
            *(float4*)(C + (size_t)row * N + col) = r;
        }
    }
}

// ---------------------------------------------------------------------------
// Flash-style causal attention with UNMASKED row max (matches reference gm):
//   m = running max over raw scores for ALL j; p = exp(s - m) with causal mask;
//   out = (sum p*v) / (sum p + eps)
// Grid: (SEQ/128, BATCH*HEADS). 128 threads: 16x8 thread grid, 8x8 microtiles.
// Br = 128 query rows, Bc = 64 key rows per tile.
// ---------------------------------------------------------------------------
#define ATTN_SMEM_FLOATS (64*128 + 64*64 + 64*64 + 128*65)
#define ATTN_SMEM_BYTES  (ATTN_SMEM_FLOATS * 4)

__global__ __launch_bounds__(128, 2)
void attn_kernel(const float* __restrict__ gq, const float* __restrict__ gkv,
                 float* __restrict__ gout)
{
    extern __shared__ float sm[];
    float* Qst = sm;                 // [64][128]  d-major, swizzled cols
    float* Kst = Qst + 64 * 128;     // [64][64]   d-major, swizzled cols
    float* Vs  = Kst + 64 * 64;      // [64][64]   row-major (j, d)
    float* Ps  = Vs  + 64 * 64;      // [128][65]  P, 3-bit-swapped col layout

    const int tid = threadIdx.x;
    const int tr = tid >> 3;         // 0..15 : owns rows tr*8 .. tr*8+7
    const int tc = tid & 7;          // 0..7  : owns cols tc*8 .. tc*8+7
    const int b  = blockIdx.y >> 4;
    const int h  = blockIdx.y & 15;
    const int qstart = blockIdx.x * 128;

    const float* qbase = gq  + ((size_t)b * SEQ + qstart) * INNER + h * DHEAD;
    const float* kvb   = gkv + (size_t)b * SEQ * (2 * INNER) + h * DHEAD;

    // ---- load Q tile (scaled by Dh^-0.5 = 0.125), transposed + swizzled ----
    #pragma unroll
    for (int it = 0; it < 16; it++) {
        int id  = tid + it * 128;        // 0..2047
        int d4  = id & 15;
        int row = id >> 4;               // 0..127
        float4 v = *(const float4*)(qbase + (size_t)row * INNER + d4 * 4);
        int sw = (d4 & 7) << 3;
        int pr = row ^ sw;
        Qst[(4 * d4 + 0) * 128 + pr] = v.x * 0.125f;
        Qst[(4 * d4 + 1) * 128 + pr] = v.y * 0.125f;
        Qst[(4 * d4 + 2) * 128 + pr] = v.z * 0.125f;
        Qst[(4 * d4 + 3) * 128 + pr] = v.w * 0.125f;
    }

    float o[8][8];
    float m[8], l[8];
    #pragma unroll
    for (int i = 0; i < 8; i++) {
        m[i] = -INFINITY; l[i] = 0.f;
        #pragma unroll
        for (int j = 0; j < 8; j++) o[i][j] = 0.f;
    }

    for (int jt = 0; jt < 32; jt++) {
        const int jstart = jt * 64;
        __syncthreads();   // previous tile's reads of Kst/Vs/Ps done

        // ---- load K (transposed+swizzled) and V (row-major) tiles ----
        #pragma unroll
        for (int it = 0; it < 8; it++) {
            int id = tid + it * 128;     // 0..1023
            int d4 = id & 15;
            int j  = id >> 4;            // 0..63
            const float* src = kvb + (size_t)(jstart + j) * (2 * INNER) + d4 * 4;
            float4 k4 = *(const float4*)(src);
            float4 v4 = *(const float4*)(src + INNER);
            int sw = (d4 & 7) << 3;
            int pj = j ^ sw;
            Kst[(4 * d4 + 0) * 64 + pj] = k4.x;
            Kst[(4 * d4 + 1) * 64 + pj] = k4.y;
            Kst[(4 * d4 + 2) * 64 + pj] = k4.z;
            Kst[(4 * d4 + 3) * 64 + pj] = k4.w;
            *(float4*)(Vs + j * 64 + d4 * 4) = v4;
        }
        __syncthreads();

        // ---- S = Q @ K^T, 8x8 frag per thread ----
        float s[8][8];
        #pragma unroll
        for (int i = 0; i < 8; i++)
            #pragma unroll
            for (int j = 0; j < 8; j++) s[i][j] = 0.f;

        #pragma unroll 4
        for (int d = 0; d < 64; d++) {
            int sw = ((d >> 2) & 7) << 3;
            int qb = (tr * 8) ^ sw;
            int kb = (tc * 8) ^ sw;
            float qv[8], kv[8];
            *(float4*)&qv[0] = *(const float4*)&Qst[d * 128 + qb];
            *(float4*)&qv[4] = *(const float4*)&Qst[d * 128 + qb + 4];
            *(float4*)&kv[0] = *(const float4*)&Kst[d * 64 + kb];
            *(float4*)&kv[4] = *(const float4*)&Kst[d * 64 + kb + 4];
            #pragma unroll
            for (int i = 0; i < 8; i++)
                #pragma unroll
                for (int j = 0; j < 8; j++)
                    s[i][j] += qv[i] * kv[j];
        }

        // ---- online softmax stats (max over raw UNMASKED scores) ----
        float al[8];
        #pragma unroll
        for (int i = 0; i < 8; i++) {
            float mx = s[i][0];
            #pragma unroll
            for (int j = 1; j < 8; j++) mx = fmaxf(mx, s[i][j]);
            #pragma unroll
            for (int off = 1; off < 8; off <<= 1)
                mx = fmaxf(mx, __shfl_xor_sync(0xffffffffu, mx, off));
            float mn = fmaxf(m[i], mx);
            al[i] = __expf(m[i] - mn);
            m[i]  = mn;
        }

        const bool active = (jstart <= qstart + 127);  // uniform over block

        if (active) {
            const int ig0 = qstart + tr * 8;
            const int jg0 = jstart + tc * 8;
            #pragma unroll
            for (int i = 0; i < 8; i++) {
                float r = 0.f;
                #pragma unroll
                for (int j = 0; j < 8; j++) {
                    float p = (jg0 + j <= ig0 + i) ? __expf(s[i][j] - m[i]) : 0.f;
                    s[i][j] = p;
                    r += p;
                }
                #pragma unroll
                for (int off = 1; off < 8; off <<= 1)
                    r += __shfl_xor_sync(0xffffffffu, r, off);
                l[i] = l[i] * al[i] + r;
            }
        } else {
            #pragma unroll
            for (int i = 0; i < 8; i++) l[i] *= al[i];
        }

        #pragma unroll
        for (int i = 0; i < 8; i++)
            #pragma unroll
            for (int j = 0; j < 8; j++)
                o[i][j] *= al[i];

        if (active) {
            // store P frag; physical col = ((c&7)<<3)|(c>>3), c = tc*8+j
            #pragma unroll
            for (int i = 0; i < 8; i++)
                #pragma unroll
                for (int j = 0; j < 8; j++)
                    Ps[(tr * 8 + i) * 65 + (j * 8 + tc)] = s[i][j];
            __syncthreads();

            // ---- O += P @ V ----
            #pragma unroll 2
            for (int jj = 0; jj < 64; jj++) {
                int pj = ((jj & 7) << 3) | (jj >> 3);
                float pv[8];
                #pragma unroll
                for (int i = 0; i < 8; i++)
                    pv[i] = Ps[(tr * 8 + i) * 65 + pj];
                float vv[8];
                *(float4*)&vv[0] = *(const float4*)&Vs[jj * 64 + tc * 8];
                *(float4*)&vv[4] = *(const float4*)&Vs[jj * 64 + tc * 8 + 4];
                #pragma unroll
                for (int i = 0; i < 8; i++)
                    #pragma unroll
                    for (int j = 0; j < 8; j++)
                        o[i][j] += pv[i] * vv[j];
            }
        }
    }

    // ---- epilogue: divide by (l + eps), write (b, n, h*Dh + d) ----
    float* ob = gout + ((size_t)b * SEQ + qstart + tr * 8) * INNER + h * DHEAD + tc * 8;
    #pragma unroll
    for (int i = 0; i < 8; i++) {
        float inv = 1.0f / (l[i] + ATTN_EPS);
        float4 r0, r1;
        r0.x = o[i][0] * inv; r0.y = o[i][1] * inv;
        r0.z = o[i][2] * inv; r0.w = o[i][3] * inv;
        r1.x = o[i][4] * inv; r1.y = o[i][5] * inv;
        r1.z = o[i][6] * inv; r1.w = o[i][7] * inv;
        *(float4*)(ob + (size_t)i * INNER)     = r0;
        *(float4*)(ob + (size_t)i * INNER + 4) = r1;
    }
}

// ---------------------------------------------------------------------------
// Launch
// ---------------------------------------------------------------------------
extern "C" void kernel_launch(void* const* d_in, const int* in_sizes, int n_in,
                              void* d_out, int out_size)
{
    const float* x   = (const float*)d_in[0];
    const float* Wq  = (const float*)d_in[1];
    const float* Wkv = (const float*)d_in[2];
    const float* Wo  = (const float*)d_in[3];
    const float* bo  = (const float*)d_in[4];
    float* out = (float*)d_out;

    float *pq, *pkv, *patt;
    cudaGetSymbolAddress((void**)&pq,   g_q);
    cudaGetSymbolAddress((void**)&pkv,  g_kv);
    cudaGetSymbolAddress((void**)&patt, g_att);

    cudaFuncSetAttribute(attn_kernel,
                         cudaFuncAttributeMaxDynamicSharedMemorySize,
                         ATTN_SMEM_BYTES);

    // q = x @ Wq   (4096x1024 @ 1024x1024)
    sgemm_kernel<<<dim3(INNER / 128, ROWS / 128), 256>>>(
        x, Wq, nullptr, pq, ROWS, INNER, DMODEL);

    // kv = x @ Wkv (4096x1024 @ 1024x2048)
    sgemm_kernel<<<dim3(2 * INNER / 128, ROWS / 128), 256>>>(
        x, Wkv, nullptr, pkv, ROWS, 2 * INNER, DMODEL);

    // attention -> g_att (b, n, h*dh)
    attn_kernel<<<dim3(SEQ / 128, BATCH * HEADS), 128, ATTN_SMEM_BYTES>>>(
        pq, pkv, patt);

    // out = att @ Wo + bo
    sgemm_kernel<<<dim3(DMODEL / 128, ROWS / 128), 256>>>(
        patt, Wo, bo, out, ROWS, DMODEL, INNER);
}

// round 5
// speedup vs baseline: 1.3921x; 1.3212x over previous
#include <cuda_runtime.h>
#include <cuda_bf16.h>
#include <math.h>
#include <stdint.h>

// ---------------------------------------------------------------------------
// Problem constants
// ---------------------------------------------------------------------------
#define BATCH   2
#define SEQ     2048
#define DMODEL  1024
#define HEADS   16
#define DHEAD   64
#define INNER   (HEADS * DHEAD)      // 1024
#define ROWS    (BATCH * SEQ)        // 4096
#define ATTN_EPS 1e-8f

// ---------------------------------------------------------------------------
// Scratch (device globals: allowed; runtime alloc is not)
// ---------------------------------------------------------------------------
__device__ float g_q  [ROWS * INNER];            // 16 MB
__device__ float g_kv [ROWS * 2 * INNER];        // 32 MB

__device__ __nv_bfloat16 g_xh  [ROWS * DMODEL];
__device__ __nv_bfloat16 g_xl  [ROWS * DMODEL];
__device__ __nv_bfloat16 g_wqt_h [INNER * DMODEL];       // Wq^T  [N,K]
__device__ __nv_bfloat16 g_wqt_l [INNER * DMODEL];
__device__ __nv_bfloat16 g_wkvt_h[2 * INNER * DMODEL];   // Wkv^T [N,K]
__device__ __nv_bfloat16 g_wkvt_l[2 * INNER * DMODEL];
__device__ __nv_bfloat16 g_wot_h [DMODEL * INNER];       // Wo^T  [N,K]
__device__ __nv_bfloat16 g_wot_l [DMODEL * INNER];
__device__ __nv_bfloat16 g_ath [ROWS * INNER];
__device__ __nv_bfloat16 g_atl [ROWS * INNER];

// ---------------------------------------------------------------------------
// Helpers (base-ISA only: ldmatrix / mma.sync / cp.async — all valid sm_103)
// ---------------------------------------------------------------------------
__device__ __forceinline__ uint32_t smem_u32(const void* p) {
    uint32_t a;
    asm("{ .reg .u64 t; cvta.to.shared.u64 t, %1; cvt.u32.u64 %0, t; }"
        : "=r"(a) : "l"(p));
    return a;
}

__device__ __forceinline__ void ldmatrix_x4(uint32_t& r0, uint32_t& r1,
                                            uint32_t& r2, uint32_t& r3,
                                            uint32_t addr) {
    asm volatile("ldmatrix.sync.aligned.m8n8.x4.shared.b16 {%0,%1,%2,%3}, [%4];"
                 : "=r"(r0), "=r"(r1), "=r"(r2), "=r"(r3) : "r"(addr));
}

__device__ __forceinline__ void mma_bf16(float* d, const uint32_t* a, const uint32_t* b) {
    asm volatile(
        "mma.sync.aligned.m16n8k16.row.col.f32.bf16.bf16.f32 "
        "{%0,%1,%2,%3}, {%4,%5,%6,%7}, {%8,%9}, {%0,%1,%2,%3};"
        : "+f"(d[0]), "+f"(d[1]), "+f"(d[2]), "+f"(d[3])
        : "r"(a[0]), "r"(a[1]), "r"(a[2]), "r"(a[3]), "r"(b[0]), "r"(b[1]));
}

__device__ __forceinline__ void cp_async16(uint32_t saddr, const void* gaddr) {
    asm volatile("cp.async.cg.shared.global [%0], [%1], 16;"
                 :: "r"(saddr), "l"(gaddr));
}
__device__ __forceinline__ void cp_commit() {
    asm volatile("cp.async.commit_group;" ::: "memory");
}
template <int N>
__device__ __forceinline__ void cp_wait() {
    asm volatile("cp.async.wait_group %0;" :: "n"(N) : "memory");
}

// SW64 swizzle for 64-byte rows (32 bf16): XOR 16B-unit bits with row bits.
__device__ __forceinline__ uint32_t sw64(uint32_t byte) {
    return byte ^ ((byte >> 3) & 0x30);
}

__device__ __forceinline__ void split2(float v, __nv_bfloat16& h, __nv_bfloat16& l) {
    h = __float2bfloat16(v);
    l = __float2bfloat16(v - __bfloat162float(h));
}

// ---------------------------------------------------------------------------
// Prep kernels
// ---------------------------------------------------------------------------
__global__ __launch_bounds__(256)
void split_kernel(const float* __restrict__ X,
                  __nv_bfloat16* __restrict__ H, __nv_bfloat16* __restrict__ L, int n4)
{
    int i = blockIdx.x * blockDim.x + threadIdx.x;
    if (i >= n4) return;
    float4 v = ((const float4*)X)[i];
    union { __nv_bfloat16 b[4]; uint2 u; } uh, ul;
    split2(v.x, uh.b[0], ul.b[0]);
    split2(v.y, uh.b[1], ul.b[1]);
    split2(v.z, uh.b[2], ul.b[2]);
    split2(v.w, uh.b[3], ul.b[3]);
    ((uint2*)H)[i] = uh.u;
    ((uint2*)L)[i] = ul.u;
}

// W[K,N] row-major  ->  Th/Tl[N,K] bf16 hi/lo
__global__ __launch_bounds__(256)
void transpose_split(const float* __restrict__ W,
                     __nv_bfloat16* __restrict__ Th, __nv_bfloat16* __restrict__ Tl,
                     int K, int N)
{
    __shared__ float t[32][33];
    int n  = blockIdx.x * 32 + threadIdx.x;
    int k0 = blockIdx.y * 32 + threadIdx.y;
    #pragma unroll
    for (int i = 0; i < 32; i += 8)
        t[threadIdx.y + i][threadIdx.x] = W[(size_t)(k0 + i) * N + n];
    __syncthreads();
    int k  = blockIdx.y * 32 + threadIdx.x;
    int n0 = blockIdx.x * 32 + threadIdx.y;
    #pragma unroll
    for (int i = 0; i < 32; i += 8) {
        float v = t[threadIdx.x][threadIdx.y + i];
        __nv_bfloat16 h, l;
        split2(v, h, l);
        Th[(size_t)(n0 + i) * K + k] = h;
        Tl[(size_t)(n0 + i) * K + k] = l;
    }
}

// ---------------------------------------------------------------------------
// HMMA GEMM:  C[M,N] = A[M,K] @ Bt^T (+bias), Bt is [N,K] row-major.
// A,Bt given as bf16 hi/lo; 3-term split (hh + hl + lh), fp32 accumulate.
// 128x128 CTA tile, 256 thr (2x4 warps of 64x32), BK=32, 3-stage cp.async.
// ---------------------------------------------------------------------------
#define STG_BYTES   32768         // 4 tiles x 8KB (Ah, Al, Bh, Bl)
#define OFF_AH      0
#define OFF_AL      8192
#define OFF_BH      16384
#define OFF_BL      24576
#define GEMM_SMEM   (3 * STG_BYTES)

__global__ __launch_bounds__(256, 1)
void gemm_mma(const __nv_bfloat16* __restrict__ Ah, const __nv_bfloat16* __restrict__ Al,
              const __nv_bfloat16* __restrict__ Bh, const __nv_bfloat16* __restrict__ Bl,
              const float* __restrict__ bias, float* __restrict__ C,
              int M, int N, int K)
{
    extern __shared__ char smraw[];
    const uint32_t sbase = smem_u32(smraw);

    const int tid  = threadIdx.x;
    const int wid  = tid >> 5;
    const int lane = tid & 31;
    const int wr   = wid >> 2;          // 0..1 : warp row (64 rows)
    const int wc   = wid & 3;           // 0..3 : warp col (32 cols)
    const int row0 = blockIdx.y * 128;
    const int col0 = blockIdx.x * 128;

    // fill decomposition: id -> (row, 16B-chunk)
    const int f_row = tid >> 1;               // rows 0..127 (two threads/row)
    const int f_c0  = (tid & 1) * 2;          // chunks {0,1} or {2,3}

    const int nIter = K >> 5;                 // K/32

    // ldmatrix lane addressing (relative byte offsets within a tile)
    const int lm_row = lane & 15;
    const int lm_koc = (lane >> 4) * 8;       // 0 or 8 (k-octet)

    float acc[4][4][4];
    #pragma unroll
    for (int mf = 0; mf < 4; mf++)
        #pragma unroll
        for (int nf = 0; nf < 4; nf++)
            #pragma unroll
            for (int r = 0; r < 4; r++) acc[mf][nf][r] = 0.f;

    // ---- stage fill via cp.async (A/B, hi/lo) ----
    auto fill_stage = [&](int s, int kk0) {
        const uint32_t st = sbase + s * STG_BYTES;
        #pragma unroll
        for (int cc = 0; cc < 2; cc++) {
            int c = f_c0 + cc;                       // 16B chunk 0..3
            uint32_t off = sw64((uint32_t)(f_row * 64 + c * 16));
            size_t ga = (size_t)(row0 + f_row) * K + kk0 + c * 8;
            size_t gb = (size_t)(col0 + f_row) * K + kk0 + c * 8;
            cp_async16(st + OFF_AH + off, Ah + ga);
            cp_async16(st + OFF_AL + off, Al + ga);
            cp_async16(st + OFF_BH + off, Bh + gb);
            cp_async16(st + OFF_BL + off, Bl + gb);
        }
    };

    fill_stage(0, 0);  cp_commit();
    fill_stage(1, 32); cp_commit();

    for (int kt = 0; kt < nIter; kt++) {
        const int s = kt % 3;
        const uint32_t st = sbase + s * STG_BYTES;

        cp_wait<1>();
        __syncthreads();

        if (kt + 2 < nIter) fill_stage((kt + 2) % 3, (kt + 2) * 32);
        cp_commit();

        #pragma unroll
        for (int ks = 0; ks < 2; ks++) {
            const int colb = (ks * 16 + lm_koc) * 2;    // byte col offset
            uint32_t ah[4][4], al[4][4], bh[4][2], bl[4][2];

            #pragma unroll
            for (int mf = 0; mf < 4; mf++) {
                uint32_t off = sw64((uint32_t)((wr * 64 + mf * 16 + lm_row) * 64 + colb));
                ldmatrix_x4(ah[mf][0], ah[mf][1], ah[mf][2], ah[mf][3], st + OFF_AH + off);
                ldmatrix_x4(al[mf][0], al[mf][1], al[mf][2], al[mf][3], st + OFF_AL + off);
            }
            #pragma unroll
            for (int np = 0; np < 2; np++) {
                uint32_t off = sw64((uint32_t)((wc * 32 + np * 16 + lm_row) * 64 + colb));
                uint32_t r0, r1, r2, r3;
                ldmatrix_x4(r0, r1, r2, r3, st + OFF_BH + off);
                bh[2*np][0] = r0; bh[2*np][1] = r2;
                bh[2*np+1][0] = r1; bh[2*np+1][1] = r3;
                ldmatrix_x4(r0, r1, r2, r3, st + OFF_BL + off);
                bl[2*np][0] = r0; bl[2*np][1] = r2;
                bl[2*np+1][0] = r1; bl[2*np+1][1] = r3;
            }

            #pragma unroll
            for (int mf = 0; mf < 4; mf++)
                #pragma unroll
                for (int nf = 0; nf < 4; nf++) {
                    mma_bf16(acc[mf][nf], ah[mf], bh[nf]);   // hi*hi
                    mma_bf16(acc[mf][nf], ah[mf], bl[nf]);   // hi*lo
                    mma_bf16(acc[mf][nf], al[mf], bh[nf]);   // lo*hi
                }
        }
        __syncthreads();
    }

    // ---- epilogue ----
    const int gq = lane >> 2;          // 0..7
    const int t4 = lane & 3;           // 0..3
    #pragma unroll
    for (int mf = 0; mf < 4; mf++) {
        int r0g = row0 + wr * 64 + mf * 16 + gq;
        #pragma unroll
        for (int nf = 0; nf < 4; nf++) {
            int cg = col0 + wc * 32 + nf * 8 + t4 * 2;
            float bx = 0.f, by = 0.f;
            if (bias) { bx = bias[cg]; by = bias[cg + 1]; }
            float2 v0 = { acc[mf][nf][0] + bx, acc[mf][nf][1] + by };
            float2 v1 = { acc[mf][nf][2] + bx, acc[mf][nf][3] + by };
            *(float2*)(C + (size_t)r0g * N + cg)       = v0;
            *(float2*)(C + (size_t)(r0g + 8) * N + cg) = v1;
        }
    }
}

// ---------------------------------------------------------------------------
// Flash-style causal attention with UNMASKED row max (matches reference gm).
// fp32 scalar path (proven); epilogue writes bf16 hi/lo for the final GEMM.
// ---------------------------------------------------------------------------
#define ATTN_SMEM_FLOATS (64*128 + 64*64 + 64*64 + 128*65)
#define ATTN_SMEM_BYTES  (ATTN_SMEM_FLOATS * 4)

__global__ __launch_bounds__(128, 2)
void attn_kernel(const float* __restrict__ gq, const float* __restrict__ gkv,
                 __nv_bfloat16* __restrict__ goh, __nv_bfloat16* __restrict__ gol)
{
    extern __shared__ float sm[];
    float* Qst = sm;                 // [64][128]  d-major, swizzled cols
    float* Kst = Qst + 64 * 128;     // [64][64]   d-major, swizzled cols
    float* Vs  = Kst + 64 * 64;      // [64][64]   row-major (j, d)
    float* Ps  = Vs  + 64 * 64;      // [128][65]

    const int tid = threadIdx.x;
    const int tr = tid >> 3;
    const int tc = tid & 7;
    const int b  = blockIdx.y >> 4;
    const int h  = blockIdx.y & 15;
    const int qstart = blockIdx.x * 128;

    const float* qbase = gq  + ((size_t)b * SEQ + qstart) * INNER + h * DHEAD;
    const float* kvb   = gkv + (size_t)b * SEQ * (2 * INNER) + h * DHEAD;

    #pragma unroll
    for (int it = 0; it < 16; it++) {
        int id  = tid + it * 128;
        int d4  = id & 15;
        int row = id >> 4;
        float4 v = *(const float4*)(qbase + (size_t)row * INNER + d4 * 4);
        int sw = (d4 & 7) << 3;
        int pr = row ^ sw;
        Qst[(4 * d4 + 0) * 128 + pr] = v.x * 0.125f;
        Qst[(4 * d4 + 1) * 128 + pr] = v.y * 0.125f;
        Qst[(4 * d4 + 2) * 128 + pr] = v.z * 0.125f;
        Qst[(4 * d4 + 3) * 128 + pr] = v.w * 0.125f;
    }

    float o[8][8];
    float m[8], l[8];
    #pragma unroll
    for (int i = 0; i < 8; i++) {
        m[i] = -INFINITY; l[i] = 0.f;
        #pragma unroll
        for (int j = 0; j < 8; j++) o[i][j] = 0.f;
    }

    for (int jt = 0; jt < 32; jt++) {
        const int jstart = jt * 64;
        __syncthreads();

        #pragma unroll
        for (int it = 0; it < 8; it++) {
            int id = tid + it * 128;
            int d4 = id & 15;
            int j  = id >> 4;
            const float* src = kvb + (size_t)(jstart + j) * (2 * INNER) + d4 * 4;
            float4 k4 = *(const float4*)(src);
            float4 v4 = *(const float4*)(src + INNER);
            int sw = (d4 & 7) << 3;
            int pj = j ^ sw;
            Kst[(4 * d4 + 0) * 64 + pj] = k4.x;
            Kst[(4 * d4 + 1) * 64 + pj] = k4.y;
            Kst[(4 * d4 + 2) * 64 + pj] = k4.z;
            Kst[(4 * d4 + 3) * 64 + pj] = k4.w;
            *(float4*)(Vs + j * 64 + d4 * 4) = v4;
        }
        __syncthreads();

        float s[8][8];
        #pragma unroll
        for (int i = 0; i < 8; i++)
            #pragma unroll
            for (int j = 0; j < 8; j++) s[i][j] = 0.f;

        #pragma unroll 4
        for (int d = 0; d < 64; d++) {
            int sw = ((d >> 2) & 7) << 3;
            int qb = (tr * 8) ^ sw;
            int kb = (tc * 8) ^ sw;
            float qv[8], kv[8];
            *(float4*)&qv[0] = *(const float4*)&Qst[d * 128 + qb];
            *(float4*)&qv[4] = *(const float4*)&Qst[d * 128 + qb + 4];
            *(float4*)&kv[0] = *(const float4*)&Kst[d * 64 + kb];
            *(float4*)&kv[4] = *(const float4*)&Kst[d * 64 + kb + 4];
            #pragma unroll
            for (int i = 0; i < 8; i++)
                #pragma unroll
                for (int j = 0; j < 8; j++)
                    s[i][j] += qv[i] * kv[j];
        }

        float al[8];
        #pragma unroll
        for (int i = 0; i < 8; i++) {
            float mx = s[i][0];
            #pragma unroll
            for (int j = 1; j < 8; j++) mx = fmaxf(mx, s[i][j]);
            #pragma unroll
            for (int off = 1; off < 8; off <<= 1)
                mx = fmaxf(mx, __shfl_xor_sync(0xffffffffu, mx, off));
            float mn = fmaxf(m[i], mx);
            al[i] = __expf(m[i] - mn);
            m[i]  = mn;
        }

        const bool active = (jstart <= qstart + 127);

        if (active) {
            const int ig0 = qstart + tr * 8;
            const int jg0 = jstart + tc * 8;
            #pragma unroll
            for (int i = 0; i < 8; i++) {
                float r = 0.f;
                #pragma unroll
                for (int j = 0; j < 8; j++) {
                    float p = (jg0 + j <= ig0 + i) ? __expf(s[i][j] - m[i]) : 0.f;
                    s[i][j] = p;
                    r += p;
                }
                #pragma unroll
                for (int off = 1; off < 8; off <<= 1)
                    r += __shfl_xor_sync(0xffffffffu, r, off);
                l[i] = l[i] * al[i] + r;
            }
        } else {
            #pragma unroll
            for (int i = 0; i < 8; i++) l[i] *= al[i];
        }

        #pragma unroll
        for (int i = 0; i < 8; i++)
            #pragma unroll
            for (int j = 0; j < 8; j++)
                o[i][j] *= al[i];

        if (active) {
            #pragma unroll
            for (int i = 0; i < 8; i++)
                #pragma unroll
                for (int j = 0; j < 8; j++)
                    Ps[(tr * 8 + i) * 65 + (j * 8 + tc)] = s[i][j];
            __syncthreads();

            #pragma unroll 2
            for (int jj = 0; jj < 64; jj++) {
                int pj = ((jj & 7) << 3) | (jj >> 3);
                float pv[8];
                #pragma unroll
                for (int i = 0; i < 8; i++)
                    pv[i] = Ps[(tr * 8 + i) * 65 + pj];
                float vv[8];
                *(float4*)&vv[0] = *(const float4*)&Vs[jj * 64 + tc * 8];
                *(float4*)&vv[4] = *(const float4*)&Vs[jj * 64 + tc * 8 + 4];
                #pragma unroll
                for (int i = 0; i < 8; i++)
                    #pragma unroll
                    for (int j = 0; j < 8; j++)
                        o[i][j] += pv[i] * vv[j];
            }
        }
    }

    const size_t obase = ((size_t)b * SEQ + qstart + tr * 8) * INNER + h * DHEAD + tc * 8;
    #pragma unroll
    for (int i = 0; i < 8; i++) {
        float inv = 1.0f / (l[i] + ATTN_EPS);
        union { __nv_bfloat16 b[4]; uint2 u; } h0, l0, h1, l1;
        #pragma unroll
        for (int j = 0; j < 4; j++) {
            split2(o[i][j]     * inv, h0.b[j], l0.b[j]);
            split2(o[i][j + 4] * inv, h1.b[j], l1.b[j]);
        }
        size_t off = obase + (size_t)i * INNER;
        *(uint2*)(goh + off)     = h0.u;
        *(uint2*)(goh + off + 4) = h1.u;
        *(uint2*)(gol + off)     = l0.u;
        *(uint2*)(gol + off + 4) = l1.u;
    }
}

// ---------------------------------------------------------------------------
// Launch
// ---------------------------------------------------------------------------
extern "C" void kernel_launch(void* const* d_in, const int* in_sizes, int n_in,
                              void* d_out, int out_size)
{
    const float* x   = (const float*)d_in[0];
    const float* Wq  = (const float*)d_in[1];
    const float* Wkv = (const float*)d_in[2];
    const float* Wo  = (const float*)d_in[3];
    const float* bo  = (const float*)d_in[4];
    float* out = (float*)d_out;

    float *pq, *pkv;
    __nv_bfloat16 *pxh, *pxl, *pwqh, *pwql, *pwkh, *pwkl, *pwoh, *pwol, *path, *patl;
    cudaGetSymbolAddress((void**)&pq,   g_q);
    cudaGetSymbolAddress((void**)&pkv,  g_kv);
    cudaGetSymbolAddress((void**)&pxh,  g_xh);
    cudaGetSymbolAddress((void**)&pxl,  g_xl);
    cudaGetSymbolAddress((void**)&pwqh, g_wqt_h);
    cudaGetSymbolAddress((void**)&pwql, g_wqt_l);
    cudaGetSymbolAddress((void**)&pwkh, g_wkvt_h);
    cudaGetSymbolAddress((void**)&pwkl, g_wkvt_l);
    cudaGetSymbolAddress((void**)&pwoh, g_wot_h);
    cudaGetSymbolAddress((void**)&pwol, g_wot_l);
    cudaGetSymbolAddress((void**)&path, g_ath);
    cudaGetSymbolAddress((void**)&patl, g_atl);

    cudaFuncSetAttribute(attn_kernel,
                         cudaFuncAttributeMaxDynamicSharedMemorySize, ATTN_SMEM_BYTES);
    cudaFuncSetAttribute(gemm_mma,
                         cudaFuncAttributeMaxDynamicSharedMemorySize, GEMM_SMEM);

    // --- prep: split x, transpose+split weights ---
    {
        int n4 = ROWS * DMODEL / 4;
        split_kernel<<<(n4 + 255) / 256, 256>>>(x, pxh, pxl, n4);
    }
    transpose_split<<<dim3(INNER / 32, DMODEL / 32),     dim3(32, 8)>>>(Wq,  pwqh, pwql, DMODEL, INNER);
    transpose_split<<<dim3(2 * INNER / 32, DMODEL / 32), dim3(32, 8)>>>(Wkv, pwkh, pwkl, DMODEL, 2 * INNER);
    transpose_split<<<dim3(DMODEL / 32, INNER / 32),     dim3(32, 8)>>>(Wo,  pwoh, pwol, INNER,  DMODEL);

    // --- q = x @ Wq ; kv = x @ Wkv  (HMMA, 3-term bf16 split) ---
    gemm_mma<<<dim3(INNER / 128, ROWS / 128), 256, GEMM_SMEM>>>(
        pxh, pxl, pwqh, pwql, nullptr, pq, ROWS, INNER, DMODEL);
    gemm_mma<<<dim3(2 * INNER / 128, ROWS / 128), 256, GEMM_SMEM>>>(
        pxh, pxl, pwkh, pwkl, nullptr, pkv, ROWS, 2 * INNER, DMODEL);

    // --- attention (writes bf16 hi/lo split directly) ---
    attn_kernel<<<dim3(SEQ / 128, BATCH * HEADS), 128, ATTN_SMEM_BYTES>>>(
        pq, pkv, path, patl);

    // --- out = att @ Wo + bo ---
    gemm_mma<<<dim3(DMODEL / 128, ROWS / 128), 256, GEMM_SMEM>>>(
        path, patl, pwoh, pwol, bo, out, ROWS, DMODEL, INNER);
}

// round 6
// speedup vs baseline: 2.3673x; 1.7006x over previous
#include <cuda_runtime.h>
#include <cuda_bf16.h>
#include <math.h>
#include <stdint.h>

// ---------------------------------------------------------------------------
// Problem constants
// ---------------------------------------------------------------------------
#define BATCH   2
#define SEQ     2048
#define DMODEL  1024
#define HEADS   16
#define DHEAD   64
#define INNER   (HEADS * DHEAD)      // 1024
#define ROWS    (BATCH * SEQ)        // 4096
#define ATTN_EPS 1e-8f

// ---------------------------------------------------------------------------
// Scratch (device globals: allowed; runtime alloc is not)
// ---------------------------------------------------------------------------
__device__ __nv_bfloat16 g_xh  [ROWS * DMODEL];
__device__ __nv_bfloat16 g_xl  [ROWS * DMODEL];
__device__ __nv_bfloat16 g_wqt_h [INNER * DMODEL];
__device__ __nv_bfloat16 g_wqt_l [INNER * DMODEL];
__device__ __nv_bfloat16 g_wkvt_h[2 * INNER * DMODEL];
__device__ __nv_bfloat16 g_wkvt_l[2 * INNER * DMODEL];
__device__ __nv_bfloat16 g_wot_h [DMODEL * INNER];
__device__ __nv_bfloat16 g_wot_l [DMODEL * INNER];
__device__ __nv_bfloat16 g_qh  [ROWS * INNER];        // q (scaled) hi/lo
__device__ __nv_bfloat16 g_ql  [ROWS * INNER];
__device__ __nv_bfloat16 g_kvh [ROWS * 2 * INNER];    // kv hi/lo
__device__ __nv_bfloat16 g_kvl [ROWS * 2 * INNER];
__device__ __nv_bfloat16 g_ath [ROWS * INNER];        // attention out hi/lo
__device__ __nv_bfloat16 g_atl [ROWS * INNER];

// ---------------------------------------------------------------------------
// Helpers (base ISA: ldmatrix / mma.sync / cp.async — valid on plain sm_103)
// ---------------------------------------------------------------------------
__device__ __forceinline__ uint32_t smem_u32(const void* p) {
    uint32_t a;
    asm("{ .reg .u64 t; cvta.to.shared.u64 t, %1; cvt.u32.u64 %0, t; }"
        : "=r"(a) : "l"(p));
    return a;
}

__device__ __forceinline__ void ldmatrix_x4(uint32_t& r0, uint32_t& r1,
                                            uint32_t& r2, uint32_t& r3,
                                            uint32_t addr) {
    asm volatile("ldmatrix.sync.aligned.m8n8.x4.shared.b16 {%0,%1,%2,%3}, [%4];"
                 : "=r"(r0), "=r"(r1), "=r"(r2), "=r"(r3) : "r"(addr));
}

__device__ __forceinline__ void mma_bf16(float* d, const uint32_t* a, const uint32_t* b) {
    asm volatile(
        "mma.sync.aligned.m16n8k16.row.col.f32.bf16.bf16.f32 "
        "{%0,%1,%2,%3}, {%4,%5,%6,%7}, {%8,%9}, {%0,%1,%2,%3};"
        : "+f"(d[0]), "+f"(d[1]), "+f"(d[2]), "+f"(d[3])
        : "r"(a[0]), "r"(a[1]), "r"(a[2]), "r"(a[3]), "r"(b[0]), "r"(b[1]));
}

__device__ __forceinline__ void cp_async16(uint32_t saddr, const void* gaddr) {
    asm volatile("cp.async.cg.shared.global [%0], [%1], 16;"
                 :: "r"(saddr), "l"(gaddr));
}
__device__ __forceinline__ void cp_commit() {
    asm volatile("cp.async.commit_group;" ::: "memory");
}
template <int N>
__device__ __forceinline__ void cp_wait() {
    asm volatile("cp.async.wait_group %0;" :: "n"(N) : "memory");
}

__device__ __forceinline__ uint32_t sw64(uint32_t byte) {
    return byte ^ ((byte >> 3) & 0x30);
}

__device__ __forceinline__ void split2(float v, __nv_bfloat16& h, __nv_bfloat16& l) {
    h = __float2bfloat16(v);
    l = __float2bfloat16(v - __bfloat162float(h));
}

// pack two floats into bf16x2 hi-part and bf16x2 lo-part (low half = first arg)
__device__ __forceinline__ void pack_split(float a, float b, uint32_t& hi, uint32_t& lo) {
    __nv_bfloat16 ha = __float2bfloat16(a), hb = __float2bfloat16(b);
    float ra = a - __bfloat162float(ha), rb = b - __bfloat162float(hb);
    __nv_bfloat162 H; H.x = ha; H.y = hb;
    __nv_bfloat162 L; L.x = __float2bfloat16(ra); L.y = __float2bfloat16(rb);
    hi = *(uint32_t*)&H;
    lo = *(uint32_t*)&L;
}

// ---------------------------------------------------------------------------
// Prep kernels
// ---------------------------------------------------------------------------
__global__ __launch_bounds__(256)
void split_kernel(const float* __restrict__ X,
                  __nv_bfloat16* __restrict__ H, __nv_bfloat16* __restrict__ L, int n4)
{
    int i = blockIdx.x * blockDim.x + threadIdx.x;
    if (i >= n4) return;
    float4 v = ((const float4*)X)[i];
    union { __nv_bfloat16 b[4]; uint2 u; } uh, ul;
    split2(v.x, uh.b[0], ul.b[0]);
    split2(v.y, uh.b[1], ul.b[1]);
    split2(v.z, uh.b[2], ul.b[2]);
    split2(v.w, uh.b[3], ul.b[3]);
    ((uint2*)H)[i] = uh.u;
    ((uint2*)L)[i] = ul.u;
}

__global__ __launch_bounds__(256)
void transpose_split(const float* __restrict__ W,
                     __nv_bfloat16* __restrict__ Th, __nv_bfloat16* __restrict__ Tl,
                     int K, int N)
{
    __shared__ float t[32][33];
    int n  = blockIdx.x * 32 + threadIdx.x;
    int k0 = blockIdx.y * 32 + threadIdx.y;
    #pragma unroll
    for (int i = 0; i < 32; i += 8)
        t[threadIdx.y + i][threadIdx.x] = W[(size_t)(k0 + i) * N + n];
    __syncthreads();
    int k  = blockIdx.y * 32 + threadIdx.x;
    int n0 = blockIdx.x * 32 + threadIdx.y;
    #pragma unroll
    for (int i = 0; i < 32; i += 8) {
        float v = t[threadIdx.x][threadIdx.y + i];
        __nv_bfloat16 h, l;
        split2(v, h, l);
        Th[(size_t)(n0 + i) * K + k] = h;
        Tl[(size_t)(n0 + i) * K + k] = l;
    }
}

// ---------------------------------------------------------------------------
// HMMA GEMM core (shared by fp32-out and split-out variants)
// 128x128 CTA tile, 256 thr (2x4 warps of 64x32), BK=32, 3-stage cp.async.
// ---------------------------------------------------------------------------
#define STG_BYTES   32768
#define OFF_AH      0
#define OFF_AL      8192
#define OFF_BH      16384
#define OFF_BL      24576
#define GEMM_SMEM   (3 * STG_BYTES)

struct GemmCtx {
    float acc[4][4][4];
    int wr, wc, lane;
};

__device__ __forceinline__ void gemm_core(
    const __nv_bfloat16* __restrict__ Ah, const __nv_bfloat16* __restrict__ Al,
    const __nv_bfloat16* __restrict__ Bh, const __nv_bfloat16* __restrict__ Bl,
    int N, int K, int row0, int col0, GemmCtx& g)
{
    extern __shared__ char smraw[];
    const uint32_t sbase = smem_u32(smraw);

    const int tid  = threadIdx.x;
    const int wid  = tid >> 5;
    const int lane = tid & 31;
    g.wr = wid >> 2; g.wc = wid & 3; g.lane = lane;

    const int f_row = tid >> 1;
    const int f_c0  = (tid & 1) * 2;
    const int nIter = K >> 5;
    const int lm_row = lane & 15;
    const int lm_koc = (lane >> 4) * 8;

    #pragma unroll
    for (int mf = 0; mf < 4; mf++)
        #pragma unroll
        for (int nf = 0; nf < 4; nf++)
            #pragma unroll
            for (int r = 0; r < 4; r++) g.acc[mf][nf][r] = 0.f;

    auto fill_stage = [&](int s, int kk0) {
        const uint32_t st = sbase + s * STG_BYTES;
        #pragma unroll
        for (int cc = 0; cc < 2; cc++) {
            int c = f_c0 + cc;
            uint32_t off = sw64((uint32_t)(f_row * 64 + c * 16));
            size_t ga = (size_t)(row0 + f_row) * K + kk0 + c * 8;
            size_t gb = (size_t)(col0 + f_row) * K + kk0 + c * 8;
            cp_async16(st + OFF_AH + off, Ah + ga);
            cp_async16(st + OFF_AL + off, Al + ga);
            cp_async16(st + OFF_BH + off, Bh + gb);
            cp_async16(st + OFF_BL + off, Bl + gb);
        }
    };

    fill_stage(0, 0);  cp_commit();
    fill_stage(1, 32); cp_commit();

    for (int kt = 0; kt < nIter; kt++) {
        const int s = kt % 3;
        const uint32_t st = sbase + s * STG_BYTES;

        cp_wait<1>();
        __syncthreads();

        if (kt + 2 < nIter) fill_stage((kt + 2) % 3, (kt + 2) * 32);
        cp_commit();

        #pragma unroll
        for (int ks = 0; ks < 2; ks++) {
            const int colb = (ks * 16 + lm_koc) * 2;
            uint32_t ah[4][4], al[4][4], bh[4][2], bl[4][2];

            #pragma unroll
            for (int mf = 0; mf < 4; mf++) {
                uint32_t off = sw64((uint32_t)((g.wr * 64 + mf * 16 + lm_row) * 64 + colb));
                ldmatrix_x4(ah[mf][0], ah[mf][1], ah[mf][2], ah[mf][3], st + OFF_AH + off);
                ldmatrix_x4(al[mf][0], al[mf][1], al[mf][2], al[mf][3], st + OFF_AL + off);
            }
            #pragma unroll
            for (int np = 0; np < 2; np++) {
                uint32_t off = sw64((uint32_t)((g.wc * 32 + np * 16 + lm_row) * 64 + colb));
                uint32_t r0, r1, r2, r3;
                ldmatrix_x4(r0, r1, r2, r3, st + OFF_BH + off);
                bh[2*np][0] = r0; bh[2*np][1] = r2;
                bh[2*np+1][0] = r1; bh[2*np+1][1] = r3;
                ldmatrix_x4(r0, r1, r2, r3, st + OFF_BL + off);
                bl[2*np][0] = r0; bl[2*np][1] = r2;
                bl[2*np+1][0] = r1; bl[2*np+1][1] = r3;
            }

            #pragma unroll
            for (int mf = 0; mf < 4; mf++)
                #pragma unroll
                for (int nf = 0; nf < 4; nf++) {
                    mma_bf16(g.acc[mf][nf], ah[mf], bh[nf]);
                    mma_bf16(g.acc[mf][nf], ah[mf], bl[nf]);
                    mma_bf16(g.acc[mf][nf], al[mf], bh[nf]);
                }
        }
        __syncthreads();
    }
}

// fp32-output GEMM (+bias) — used for the final projection
__global__ __launch_bounds__(256, 1)
void gemm_mma(const __nv_bfloat16* __restrict__ Ah, const __nv_bfloat16* __restrict__ Al,
              const __nv_bfloat16* __restrict__ Bh, const __nv_bfloat16* __restrict__ Bl,
              const float* __restrict__ bias, float* __restrict__ C,
              int M, int N, int K)
{
    GemmCtx g;
    const int row0 = blockIdx.y * 128;
    const int col0 = blockIdx.x * 128;
    gemm_core(Ah, Al, Bh, Bl, N, K, row0, col0, g);

    const int gq = g.lane >> 2;
    const int t4 = g.lane & 3;
    #pragma unroll
    for (int mf = 0; mf < 4; mf++) {
        int r0g = row0 + g.wr * 64 + mf * 16 + gq;
        #pragma unroll
        for (int nf = 0; nf < 4; nf++) {
            int cg = col0 + g.wc * 32 + nf * 8 + t4 * 2;
            float bx = 0.f, by = 0.f;
            if (bias) { bx = bias[cg]; by = bias[cg + 1]; }
            float2 v0 = { g.acc[mf][nf][0] + bx, g.acc[mf][nf][1] + by };
            float2 v1 = { g.acc[mf][nf][2] + bx, g.acc[mf][nf][3] + by };
            *(float2*)(C + (size_t)r0g * N + cg)       = v0;
            *(float2*)(C + (size_t)(r0g + 8) * N + cg) = v1;
        }
    }
}

// split-output GEMM: C -> (Oh, Ol) bf16 hi/lo, optional scale (exact pow2)
__global__ __launch_bounds__(256, 1)
void gemm_mma_split(const __nv_bfloat16* __restrict__ Ah, const __nv_bfloat16* __restrict__ Al,
                    const __nv_bfloat16* __restrict__ Bh, const __nv_bfloat16* __restrict__ Bl,
                    __nv_bfloat16* __restrict__ Oh, __nv_bfloat16* __restrict__ Ol,
                    int M, int N, int K, float scale)
{
    GemmCtx g;
    const int row0 = blockIdx.y * 128;
    const int col0 = blockIdx.x * 128;
    gemm_core(Ah, Al, Bh, Bl, N, K, row0, col0, g);

    const int gq = g.lane >> 2;
    const int t4 = g.lane & 3;
    #pragma unroll
    for (int mf = 0; mf < 4; mf++) {
        int r0g = row0 + g.wr * 64 + mf * 16 + gq;
        #pragma unroll
        for (int nf = 0; nf < 4; nf++) {
            int cg = col0 + g.wc * 32 + nf * 8 + t4 * 2;
            uint32_t h0, l0, h1, l1;
            pack_split(g.acc[mf][nf][0] * scale, g.acc[mf][nf][1] * scale, h0, l0);
            pack_split(g.acc[mf][nf][2] * scale, g.acc[mf][nf][3] * scale, h1, l1);
            *(uint32_t*)(Oh + (size_t)r0g * N + cg)       = h0;
            *(uint32_t*)(Ol + (size_t)r0g * N + cg)       = l0;
            *(uint32_t*)(Oh + (size_t)(r0g + 8) * N + cg) = h1;
            *(uint32_t*)(Ol + (size_t)(r0g + 8) * N + cg) = l1;
        }
    }
}

// ---------------------------------------------------------------------------
// HMMA flash attention, causal-only tiles.
// Grid (16 qtiles reversed, 32 bh). 256 thr = 8 warps, each warp 16 q-rows.
// Br=128, Bc=64. Q,K,V bf16 hi/lo; P split in registers; fp32 accumulators.
// Row max over processed (causal) tiles only: differs from reference gm only
// through the eps term -> rel deviation <= eps/l ~ 1e-5 worst case.
// ---------------------------------------------------------------------------
#define AT_SMEM (65536 + 1024)

__global__ __launch_bounds__(256, 1)
void attn_mma(const __nv_bfloat16* __restrict__ qh, const __nv_bfloat16* __restrict__ ql,
              const __nv_bfloat16* __restrict__ kvh, const __nv_bfloat16* __restrict__ kvl,
              __nv_bfloat16* __restrict__ goh, __nv_bfloat16* __restrict__ gol)
{
    extern __shared__ char smraw[];
    const uint32_t b0a = smem_u32(smraw);
    const uint32_t sb = (b0a + 1023u) & ~1023u;
    char* smc = smraw + (sb - b0a);

    const int tid = threadIdx.x;
    const int w = tid >> 5, lane = tid & 31;
    const int gq = lane >> 2, t4 = lane & 3;
    const int lm_row = lane & 15, lm_koc = (lane >> 4) * 8;
    const int b = blockIdx.y >> 4, h = blockIdx.y & 15;
    const int qt = gridDim.x - 1 - blockIdx.x;     // heavy tiles first
    const int qstart = qt * 128;

    const uint32_t QH = sb, QL = sb + 16384;
    const uint32_t KH = sb + 32768, KL = sb + 40960;
    const uint32_t VH = sb + 49152, VL = sb + 57344;
    const int VHrel = 49152, VLrel = 57344;

    // ---- Q tile fill (cp.async, SW128 swizzle) ----
    #pragma unroll
    for (int it = 0; it < 8; it++) {
        int idx = tid + it * 256;
        int bs = idx >> 10, r = (idx >> 3) & 127, c = idx & 7;
        const __nv_bfloat16* src = (bs ? ql : qh)
            + (size_t)(b * SEQ + qstart + r) * INNER + h * 64 + c * 8;
        cp_async16((bs ? QL : QH) + (uint32_t)(r * 128 + ((c * 16) ^ ((r & 7) << 4))), src);
    }
    cp_commit();

    float o[8][4];
    float m[2] = { -INFINITY, -INFINITY }, lsum[2] = { 0.f, 0.f };
    #pragma unroll
    for (int nd = 0; nd < 8; nd++)
        #pragma unroll
        for (int r = 0; r < 4; r++) o[nd][r] = 0.f;

    const int nT = 2 * qt + 2;
    for (int jt = 0; jt < nT; jt++) {
        const int jstart = jt * 64;
        __syncthreads();       // previous tile's smem reads complete

        // ---- K tile fill (cp.async) ----
        #pragma unroll
        for (int it = 0; it < 4; it++) {
            int idx = tid + it * 256;
            int bs = idx >> 9, j = (idx >> 3) & 63, c = idx & 7;
            const __nv_bfloat16* src = (bs ? kvl : kvh)
                + (size_t)(b * SEQ + jstart + j) * 2048 + h * 64 + c * 8;
            cp_async16((bs ? KL : KH) + (uint32_t)(j * 128 + ((c * 16) ^ ((j & 7) << 4))), src);
        }
        cp_commit();

        // ---- V tile transpose fill (register path, j-fastest lanes) ----
        #pragma unroll
        for (int it = 0; it < 2; it++) {
            int idx = tid + it * 256;            // 0..511
            int j = idx & 63, c = idx >> 6;      // c in 0..7
            size_t gsrc = (size_t)(b * SEQ + jstart + j) * 2048 + 1024 + h * 64 + c * 8;
            union { uint4 q; __nv_bfloat16 e[8]; } uh, ul;
            uh.q = *(const uint4*)(kvh + gsrc);
            ul.q = *(const uint4*)(kvl + gsrc);
            #pragma unroll
            for (int i = 0; i < 8; i++) {
                int d = c * 8 + i;
                uint32_t off = (uint32_t)(d * 128 + ((j * 2) ^ ((d & 7) << 4)));
                *(__nv_bfloat16*)(smc + VHrel + off) = uh.e[i];
                *(__nv_bfloat16*)(smc + VLrel + off) = ul.e[i];
            }
        }
        cp_wait<0>();
        __syncthreads();

        // ---- S = Q @ K^T (3-term split) ----
        float s[8][4];
        #pragma unroll
        for (int nj = 0; nj < 8; nj++)
            #pragma unroll
            for (int r = 0; r < 4; r++) s[nj][r] = 0.f;

        #pragma unroll
        for (int kd = 0; kd < 4; kd++) {
            const int cb = (kd * 16 + lm_koc) * 2;
            uint32_t ah[4], al[4];
            {
                int r = w * 16 + lm_row;
                uint32_t off = (uint32_t)(r * 128 + (cb ^ ((r & 7) << 4)));
                ldmatrix_x4(ah[0], ah[1], ah[2], ah[3], QH + off);
                ldmatrix_x4(al[0], al[1], al[2], al[3], QL + off);
            }
            #pragma unroll
            for (int jp = 0; jp < 4; jp++) {
                int r = jp * 16 + lm_row;
                uint32_t off = (uint32_t)(r * 128 + (cb ^ ((r & 7) << 4)));
                uint32_t r0, r1, r2, r3;
                uint32_t bh0[2], bh1[2], bl0[2], bl1[2];
                ldmatrix_x4(r0, r1, r2, r3, KH + off);
                bh0[0] = r0; bh0[1] = r2; bh1[0] = r1; bh1[1] = r3;
                ldmatrix_x4(r0, r1, r2, r3, KL + off);
                bl0[0] = r0; bl0[1] = r2; bl1[0] = r1; bl1[1] = r3;
                mma_bf16(s[2*jp],   ah, bh0); mma_bf16(s[2*jp],   ah, bl0); mma_bf16(s[2*jp],   al, bh0);
                mma_bf16(s[2*jp+1], ah, bh1); mma_bf16(s[2*jp+1], ah, bl1); mma_bf16(s[2*jp+1], al, bh1);
            }
        }

        // ---- online softmax (rows gq / gq+8 per thread) ----
        float alpha[2];
        #pragma unroll
        for (int hh = 0; hh < 2; hh++) {
            float mx = -INFINITY;
            #pragma unroll
            for (int nj = 0; nj < 8; nj++)
                mx = fmaxf(mx, fmaxf(s[nj][2*hh], s[nj][2*hh+1]));
            mx = fmaxf(mx, __shfl_xor_sync(0xffffffffu, mx, 1));
            mx = fmaxf(mx, __shfl_xor_sync(0xffffffffu, mx, 2));
            float mn = fmaxf(m[hh], mx);
            alpha[hh] = __expf(m[hh] - mn);
            m[hh] = mn;
            const int ig = qstart + w * 16 + hh * 8 + gq;
            float rs = 0.f;
            #pragma unroll
            for (int nj = 0; nj < 8; nj++) {
                int jg = jstart + nj * 8 + t4 * 2;
                float p0 = (jg     <= ig) ? __expf(s[nj][2*hh]   - mn) : 0.f;
                float p1 = (jg + 1 <= ig) ? __expf(s[nj][2*hh+1] - mn) : 0.f;
                s[nj][2*hh] = p0; s[nj][2*hh+1] = p1;
                rs += p0 + p1;
            }
            rs += __shfl_xor_sync(0xffffffffu, rs, 1);
            rs += __shfl_xor_sync(0xffffffffu, rs, 2);
            lsum[hh] = lsum[hh] * alpha[hh] + rs;
        }
        #pragma unroll
        for (int nd = 0; nd < 8; nd++) {
            o[nd][0] *= alpha[0]; o[nd][1] *= alpha[0];
            o[nd][2] *= alpha[1]; o[nd][3] *= alpha[1];
        }

        // ---- O += P @ V (P split in registers; V from transposed smem) ----
        #pragma unroll
        for (int kj = 0; kj < 4; kj++) {
            uint32_t ph[4], pl[4];
            pack_split(s[2*kj][0],   s[2*kj][1],   ph[0], pl[0]);
            pack_split(s[2*kj][2],   s[2*kj][3],   ph[1], pl[1]);
            pack_split(s[2*kj+1][0], s[2*kj+1][1], ph[2], pl[2]);
            pack_split(s[2*kj+1][2], s[2*kj+1][3], ph[3], pl[3]);
            const int cb = (kj * 16 + lm_koc) * 2;
            #pragma unroll
            for (int ndp = 0; ndp < 4; ndp++) {
                int r = ndp * 16 + lm_row;
                uint32_t off = (uint32_t)(r * 128 + (cb ^ ((r & 7) << 4)));
                uint32_t r0, r1, r2, r3;
                uint32_t bh0[2], bh1[2], bl0[2], bl1[2];
                ldmatrix_x4(r0, r1, r2, r3, VH + off);
                bh0[0] = r0; bh0[1] = r2; bh1[0] = r1; bh1[1] = r3;
                ldmatrix_x4(r0, r1, r2, r3, VL + off);
                bl0[0] = r0; bl0[1] = r2; bl1[0] = r1; bl1[1] = r3;
                mma_bf16(o[2*ndp],   ph, bh0); mma_bf16(o[2*ndp],   ph, bl0); mma_bf16(o[2*ndp],   pl, bh0);
                mma_bf16(o[2*ndp+1], ph, bh1); mma_bf16(o[2*ndp+1], ph, bl1); mma_bf16(o[2*ndp+1], pl, bh1);
            }
        }
    }

    // ---- epilogue: normalize, split hi/lo, store ----
    const float inv0 = 1.0f / (lsum[0] + ATTN_EPS);
    const float inv1 = 1.0f / (lsum[1] + ATTN_EPS);
    const size_t base0 = (size_t)(b * SEQ + qstart + w * 16 + gq) * INNER + h * 64 + t4 * 2;
    const size_t base1 = base0 + (size_t)8 * INNER;
    #pragma unroll
    for (int nd = 0; nd < 8; nd++) {
        uint32_t h0, l0, h1, l1;
        pack_split(o[nd][0] * inv0, o[nd][1] * inv0, h0, l0);
        pack_split(o[nd][2] * inv1, o[nd][3] * inv1, h1, l1);
        *(uint32_t*)(goh + base0 + nd * 8) = h0;
        *(uint32_t*)(gol + base0 + nd * 8) = l0;
        *(uint32_t*)(goh + base1 + nd * 8) = h1;
        *(uint32_t*)(gol + base1 + nd * 8) = l1;
    }
}

// ---------------------------------------------------------------------------
// Launch
// ---------------------------------------------------------------------------
extern "C" void kernel_launch(void* const* d_in, const int* in_sizes, int n_in,
                              void* d_out, int out_size)
{
    const float* x   = (const float*)d_in[0];
    const float* Wq  = (const float*)d_in[1];
    const float* Wkv = (const float*)d_in[2];
    const float* Wo  = (const float*)d_in[3];
    const float* bo  = (const float*)d_in[4];
    float* out = (float*)d_out;

    __nv_bfloat16 *pxh, *pxl, *pwqh, *pwql, *pwkh, *pwkl, *pwoh, *pwol;
    __nv_bfloat16 *pqh, *pql, *pkvh, *pkvl, *path, *patl;
    cudaGetSymbolAddress((void**)&pxh,  g_xh);
    cudaGetSymbolAddress((void**)&pxl,  g_xl);
    cudaGetSymbolAddress((void**)&pwqh, g_wqt_h);
    cudaGetSymbolAddress((void**)&pwql, g_wqt_l);
    cudaGetSymbolAddress((void**)&pwkh, g_wkvt_h);
    cudaGetSymbolAddress((void**)&pwkl, g_wkvt_l);
    cudaGetSymbolAddress((void**)&pwoh, g_wot_h);
    cudaGetSymbolAddress((void**)&pwol, g_wot_l);
    cudaGetSymbolAddress((void**)&pqh,  g_qh);
    cudaGetSymbolAddress((void**)&pql,  g_ql);
    cudaGetSymbolAddress((void**)&pkvh, g_kvh);
    cudaGetSymbolAddress((void**)&pkvl, g_kvl);
    cudaGetSymbolAddress((void**)&path, g_ath);
    cudaGetSymbolAddress((void**)&patl, g_atl);

    cudaFuncSetAttribute(gemm_mma,
                         cudaFuncAttributeMaxDynamicSharedMemorySize, GEMM_SMEM);
    cudaFuncSetAttribute(gemm_mma_split,
                         cudaFuncAttributeMaxDynamicSharedMemorySize, GEMM_SMEM);
    cudaFuncSetAttribute(attn_mma,
                         cudaFuncAttributeMaxDynamicSharedMemorySize, AT_SMEM);

    // --- prep ---
    {
        int n4 = ROWS * DMODEL / 4;
        split_kernel<<<(n4 + 255) / 256, 256>>>(x, pxh, pxl, n4);
    }
    transpose_split<<<dim3(INNER / 32, DMODEL / 32),     dim3(32, 8)>>>(Wq,  pwqh, pwql, DMODEL, INNER);
    transpose_split<<<dim3(2 * INNER / 32, DMODEL / 32), dim3(32, 8)>>>(Wkv, pwkh, pwkl, DMODEL, 2 * INNER);
    transpose_split<<<dim3(DMODEL / 32, INNER / 32),     dim3(32, 8)>>>(Wo,  pwoh, pwol, INNER,  DMODEL);

    // --- projections: q (pre-scaled by Dh^-0.5) and kv, split bf16 out ---
    gemm_mma_split<<<dim3(INNER / 128, ROWS / 128), 256, GEMM_SMEM>>>(
        pxh, pxl, pwqh, pwql, pqh, pql, ROWS, INNER, DMODEL, 0.125f);
    gemm_mma_split<<<dim3(2 * INNER / 128, ROWS / 128), 256, GEMM_SMEM>>>(
        pxh, pxl, pwkh, pwkl, pkvh, pkvl, ROWS, 2 * INNER, DMODEL, 1.0f);

    // --- attention (HMMA, causal tiles only) ---
    attn_mma<<<dim3(SEQ / 128, BATCH * HEADS), 256, AT_SMEM>>>(
        pqh, pql, pkvh, pkvl, path, patl);

    // --- out = att @ Wo + bo ---
    gemm_mma<<<dim3(DMODEL / 128, ROWS / 128), 256, GEMM_SMEM>>>(
        path, patl, pwoh, pwol, bo, out, ROWS, DMODEL, INNER);
}

// round 7
// speedup vs baseline: 2.5326x; 1.0698x over previous
#include <cuda_runtime.h>
#include <cuda_bf16.h>
#include <math.h>
#include <stdint.h>

// ---------------------------------------------------------------------------
// Problem constants
// ---------------------------------------------------------------------------
#define BATCH   2
#define SEQ     2048
#define DMODEL  1024
#define HEADS   16
#define DHEAD   64
#define INNER   (HEADS * DHEAD)      // 1024
#define ROWS    (BATCH * SEQ)        // 4096
#define QKVW    (3 * INNER)          // 3072 fused projection width
#define ATTN_EPS 1e-8f

// ---------------------------------------------------------------------------
// Scratch (device globals)
// ---------------------------------------------------------------------------
__device__ __nv_bfloat16 g_xh  [ROWS * DMODEL];
__device__ __nv_bfloat16 g_xl  [ROWS * DMODEL];
__device__ __nv_bfloat16 g_w1h [QKVW * DMODEL];       // [Wq^T; Wkv^T] fused
__device__ __nv_bfloat16 g_w1l [QKVW * DMODEL];
__device__ __nv_bfloat16 g_wot_h [DMODEL * INNER];
__device__ __nv_bfloat16 g_wot_l [DMODEL * INNER];
__device__ __nv_bfloat16 g_qkvh [ROWS * QKVW];        // fused q|k|v hi/lo
__device__ __nv_bfloat16 g_qkvl [ROWS * QKVW];
__device__ __nv_bfloat16 g_ath [ROWS * INNER];        // attention out hi/lo
__device__ __nv_bfloat16 g_atl [ROWS * INNER];

// ---------------------------------------------------------------------------
// Helpers (base ISA only)
// ---------------------------------------------------------------------------
__device__ __forceinline__ uint32_t smem_u32(const void* p) {
    uint32_t a;
    asm("{ .reg .u64 t; cvta.to.shared.u64 t, %1; cvt.u32.u64 %0, t; }"
        : "=r"(a) : "l"(p));
    return a;
}

__device__ __forceinline__ void ldmatrix_x4(uint32_t& r0, uint32_t& r1,
                                            uint32_t& r2, uint32_t& r3,
                                            uint32_t addr) {
    asm volatile("ldmatrix.sync.aligned.m8n8.x4.shared.b16 {%0,%1,%2,%3}, [%4];"
                 : "=r"(r0), "=r"(r1), "=r"(r2), "=r"(r3) : "r"(addr));
}

__device__ __forceinline__ void ldmatrix_x4_trans(uint32_t& r0, uint32_t& r1,
                                                  uint32_t& r2, uint32_t& r3,
                                                  uint32_t addr) {
    asm volatile("ldmatrix.sync.aligned.m8n8.x4.trans.shared.b16 {%0,%1,%2,%3}, [%4];"
                 : "=r"(r0), "=r"(r1), "=r"(r2), "=r"(r3) : "r"(addr));
}

__device__ __forceinline__ void mma_bf16(float* d, const uint32_t* a, const uint32_t* b) {
    asm volatile(
        "mma.sync.aligned.m16n8k16.row.col.f32.bf16.bf16.f32 "
        "{%0,%1,%2,%3}, {%4,%5,%6,%7}, {%8,%9}, {%0,%1,%2,%3};"
        : "+f"(d[0]), "+f"(d[1]), "+f"(d[2]), "+f"(d[3])
        : "r"(a[0]), "r"(a[1]), "r"(a[2]), "r"(a[3]), "r"(b[0]), "r"(b[1]));
}

__device__ __forceinline__ void cp_async16(uint32_t saddr, const void* gaddr) {
    asm volatile("cp.async.cg.shared.global [%0], [%1], 16;"
                 :: "r"(saddr), "l"(gaddr));
}
__device__ __forceinline__ void cp_commit() {
    asm volatile("cp.async.commit_group;" ::: "memory");
}
template <int N>
__device__ __forceinline__ void cp_wait() {
    asm volatile("cp.async.wait_group %0;" :: "n"(N) : "memory");
}

__device__ __forceinline__ uint32_t sw64(uint32_t byte) {
    return byte ^ ((byte >> 3) & 0x30);
}

__device__ __forceinline__ void split2(float v, __nv_bfloat16& h, __nv_bfloat16& l) {
    h = __float2bfloat16(v);
    l = __float2bfloat16(v - __bfloat162float(h));
}

__device__ __forceinline__ void pack_split(float a, float b, uint32_t& hi, uint32_t& lo) {
    __nv_bfloat16 ha = __float2bfloat16(a), hb = __float2bfloat16(b);
    float ra = a - __bfloat162float(ha), rb = b - __bfloat162float(hb);
    __nv_bfloat162 H; H.x = ha; H.y = hb;
    __nv_bfloat162 L; L.x = __float2bfloat16(ra); L.y = __float2bfloat16(rb);
    hi = *(uint32_t*)&H;
    lo = *(uint32_t*)&L;
}

// ---------------------------------------------------------------------------
// Prep kernels
// ---------------------------------------------------------------------------
__global__ __launch_bounds__(256)
void split_kernel(const float* __restrict__ X,
                  __nv_bfloat16* __restrict__ H, __nv_bfloat16* __restrict__ L, int n4)
{
    int i = blockIdx.x * blockDim.x + threadIdx.x;
    if (i >= n4) return;
    float4 v = ((const float4*)X)[i];
    union { __nv_bfloat16 b[4]; uint2 u; } uh, ul;
    split2(v.x, uh.b[0], ul.b[0]);
    split2(v.y, uh.b[1], ul.b[1]);
    split2(v.z, uh.b[2], ul.b[2]);
    split2(v.w, uh.b[3], ul.b[3]);
    ((uint2*)H)[i] = uh.u;
    ((uint2*)L)[i] = ul.u;
}

__global__ __launch_bounds__(256)
void transpose_split(const float* __restrict__ W,
                     __nv_bfloat16* __restrict__ Th, __nv_bfloat16* __restrict__ Tl,
                     int K, int N)
{
    __shared__ float t[32][33];
    int n  = blockIdx.x * 32 + threadIdx.x;
    int k0 = blockIdx.y * 32 + threadIdx.y;
    #pragma unroll
    for (int i = 0; i < 32; i += 8)
        t[threadIdx.y + i][threadIdx.x] = W[(size_t)(k0 + i) * N + n];
    __syncthreads();
    int k  = blockIdx.y * 32 + threadIdx.x;
    int n0 = blockIdx.x * 32 + threadIdx.y;
    #pragma unroll
    for (int i = 0; i < 32; i += 8) {
        float v = t[threadIdx.x][threadIdx.y + i];
        __nv_bfloat16 h, l;
        split2(v, h, l);
        Th[(size_t)(n0 + i) * K + k] = h;
        Tl[(size_t)(n0 + i) * K + k] = l;
    }
}

// ---------------------------------------------------------------------------
// HMMA GEMM core: 128x128 CTA tile, 256 thr (2x4 warps, 64x32 each), BK=32,
// 3-stage cp.async; 3-term bf16 split (hh + hl + lh), fp32 accumulate.
// ---------------------------------------------------------------------------
#define STG_BYTES   32768
#define OFF_AH      0
#define OFF_AL      8192
#define OFF_BH      16384
#define OFF_BL      24576
#define GEMM_SMEM   (3 * STG_BYTES)

struct GemmCtx {
    float acc[4][4][4];
    int wr, wc, lane;
};

__device__ __forceinline__ void gemm_core(
    const __nv_bfloat16* __restrict__ Ah, const __nv_bfloat16* __restrict__ Al,
    const __nv_bfloat16* __restrict__ Bh, const __nv_bfloat16* __restrict__ Bl,
    int N, int K, int row0, int col0, GemmCtx& g)
{
    extern __shared__ char smraw[];
    const uint32_t sbase = smem_u32(smraw);

    const int tid  = threadIdx.x;
    const int wid  = tid >> 5;
    const int lane = tid & 31;
    g.wr = wid >> 2; g.wc = wid & 3; g.lane = lane;

    const int f_row = tid >> 1;
    const int f_c0  = (tid & 1) * 2;
    const int nIter = K >> 5;
    const int lm_row = lane & 15;
    const int lm_koc = (lane >> 4) * 8;

    #pragma unroll
    for (int mf = 0; mf < 4; mf++)
        #pragma unroll
        for (int nf = 0; nf < 4; nf++)
            #pragma unroll
            for (int r = 0; r < 4; r++) g.acc[mf][nf][r] = 0.f;

    auto fill_stage = [&](int s, int kk0) {
        const uint32_t st = sbase + s * STG_BYTES;
        #pragma unroll
        for (int cc = 0; cc < 2; cc++) {
            int c = f_c0 + cc;
            uint32_t off = sw64((uint32_t)(f_row * 64 + c * 16));
            size_t ga = (size_t)(row0 + f_row) * K + kk0 + c * 8;
            size_t gb = (size_t)(col0 + f_row) * K + kk0 + c * 8;
            cp_async16(st + OFF_AH + off, Ah + ga);
            cp_async16(st + OFF_AL + off, Al + ga);
            cp_async16(st + OFF_BH + off, Bh + gb);
            cp_async16(st + OFF_BL + off, Bl + gb);
        }
    };

    fill_stage(0, 0);  cp_commit();
    fill_stage(1, 32); cp_commit();

    for (int kt = 0; kt < nIter; kt++) {
        const int s = kt % 3;
        const uint32_t st = sbase + s * STG_BYTES;

        cp_wait<1>();
        __syncthreads();

        if (kt + 2 < nIter) fill_stage((kt + 2) % 3, (kt + 2) * 32);
        cp_commit();

        #pragma unroll
        for (int ks = 0; ks < 2; ks++) {
            const int colb = (ks * 16 + lm_koc) * 2;
            uint32_t ah[4][4], al[4][4], bh[4][2], bl[4][2];

            #pragma unroll
            for (int mf = 0; mf < 4; mf++) {
                uint32_t off = sw64((uint32_t)((g.wr * 64 + mf * 16 + lm_row) * 64 + colb));
                ldmatrix_x4(ah[mf][0], ah[mf][1], ah[mf][2], ah[mf][3], st + OFF_AH + off);
                ldmatrix_x4(al[mf][0], al[mf][1], al[mf][2], al[mf][3], st + OFF_AL + off);
            }
            #pragma unroll
            for (int np = 0; np < 2; np++) {
                uint32_t off = sw64((uint32_t)((g.wc * 32 + np * 16 + lm_row) * 64 + colb));
                uint32_t r0, r1, r2, r3;
                ldmatrix_x4(r0, r1, r2, r3, st + OFF_BH + off);
                bh[2*np][0] = r0; bh[2*np][1] = r2;
                bh[2*np+1][0] = r1; bh[2*np+1][1] = r3;
                ldmatrix_x4(r0, r1, r2, r3, st + OFF_BL + off);
                bl[2*np][0] = r0; bl[2*np][1] = r2;
                bl[2*np+1][0] = r1; bl[2*np+1][1] = r3;
            }

            #pragma unroll
            for (int mf = 0; mf < 4; mf++)
                #pragma unroll
                for (int nf = 0; nf < 4; nf++) {
                    mma_bf16(g.acc[mf][nf], ah[mf], bh[nf]);
                    mma_bf16(g.acc[mf][nf], ah[mf], bl[nf]);
                    mma_bf16(g.acc[mf][nf], al[mf], bh[nf]);
                }
        }
        __syncthreads();
    }
}

// fp32-output GEMM (+bias) — final projection
__global__ __launch_bounds__(256, 1)
void gemm_mma(const __nv_bfloat16* __restrict__ Ah, const __nv_bfloat16* __restrict__ Al,
              const __nv_bfloat16* __restrict__ Bh, const __nv_bfloat16* __restrict__ Bl,
              const float* __restrict__ bias, float* __restrict__ C,
              int M, int N, int K)
{
    GemmCtx g;
    const int row0 = blockIdx.y * 128;
    const int col0 = blockIdx.x * 128;
    gemm_core(Ah, Al, Bh, Bl, N, K, row0, col0, g);

    const int gq = g.lane >> 2;
    const int t4 = g.lane & 3;
    #pragma unroll
    for (int mf = 0; mf < 4; mf++) {
        int r0g = row0 + g.wr * 64 + mf * 16 + gq;
        #pragma unroll
        for (int nf = 0; nf < 4; nf++) {
            int cg = col0 + g.wc * 32 + nf * 8 + t4 * 2;
            float bx = bias[cg], by = bias[cg + 1];
            float2 v0 = { g.acc[mf][nf][0] + bx, g.acc[mf][nf][1] + by };
            float2 v1 = { g.acc[mf][nf][2] + bx, g.acc[mf][nf][3] + by };
            *(float2*)(C + (size_t)r0g * N + cg)       = v0;
            *(float2*)(C + (size_t)(r0g + 8) * N + cg) = v1;
        }
    }
}

// split-output GEMM: scale applied where global col < scaleN (exact pow2 scale)
__global__ __launch_bounds__(256, 1)
void gemm_mma_split(const __nv_bfloat16* __restrict__ Ah, const __nv_bfloat16* __restrict__ Al,
                    const __nv_bfloat16* __restrict__ Bh, const __nv_bfloat16* __restrict__ Bl,
                    __nv_bfloat16* __restrict__ Oh, __nv_bfloat16* __restrict__ Ol,
                    int M, int N, int K, int scaleN, float scaleV)
{
    GemmCtx g;
    const int row0 = blockIdx.y * 128;
    const int col0 = blockIdx.x * 128;
    gemm_core(Ah, Al, Bh, Bl, N, K, row0, col0, g);

    const int gq = g.lane >> 2;
    const int t4 = g.lane & 3;
    #pragma unroll
    for (int mf = 0; mf < 4; mf++) {
        int r0g = row0 + g.wr * 64 + mf * 16 + gq;
        #pragma unroll
        for (int nf = 0; nf < 4; nf++) {
            int cg = col0 + g.wc * 32 + nf * 8 + t4 * 2;
            float sc = (cg < scaleN) ? scaleV : 1.0f;
            uint32_t h0, l0, h1, l1;
            pack_split(g.acc[mf][nf][0] * sc, g.acc[mf][nf][1] * sc, h0, l0);
            pack_split(g.acc[mf][nf][2] * sc, g.acc[mf][nf][3] * sc, h1, l1);
            *(uint32_t*)(Oh + (size_t)r0g * N + cg)       = h0;
            *(uint32_t*)(Ol + (size_t)r0g * N + cg)       = l0;
            *(uint32_t*)(Oh + (size_t)(r0g + 8) * N + cg) = h1;
            *(uint32_t*)(Ol + (size_t)(r0g + 8) * N + cg) = l1;
        }
    }
}

// ---------------------------------------------------------------------------
// HMMA flash attention, causal tiles, double-buffered K/V, ldmatrix.trans V.
// Grid (16 qtiles reversed, 32 bh). 256 thr = 8 warps x 16 q-rows.
// Input: fused qkv rows of width 3072 (q | k | v), q pre-scaled.
// ---------------------------------------------------------------------------
#define AT_Q_BYTES   32768                    // QH + QL
#define AT_STG_BYTES 32768                    // KH,KL,VH,VL (8KB each)
#define AT_SMEM      (1024 + AT_Q_BYTES + 2 * AT_STG_BYTES)

__global__ __launch_bounds__(256, 1)
void attn_mma(const __nv_bfloat16* __restrict__ qkvh,
              const __nv_bfloat16* __restrict__ qkvl,
              __nv_bfloat16* __restrict__ goh, __nv_bfloat16* __restrict__ gol)
{
    extern __shared__ char smraw[];
    const uint32_t b0a = smem_u32(smraw);
    const uint32_t sb = (b0a + 1023u) & ~1023u;

    const int tid = threadIdx.x;
    const int w = tid >> 5, lane = tid & 31;
    const int gq = lane >> 2, t4 = lane & 3;
    const int lm_row = lane & 15, lm_koc = (lane >> 4) * 8;
    const int vt = lane >> 3, vrl = lane & 7;           // trans-ldsm decomposition
    const int b = blockIdx.y >> 4, h = blockIdx.y & 15;
    const int qt = gridDim.x - 1 - blockIdx.x;          // heavy tiles first
    const int qstart = qt * 128;
    const int igmax = qstart + w * 16 + 15;             // this warp's max q row

    const uint32_t QH = sb, QL = sb + 16384;
    const uint32_t ST0 = sb + AT_Q_BYTES;

    const size_t rowbase = (size_t)(b * SEQ) * QKVW + h * 64;

    // ---- Q fill (cp.async) ----
    #pragma unroll
    for (int it = 0; it < 8; it++) {
        int idx = tid + it * 256;
        int bs = idx >> 10, r = (idx >> 3) & 127, c = idx & 7;
        const __nv_bfloat16* src = (bs ? qkvl : qkvh)
            + rowbase + (size_t)(qstart + r) * QKVW + c * 8;
        cp_async16((bs ? QL : QH) + (uint32_t)(r * 128 + ((c * 16) ^ ((r & 7) << 4))), src);
    }

    // ---- K/V stage fill: 4 tiles (KH,KL,VH,VL) x 64 rows x 64 bf16 ----
    auto fill_kv = [&](int s, int jstart) {
        const uint32_t st = ST0 + s * AT_STG_BYTES;
        #pragma unroll
        for (int it = 0; it < 8; it++) {
            int idx = tid + it * 256;            // 0..2047
            int tile = idx >> 9;                 // 0:KH 1:KL 2:VH 3:VL
            int r = (idx >> 3) & 63, c = idx & 7;
            const __nv_bfloat16* base = (tile & 1) ? qkvl : qkvh;
            int col = ((tile >> 1) ? 2048 : 1024) + c * 8;
            const __nv_bfloat16* src = base + rowbase + (size_t)(jstart + r) * QKVW + col;
            cp_async16(st + (uint32_t)(tile * 8192 + r * 128 + ((c * 16) ^ ((r & 7) << 4))), src);
        }
    };

    fill_kv(0, 0);
    cp_commit();                                // group: Q + KV(0)

    float o[8][4];
    float m[2] = { -INFINITY, -INFINITY }, lsum[2] = { 0.f, 0.f };
    #pragma unroll
    for (int nd = 0; nd < 8; nd++)
        #pragma unroll
        for (int r = 0; r < 4; r++) o[nd][r] = 0.f;

    const int nT = 2 * qt + 2;
    for (int jt = 0; jt < nT; jt++) {
        const int jstart = jt * 64;
        const uint32_t st = ST0 + (jt & 1) * AT_STG_BYTES;
        const uint32_t KH = st, KL = st + 8192, VH = st + 16384, VL = st + 24576;

        if (jt > 0) __syncthreads();            // prev compute done before refill
        if (jt + 1 < nT) {
            fill_kv((jt + 1) & 1, jstart + 64);
            cp_commit();
            cp_wait<1>();
        } else {
            cp_wait<0>();
        }
        __syncthreads();                        // stage jt visible to all warps

        // ---- S = Q @ K^T (3-term split), per-warp causal chunk skip ----
        float s[8][4];
        #pragma unroll
        for (int nj = 0; nj < 8; nj++)
            #pragma unroll
            for (int r = 0; r < 4; r++) s[nj][r] = 0.f;

        #pragma unroll
        for (int kd = 0; kd < 4; kd++) {
            const int cb = (kd * 16 + lm_koc) * 2;
            uint32_t ah[4], al[4];
            {
                int r = w * 16 + lm_row;
                uint32_t off = (uint32_t)(r * 128 + (cb ^ ((r & 7) << 4)));
                ldmatrix_x4(ah[0], ah[1], ah[2], ah[3], QH + off);
                ldmatrix_x4(al[0], al[1], al[2], al[3], QL + off);
            }
            #pragma unroll
            for (int jp = 0; jp < 4; jp++) {
                if (jstart + jp * 16 > igmax) continue;   // fully masked chunk
                int r = jp * 16 + lm_row;
                uint32_t off = (uint32_t)(r * 128 + (cb ^ ((r & 7) << 4)));
                uint32_t r0, r1, r2, r3;
                uint32_t bh0[2], bh1[2], bl0[2], bl1[2];
                ldmatrix_x4(r0, r1, r2, r3, KH + off);
                bh0[0] = r0; bh0[1] = r2; bh1[0] = r1; bh1[1] = r3;
                ldmatrix_x4(r0, r1, r2, r3, KL + off);
                bl0[0] = r0; bl0[1] = r2; bl1[0] = r1; bl1[1] = r3;
                mma_bf16(s[2*jp],   ah, bh0); mma_bf16(s[2*jp],   ah, bl0); mma_bf16(s[2*jp],   al, bh0);
                mma_bf16(s[2*jp+1], ah, bh1); mma_bf16(s[2*jp+1], ah, bl1); mma_bf16(s[2*jp+1], al, bh1);
            }
        }

        // ---- online softmax (rows gq / gq+8 per thread) ----
        float alpha[2];
        #pragma unroll
        for (int hh = 0; hh < 2; hh++) {
            float mx = -INFINITY;
            #pragma unroll
            for (int nj = 0; nj < 8; nj++)
                mx = fmaxf(mx, fmaxf(s[nj][2*hh], s[nj][2*hh+1]));
            mx = fmaxf(mx, __shfl_xor_sync(0xffffffffu, mx, 1));
            mx = fmaxf(mx, __shfl_xor_sync(0xffffffffu, mx, 2));
            float mn = fmaxf(m[hh], mx);
            alpha[hh] = __expf(m[hh] - mn);
            m[hh] = mn;
            const int ig = qstart + w * 16 + hh * 8 + gq;
            float rs = 0.f;
            #pragma unroll
            for (int nj = 0; nj < 8; nj++) {
                int jg = jstart + nj * 8 + t4 * 2;
                float p0 = (jg     <= ig) ? __expf(s[nj][2*hh]   - mn) : 0.f;
                float p1 = (jg + 1 <= ig) ? __expf(s[nj][2*hh+1] - mn) : 0.f;
                s[nj][2*hh] = p0; s[nj][2*hh+1] = p1;
                rs += p0 + p1;
            }
            rs += __shfl_xor_sync(0xffffffffu, rs, 1);
            rs += __shfl_xor_sync(0xffffffffu, rs, 2);
            lsum[hh] = lsum[hh] * alpha[hh] + rs;
        }
        #pragma unroll
        for (int nd = 0; nd < 8; nd++) {
            o[nd][0] *= alpha[0]; o[nd][1] *= alpha[0];
            o[nd][2] *= alpha[1]; o[nd][3] *= alpha[1];
        }

        // ---- O += P @ V (V via ldmatrix.trans from row-major smem) ----
        #pragma unroll
        for (int kj = 0; kj < 4; kj++) {
            if (jstart + kj * 16 > igmax) continue;       // P chunk all zero
            uint32_t ph[4], pl[4];
            pack_split(s[2*kj][0],   s[2*kj][1],   ph[0], pl[0]);
            pack_split(s[2*kj][2],   s[2*kj][3],   ph[1], pl[1]);
            pack_split(s[2*kj+1][0], s[2*kj+1][1], ph[2], pl[2]);
            pack_split(s[2*kj+1][2], s[2*kj+1][3], ph[3], pl[3]);
            const int j = kj * 16 + (vt & 1) * 8 + vrl;   // source V row
            const uint32_t jsw = (uint32_t)(j * 128);
            const int ch = (vt >> 1);                      // n-octet within 16
            #pragma unroll
            for (int ndp = 0; ndp < 4; ndp++) {
                int c = ndp * 2 + ch;                      // 16B chunk in row
                uint32_t off = jsw + (uint32_t)((c * 16) ^ ((j & 7) << 4));
                uint32_t r0, r1, r2, r3;
                uint32_t bh0[2], bh1[2], bl0[2], bl1[2];
                ldmatrix_x4_trans(r0, r1, r2, r3, VH + off);
                bh0[0] = r0; bh0[1] = r1; bh1[0] = r2; bh1[1] = r3;
                ldmatrix_x4_trans(r0, r1, r2, r3, VL + off);
                bl0[0] = r0; bl0[1] = r1; bl1[0] = r2; bl1[1] = r3;
                mma_bf16(o[2*ndp],   ph, bh0); mma_bf16(o[2*ndp],   ph, bl0); mma_bf16(o[2*ndp],   pl, bh0);
                mma_bf16(o[2*ndp+1], ph, bh1); mma_bf16(o[2*ndp+1], ph, bl1); mma_bf16(o[2*ndp+1], pl, bh1);
            }
        }
    }

    // ---- epilogue: normalize, split hi/lo, store [b,n,h*64+d] ----
    const float inv0 = 1.0f / (lsum[0] + ATTN_EPS);
    const float inv1 = 1.0f / (lsum[1] + ATTN_EPS);
    const size_t base0 = (size_t)(b * SEQ + qstart + w * 16 + gq) * INNER + h * 64 + t4 * 2;
    const size_t base1 = base0 + (size_t)8 * INNER;
    #pragma unroll
    for (int nd = 0; nd < 8; nd++) {
        uint32_t h0, l0, h1, l1;
        pack_split(o[nd][0] * inv0, o[nd][1] * inv0, h0, l0);
        pack_split(o[nd][2] * inv1, o[nd][3] * inv1, h1, l1);
        *(uint32_t*)(goh + base0 + nd * 8) = h0;
        *(uint32_t*)(gol + base0 + nd * 8) = l0;
        *(uint32_t*)(goh + base1 + nd * 8) = h1;
        *(uint32_t*)(gol + base1 + nd * 8) = l1;
    }
}

// ---------------------------------------------------------------------------
// Launch
// ---------------------------------------------------------------------------
extern "C" void kernel_launch(void* const* d_in, const int* in_sizes, int n_in,
                              void* d_out, int out_size)
{
    const float* x   = (const float*)d_in[0];
    const float* Wq  = (const float*)d_in[1];
    const float* Wkv = (const float*)d_in[2];
    const float* Wo  = (const float*)d_in[3];
    const float* bo  = (const float*)d_in[4];
    float* out = (float*)d_out;

    __nv_bfloat16 *pxh, *pxl, *pw1h, *pw1l, *pwoh, *pwol;
    __nv_bfloat16 *pqkvh, *pqkvl, *path, *patl;
    cudaGetSymbolAddress((void**)&pxh,   g_xh);
    cudaGetSymbolAddress((void**)&pxl,   g_xl);
    cudaGetSymbolAddress((void**)&pw1h,  g_w1h);
    cudaGetSymbolAddress((void**)&pw1l,  g_w1l);
    cudaGetSymbolAddress((void**)&pwoh,  g_wot_h);
    cudaGetSymbolAddress((void**)&pwol,  g_wot_l);
    cudaGetSymbolAddress((void**)&pqkvh, g_qkvh);
    cudaGetSymbolAddress((void**)&pqkvl, g_qkvl);
    cudaGetSymbolAddress((void**)&path,  g_ath);
    cudaGetSymbolAddress((void**)&patl,  g_atl);

    cudaFuncSetAttribute(gemm_mma,
                         cudaFuncAttributeMaxDynamicSharedMemorySize, GEMM_SMEM);
    cudaFuncSetAttribute(gemm_mma_split,
                         cudaFuncAttributeMaxDynamicSharedMemorySize, GEMM_SMEM);
    cudaFuncSetAttribute(attn_mma,
                         cudaFuncAttributeMaxDynamicSharedMemorySize, AT_SMEM);

    // --- prep: split x; transpose Wq,Wkv into fused [3072,1024]; Wo ---
    {
        int n4 = ROWS * DMODEL / 4;
        split_kernel<<<(n4 + 255) / 256, 256>>>(x, pxh, pxl, n4);
    }
    transpose_split<<<dim3(INNER / 32, DMODEL / 32),     dim3(32, 8)>>>(
        Wq,  pw1h, pw1l, DMODEL, INNER);
    transpose_split<<<dim3(2 * INNER / 32, DMODEL / 32), dim3(32, 8)>>>(
        Wkv, pw1h + (size_t)INNER * DMODEL, pw1l + (size_t)INNER * DMODEL,
        DMODEL, 2 * INNER);
    transpose_split<<<dim3(DMODEL / 32, INNER / 32),     dim3(32, 8)>>>(
        Wo,  pwoh, pwol, INNER, DMODEL);

    // --- fused projection: [q|kv] = x @ [Wq Wkv], q pre-scaled by 0.125 ---
    gemm_mma_split<<<dim3(QKVW / 128, ROWS / 128), 256, GEMM_SMEM>>>(
        pxh, pxl, pw1h, pw1l, pqkvh, pqkvl, ROWS, QKVW, DMODEL, INNER, 0.125f);

    // --- attention (HMMA, causal, double-buffered) ---
    attn_mma<<<dim3(SEQ / 128, BATCH * HEADS), 256, AT_SMEM>>>(
        pqkvh, pqkvl, path, patl);

    // --- out = att @ Wo + bo ---
    gemm_mma<<<dim3(DMODEL / 128, ROWS / 128), 256, GEMM_SMEM>>>(
        path, patl, pwoh, pwol, bo, out, ROWS, DMODEL, INNER);
}

// round 8
// speedup vs baseline: 2.8323x; 1.1183x over previous
#include <cuda_runtime.h>
#include <cuda_bf16.h>
#include <math.h>
#include <stdint.h>

// ---------------------------------------------------------------------------
// Problem constants
// ---------------------------------------------------------------------------
#define BATCH   2
#define SEQ     2048
#define DMODEL  1024
#define HEADS   16
#define DHEAD   64
#define INNER   (HEADS * DHEAD)      // 1024
#define ROWS    (BATCH * SEQ)        // 4096
#define QKVW    (3 * INNER)          // 3072
#define ATTN_EPS 1e-8f

// ---------------------------------------------------------------------------
// Scratch (device globals)
// ---------------------------------------------------------------------------
__device__ __nv_bfloat16 g_xh  [ROWS * DMODEL];
__device__ __nv_bfloat16 g_xl  [ROWS * DMODEL];
__device__ __nv_bfloat16 g_w1h [QKVW * DMODEL];       // [Wq^T; Wkv^T]
__device__ __nv_bfloat16 g_w1l [QKVW * DMODEL];
__device__ __nv_bfloat16 g_wot_h [DMODEL * INNER];
__device__ __nv_bfloat16 g_wot_l [DMODEL * INNER];
__device__ __nv_bfloat16 g_qkvh [ROWS * QKVW];
__device__ __nv_bfloat16 g_qkvl [ROWS * QKVW];
__device__ __nv_bfloat16 g_ath [ROWS * INNER];
__device__ __nv_bfloat16 g_atl [ROWS * INNER];

// ---------------------------------------------------------------------------
// Helpers (base ISA only)
// ---------------------------------------------------------------------------
__device__ __forceinline__ uint32_t smem_u32(const void* p) {
    uint32_t a;
    asm("{ .reg .u64 t; cvta.to.shared.u64 t, %1; cvt.u32.u64 %0, t; }"
        : "=r"(a) : "l"(p));
    return a;
}

__device__ __forceinline__ void ldmatrix_x4(uint32_t& r0, uint32_t& r1,
                                            uint32_t& r2, uint32_t& r3,
                                            uint32_t addr) {
    asm volatile("ldmatrix.sync.aligned.m8n8.x4.shared.b16 {%0,%1,%2,%3}, [%4];"
                 : "=r"(r0), "=r"(r1), "=r"(r2), "=r"(r3) : "r"(addr));
}

__device__ __forceinline__ void ldmatrix_x4_trans(uint32_t& r0, uint32_t& r1,
                                                  uint32_t& r2, uint32_t& r3,
                                                  uint32_t addr) {
    asm volatile("ldmatrix.sync.aligned.m8n8.x4.trans.shared.b16 {%0,%1,%2,%3}, [%4];"
                 : "=r"(r0), "=r"(r1), "=r"(r2), "=r"(r3) : "r"(addr));
}

__device__ __forceinline__ void mma_bf16(float* d, const uint32_t* a, const uint32_t* b) {
    asm volatile(
        "mma.sync.aligned.m16n8k16.row.col.f32.bf16.bf16.f32 "
        "{%0,%1,%2,%3}, {%4,%5,%6,%7}, {%8,%9}, {%0,%1,%2,%3};"
        : "+f"(d[0]), "+f"(d[1]), "+f"(d[2]), "+f"(d[3])
        : "r"(a[0]), "r"(a[1]), "r"(a[2]), "r"(a[3]), "r"(b[0]), "r"(b[1]));
}

__device__ __forceinline__ void cp_async16(uint32_t saddr, const void* gaddr) {
    asm volatile("cp.async.cg.shared.global [%0], [%1], 16;"
                 :: "r"(saddr), "l"(gaddr));
}
__device__ __forceinline__ void cp_commit() {
    asm volatile("cp.async.commit_group;" ::: "memory");
}
template <int N>
__device__ __forceinline__ void cp_wait() {
    asm volatile("cp.async.wait_group %0;" :: "n"(N) : "memory");
}

__device__ __forceinline__ uint32_t sw64(uint32_t byte) {
    return byte ^ ((byte >> 3) & 0x30);
}

__device__ __forceinline__ void split2(float v, __nv_bfloat16& h, __nv_bfloat16& l) {
    h = __float2bfloat16(v);
    l = __float2bfloat16(v - __bfloat162float(h));
}

__device__ __forceinline__ void pack_split(float a, float b, uint32_t& hi, uint32_t& lo) {
    __nv_bfloat16 ha = __float2bfloat16(a), hb = __float2bfloat16(b);
    float ra = a - __bfloat162float(ha), rb = b - __bfloat162float(hb);
    __nv_bfloat162 H; H.x = ha; H.y = hb;
    __nv_bfloat162 L; L.x = __float2bfloat16(ra); L.y = __float2bfloat16(rb);
    hi = *(uint32_t*)&H;
    lo = *(uint32_t*)&L;
}

// ---------------------------------------------------------------------------
// Prep kernels
// ---------------------------------------------------------------------------
__global__ __launch_bounds__(256)
void split_kernel(const float* __restrict__ X,
                  __nv_bfloat16* __restrict__ H, __nv_bfloat16* __restrict__ L, int n4)
{
    int i = blockIdx.x * blockDim.x + threadIdx.x;
    if (i >= n4) return;
    float4 v = ((const float4*)X)[i];
    union { __nv_bfloat16 b[4]; uint2 u; } uh, ul;
    split2(v.x, uh.b[0], ul.b[0]);
    split2(v.y, uh.b[1], ul.b[1]);
    split2(v.z, uh.b[2], ul.b[2]);
    split2(v.w, uh.b[3], ul.b[3]);
    ((uint2*)H)[i] = uh.u;
    ((uint2*)L)[i] = ul.u;
}

__global__ __launch_bounds__(256)
void transpose_split(const float* __restrict__ W,
                     __nv_bfloat16* __restrict__ Th, __nv_bfloat16* __restrict__ Tl,
                     int K, int N)
{
    __shared__ float t[32][33];
    int n  = blockIdx.x * 32 + threadIdx.x;
    int k0 = blockIdx.y * 32 + threadIdx.y;
    #pragma unroll
    for (int i = 0; i < 32; i += 8)
        t[threadIdx.y + i][threadIdx.x] = W[(size_t)(k0 + i) * N + n];
    __syncthreads();
    int k  = blockIdx.y * 32 + threadIdx.x;
    int n0 = blockIdx.x * 32 + threadIdx.y;
    #pragma unroll
    for (int i = 0; i < 32; i += 8) {
        float v = t[threadIdx.x][threadIdx.y + i];
        __nv_bfloat16 h, l;
        split2(v, h, l);
        Th[(size_t)(n0 + i) * K + k] = h;
        Tl[(size_t)(n0 + i) * K + k] = l;
    }
}

// ---------------------------------------------------------------------------
// HMMA GEMM core v2: 256x128 CTA tile, 256 thr (4x2 warps, 64x64 each),
// BK=32, 3-stage cp.async; 3-term bf16 split, fp32 accumulate.
// Per-stage smem: AH 16K | AL 16K | BH 8K | BL 8K = 48K; 3 stages = 144K.
// ---------------------------------------------------------------------------
#define STG_BYTES   49152
#define OFF_AH      0
#define OFF_AL      16384
#define OFF_BH      32768
#define OFF_BL      40960
#define GEMM_SMEM   (3 * STG_BYTES)

struct GemmCtx {
    float acc[4][8][4];
    int wr, wc, lane;
};

__device__ __forceinline__ void gemm_core(
    const __nv_bfloat16* __restrict__ Ah, const __nv_bfloat16* __restrict__ Al,
    const __nv_bfloat16* __restrict__ Bh, const __nv_bfloat16* __restrict__ Bl,
    int N, int K, int row0, int col0, GemmCtx& g)
{
    extern __shared__ char smraw[];
    const uint32_t sbase = smem_u32(smraw);

    const int tid  = threadIdx.x;
    const int wid  = tid >> 5;
    const int lane = tid & 31;
    g.wr = wid & 3; g.wc = wid >> 2; g.lane = lane;   // 4 x 2 warp grid

    const int nIter = K >> 5;
    const int lm_row = lane & 15;
    const int lm_koc = (lane >> 4) * 8;

    #pragma unroll
    for (int mf = 0; mf < 4; mf++)
        #pragma unroll
        for (int nf = 0; nf < 8; nf++)
            #pragma unroll
            for (int r = 0; r < 4; r++) g.acc[mf][nf][r] = 0.f;

    auto fill_stage = [&](int s, int kk0) {
        const uint32_t st = sbase + s * STG_BYTES;
        // A: 256 rows x 4 chunks, hi+lo
        #pragma unroll
        for (int it = 0; it < 4; it++) {
            int idx = tid + it * 256;            // 0..1023
            int r = idx >> 2, c = idx & 3;
            uint32_t off = sw64((uint32_t)(r * 64 + c * 16));
            size_t ga = (size_t)(row0 + r) * K + kk0 + c * 8;
            cp_async16(st + OFF_AH + off, Ah + ga);
            cp_async16(st + OFF_AL + off, Al + ga);
        }
        // B: 128 rows x 4 chunks, hi+lo
        #pragma unroll
        for (int it = 0; it < 2; it++) {
            int idx = tid + it * 256;            // 0..511
            int r = idx >> 2, c = idx & 3;
            uint32_t off = sw64((uint32_t)(r * 64 + c * 16));
            size_t gb = (size_t)(col0 + r) * K + kk0 + c * 8;
            cp_async16(st + OFF_BH + off, Bh + gb);
            cp_async16(st + OFF_BL + off, Bl + gb);
        }
    };

    fill_stage(0, 0);  cp_commit();
    fill_stage(1, 32); cp_commit();

    for (int kt = 0; kt < nIter; kt++) {
        const int s = kt % 3;
        const uint32_t st = sbase + s * STG_BYTES;

        cp_wait<1>();
        __syncthreads();

        if (kt + 2 < nIter) fill_stage((kt + 2) % 3, (kt + 2) * 32);
        cp_commit();

        #pragma unroll
        for (int ks = 0; ks < 2; ks++) {
            const int colb = (ks * 16 + lm_koc) * 2;
            uint32_t ah[4][4], al[4][4];

            #pragma unroll
            for (int mf = 0; mf < 4; mf++) {
                int r = g.wr * 64 + mf * 16 + lm_row;
                uint32_t off = sw64((uint32_t)(r * 64 + colb));
                ldmatrix_x4(ah[mf][0], ah[mf][1], ah[mf][2], ah[mf][3], st + OFF_AH + off);
                ldmatrix_x4(al[mf][0], al[mf][1], al[mf][2], al[mf][3], st + OFF_AL + off);
            }
            #pragma unroll
            for (int np = 0; np < 4; np++) {
                int r = g.wc * 64 + np * 16 + lm_row;
                uint32_t off = sw64((uint32_t)(r * 64 + colb));
                uint32_t r0, r1, r2, r3;
                uint32_t bh0[2], bh1[2], bl0[2], bl1[2];
                ldmatrix_x4(r0, r1, r2, r3, st + OFF_BH + off);
                bh0[0] = r0; bh0[1] = r2; bh1[0] = r1; bh1[1] = r3;
                ldmatrix_x4(r0, r1, r2, r3, st + OFF_BL + off);
                bl0[0] = r0; bl0[1] = r2; bl1[0] = r1; bl1[1] = r3;
                #pragma unroll
                for (int mf = 0; mf < 4; mf++) {
                    mma_bf16(g.acc[mf][2*np],   ah[mf], bh0);
                    mma_bf16(g.acc[mf][2*np],   ah[mf], bl0);
                    mma_bf16(g.acc[mf][2*np],   al[mf], bh0);
                    mma_bf16(g.acc[mf][2*np+1], ah[mf], bh1);
                    mma_bf16(g.acc[mf][2*np+1], ah[mf], bl1);
                    mma_bf16(g.acc[mf][2*np+1], al[mf], bh1);
                }
            }
        }
        __syncthreads();
    }
}

// fp32-output GEMM (+bias) — final projection
__global__ __launch_bounds__(256, 1)
void gemm_mma(const __nv_bfloat16* __restrict__ Ah, const __nv_bfloat16* __restrict__ Al,
              const __nv_bfloat16* __restrict__ Bh, const __nv_bfloat16* __restrict__ Bl,
              const float* __restrict__ bias, float* __restrict__ C,
              int M, int N, int K)
{
    GemmCtx g;
    const int row0 = blockIdx.y * 256;
    const int col0 = blockIdx.x * 128;
    gemm_core(Ah, Al, Bh, Bl, N, K, row0, col0, g);

    const int gq = g.lane >> 2;
    const int t4 = g.lane & 3;
    #pragma unroll
    for (int mf = 0; mf < 4; mf++) {
        int r0g = row0 + g.wr * 64 + mf * 16 + gq;
        #pragma unroll
        for (int nf = 0; nf < 8; nf++) {
            int cg = col0 + g.wc * 64 + nf * 8 + t4 * 2;
            float bx = bias[cg], by = bias[cg + 1];
            float2 v0 = { g.acc[mf][nf][0] + bx, g.acc[mf][nf][1] + by };
            float2 v1 = { g.acc[mf][nf][2] + bx, g.acc[mf][nf][3] + by };
            *(float2*)(C + (size_t)r0g * N + cg)       = v0;
            *(float2*)(C + (size_t)(r0g + 8) * N + cg) = v1;
        }
    }
}

// split-output GEMM: scale cols < scaleN by scaleV (exact pow2)
__global__ __launch_bounds__(256, 1)
void gemm_mma_split(const __nv_bfloat16* __restrict__ Ah, const __nv_bfloat16* __restrict__ Al,
                    const __nv_bfloat16* __restrict__ Bh, const __nv_bfloat16* __restrict__ Bl,
                    __nv_bfloat16* __restrict__ Oh, __nv_bfloat16* __restrict__ Ol,
                    int M, int N, int K, int scaleN, float scaleV)
{
    GemmCtx g;
    const int row0 = blockIdx.y * 256;
    const int col0 = blockIdx.x * 128;
    gemm_core(Ah, Al, Bh, Bl, N, K, row0, col0, g);

    const int gq = g.lane >> 2;
    const int t4 = g.lane & 3;
    #pragma unroll
    for (int mf = 0; mf < 4; mf++) {
        int r0g = row0 + g.wr * 64 + mf * 16 + gq;
        #pragma unroll
        for (int nf = 0; nf < 8; nf++) {
            int cg = col0 + g.wc * 64 + nf * 8 + t4 * 2;
            float sc = (cg < scaleN) ? scaleV : 1.0f;
            uint32_t h0, l0, h1, l1;
            pack_split(g.acc[mf][nf][0] * sc, g.acc[mf][nf][1] * sc, h0, l0);
            pack_split(g.acc[mf][nf][2] * sc, g.acc[mf][nf][3] * sc, h1, l1);
            *(uint32_t*)(Oh + (size_t)r0g * N + cg)       = h0;
            *(uint32_t*)(Ol + (size_t)r0g * N + cg)       = l0;
            *(uint32_t*)(Oh + (size_t)(r0g + 8) * N + cg) = h1;
            *(uint32_t*)(Ol + (size_t)(r0g + 8) * N + cg) = l1;
        }
    }
}

// ---------------------------------------------------------------------------
// HMMA flash attention v2: 4 warps x 32 q-rows (Br=128, Bc=64),
// double-buffered K/V, ldmatrix.trans V, 2 CTAs/SM.
// ---------------------------------------------------------------------------
#define AT_Q_BYTES   32768
#define AT_STG_BYTES 32768
#define AT_SMEM      (1024 + AT_Q_BYTES + 2 * AT_STG_BYTES)

__global__ __launch_bounds__(128, 2)
void attn_mma(const __nv_bfloat16* __restrict__ qkvh,
              const __nv_bfloat16* __restrict__ qkvl,
              __nv_bfloat16* __restrict__ goh, __nv_bfloat16* __restrict__ gol)
{
    extern __shared__ char smraw[];
    const uint32_t b0a = smem_u32(smraw);
    const uint32_t sb = (b0a + 1023u) & ~1023u;

    const int tid = threadIdx.x;
    const int w = tid >> 5, lane = tid & 31;
    const int gq = lane >> 2, t4 = lane & 3;
    const int lm_row = lane & 15, lm_koc = (lane >> 4) * 8;
    const int vt = lane >> 3, vrl = lane & 7;
    const int b = blockIdx.y >> 4, h = blockIdx.y & 15;
    const int qt = gridDim.x - 1 - blockIdx.x;
    const int qstart = qt * 128;
    const int igmax = qstart + w * 32 + 31;

    const uint32_t QH = sb, QL = sb + 16384;
    const uint32_t ST0 = sb + AT_Q_BYTES;

    const size_t rowbase = (size_t)(b * SEQ) * QKVW + h * 64;

    // ---- Q fill ----
    #pragma unroll
    for (int it = 0; it < 16; it++) {
        int idx = tid + it * 128;
        int bs = idx >> 10, r = (idx >> 3) & 127, c = idx & 7;
        const __nv_bfloat16* src = (bs ? qkvl : qkvh)
            + rowbase + (size_t)(qstart + r) * QKVW + c * 8;
        cp_async16((bs ? QL : QH) + (uint32_t)(r * 128 + ((c * 16) ^ ((r & 7) << 4))), src);
    }

    auto fill_kv = [&](int s, int jstart) {
        const uint32_t st = ST0 + s * AT_STG_BYTES;
        #pragma unroll
        for (int it = 0; it < 16; it++) {
            int idx = tid + it * 128;            // 0..2047
            int tile = idx >> 9;                 // 0:KH 1:KL 2:VH 3:VL
            int r = (idx >> 3) & 63, c = idx & 7;
            const __nv_bfloat16* base = (tile & 1) ? qkvl : qkvh;
            int col = ((tile >> 1) ? 2048 : 1024) + c * 8;
            const __nv_bfloat16* src = base + rowbase + (size_t)(jstart + r) * QKVW + col;
            cp_async16(st + (uint32_t)(tile * 8192 + r * 128 + ((c * 16) ^ ((r & 7) << 4))), src);
        }
    };

    fill_kv(0, 0);
    cp_commit();                                 // group: Q + KV(0)

    float o[2][8][4];
    float m[4] = { -INFINITY, -INFINITY, -INFINITY, -INFINITY };
    float lsum[4] = { 0.f, 0.f, 0.f, 0.f };
    #pragma unroll
    for (int mf = 0; mf < 2; mf++)
        #pragma unroll
        for (int nd = 0; nd < 8; nd++)
            #pragma unroll
            for (int r = 0; r < 4; r++) o[mf][nd][r] = 0.f;

    const int nT = 2 * qt + 2;
    for (int jt = 0; jt < nT; jt++) {
        const int jstart = jt * 64;
        const uint32_t st = ST0 + (jt & 1) * AT_STG_BYTES;
        const uint32_t KH = st, KL = st + 8192, VH = st + 16384, VL = st + 24576;

        if (jt > 0) __syncthreads();
        if (jt + 1 < nT) {
            fill_kv((jt + 1) & 1, jstart + 64);
            cp_commit();
            cp_wait<1>();
        } else {
            cp_wait<0>();
        }
        __syncthreads();

        // ---- S = Q @ K^T (3-term split) ----
        float s[2][8][4];
        #pragma unroll
        for (int mf = 0; mf < 2; mf++)
            #pragma unroll
            for (int nj = 0; nj < 8; nj++)
                #pragma unroll
                for (int r = 0; r < 4; r++) s[mf][nj][r] = 0.f;

        #pragma unroll
        for (int kd = 0; kd < 4; kd++) {
            const int cb = (kd * 16 + lm_koc) * 2;
            uint32_t qa[2][4], qb[2][4];
            #pragma unroll
            for (int mf = 0; mf < 2; mf++) {
                int r = w * 32 + mf * 16 + lm_row;
                uint32_t off = (uint32_t)(r * 128 + (cb ^ ((r & 7) << 4)));
                ldmatrix_x4(qa[mf][0], qa[mf][1], qa[mf][2], qa[mf][3], QH + off);
                ldmatrix_x4(qb[mf][0], qb[mf][1], qb[mf][2], qb[mf][3], QL + off);
            }
            #pragma unroll
            for (int jp = 0; jp < 4; jp++) {
                if (jstart + jp * 16 > igmax) continue;
                int r = jp * 16 + lm_row;
                uint32_t off = (uint32_t)(r * 128 + (cb ^ ((r & 7) << 4)));
                uint32_t r0, r1, r2, r3;
                uint32_t bh0[2], bh1[2], bl0[2], bl1[2];
                ldmatrix_x4(r0, r1, r2, r3, KH + off);
                bh0[0] = r0; bh0[1] = r2; bh1[0] = r1; bh1[1] = r3;
                ldmatrix_x4(r0, r1, r2, r3, KL + off);
                bl0[0] = r0; bl0[1] = r2; bl1[0] = r1; bl1[1] = r3;
                #pragma unroll
                for (int mf = 0; mf < 2; mf++) {
                    mma_bf16(s[mf][2*jp],   qa[mf], bh0);
                    mma_bf16(s[mf][2*jp],   qa[mf], bl0);
                    mma_bf16(s[mf][2*jp],   qb[mf], bh0);
                    mma_bf16(s[mf][2*jp+1], qa[mf], bh1);
                    mma_bf16(s[mf][2*jp+1], qa[mf], bl1);
                    mma_bf16(s[mf][2*jp+1], qb[mf], bh1);
                }
            }
        }

        // ---- online softmax (4 row-halves per thread) ----
        float alpha[4];
        #pragma unroll
        for (int mf = 0; mf < 2; mf++) {
            #pragma unroll
            for (int hh = 0; hh < 2; hh++) {
                const int hr = 2 * mf + hh;
                float mx = -INFINITY;
                #pragma unroll
                for (int nj = 0; nj < 8; nj++)
                    mx = fmaxf(mx, fmaxf(s[mf][nj][2*hh], s[mf][nj][2*hh+1]));
                mx = fmaxf(mx, __shfl_xor_sync(0xffffffffu, mx, 1));
                mx = fmaxf(mx, __shfl_xor_sync(0xffffffffu, mx, 2));
                float mn = fmaxf(m[hr], mx);
                alpha[hr] = __expf(m[hr] - mn);
                m[hr] = mn;
                const int ig = qstart + w * 32 + mf * 16 + hh * 8 + gq;
                float rs = 0.f;
                #pragma unroll
                for (int nj = 0; nj < 8; nj++) {
                    int jg = jstart + nj * 8 + t4 * 2;
                    float p0 = (jg     <= ig) ? __expf(s[mf][nj][2*hh]   - mn) : 0.f;
                    float p1 = (jg + 1 <= ig) ? __expf(s[mf][nj][2*hh+1] - mn) : 0.f;
                    s[mf][nj][2*hh] = p0; s[mf][nj][2*hh+1] = p1;
                    rs += p0 + p1;
                }
                rs += __shfl_xor_sync(0xffffffffu, rs, 1);
                rs += __shfl_xor_sync(0xffffffffu, rs, 2);
                lsum[hr] = lsum[hr] * alpha[hr] + rs;
            }
            #pragma unroll
            for (int nd = 0; nd < 8; nd++) {
                o[mf][nd][0] *= alpha[2*mf];     o[mf][nd][1] *= alpha[2*mf];
                o[mf][nd][2] *= alpha[2*mf + 1]; o[mf][nd][3] *= alpha[2*mf + 1];
            }
        }

        // ---- O += P @ V ----
        #pragma unroll
        for (int kj = 0; kj < 4; kj++) {
            if (jstart + kj * 16 > igmax) continue;
            uint32_t ph[2][4], pl[2][4];
            #pragma unroll
            for (int mf = 0; mf < 2; mf++) {
                pack_split(s[mf][2*kj][0],   s[mf][2*kj][1],   ph[mf][0], pl[mf][0]);
                pack_split(s[mf][2*kj][2],   s[mf][2*kj][3],   ph[mf][1], pl[mf][1]);
                pack_split(s[mf][2*kj+1][0], s[mf][2*kj+1][1], ph[mf][2], pl[mf][2]);
                pack_split(s[mf][2*kj+1][2], s[mf][2*kj+1][3], ph[mf][3], pl[mf][3]);
            }
            const int j = kj * 16 + (vt & 1) * 8 + vrl;
            const uint32_t jsw = (uint32_t)(j * 128);
            const int ch = (vt >> 1);
            #pragma unroll
            for (int ndp = 0; ndp < 4; ndp++) {
                int c = ndp * 2 + ch;
                uint32_t off = jsw + (uint32_t)((c * 16) ^ ((j & 7) << 4));
                uint32_t r0, r1, r2, r3;
                uint32_t bh0[2], bh1[2], bl0[2], bl1[2];
                ldmatrix_x4_trans(r0, r1, r2, r3, VH + off);
                bh0[0] = r0; bh0[1] = r1; bh1[0] = r2; bh1[1] = r3;
                ldmatrix_x4_trans(r0, r1, r2, r3, VL + off);
                bl0[0] = r0; bl0[1] = r1; bl1[0] = r2; bl1[1] = r3;
                #pragma unroll
                for (int mf = 0; mf < 2; mf++) {
                    mma_bf16(o[mf][2*ndp],   ph[mf], bh0);
                    mma_bf16(o[mf][2*ndp],   ph[mf], bl0);
                    mma_bf16(o[mf][2*ndp],   pl[mf], bh0);
                    mma_bf16(o[mf][2*ndp+1], ph[mf], bh1);
                    mma_bf16(o[mf][2*ndp+1], ph[mf], bl1);
                    mma_bf16(o[mf][2*ndp+1], pl[mf], bh1);
                }
            }
        }
    }

    // ---- epilogue ----
    #pragma unroll
    for (int mf = 0; mf < 2; mf++) {
        const float inv0 = 1.0f / (lsum[2*mf]     + ATTN_EPS);
        const float inv1 = 1.0f / (lsum[2*mf + 1] + ATTN_EPS);
        const size_t base0 = (size_t)(b * SEQ + qstart + w * 32 + mf * 16 + gq) * INNER
                           + h * 64 + t4 * 2;
        const size_t base1 = base0 + (size_t)8 * INNER;
        #pragma unroll
        for (int nd = 0; nd < 8; nd++) {
            uint32_t h0, l0, h1, l1;
            pack_split(o[mf][nd][0] * inv0, o[mf][nd][1] * inv0, h0, l0);
            pack_split(o[mf][nd][2] * inv1, o[mf][nd][3] * inv1, h1, l1);
            *(uint32_t*)(goh + base0 + nd * 8) = h0;
            *(uint32_t*)(gol + base0 + nd * 8) = l0;
            *(uint32_t*)(goh + base1 + nd * 8) = h1;
            *(uint32_t*)(gol + base1 + nd * 8) = l1;
        }
    }
}

// ---------------------------------------------------------------------------
// Launch
// ---------------------------------------------------------------------------
extern "C" void kernel_launch(void* const* d_in, const int* in_sizes, int n_in,
                              void* d_out, int out_size)
{
    const float* x   = (const float*)d_in[0];
    const float* Wq  = (const float*)d_in[1];
    const float* Wkv = (const float*)d_in[2];
    const float* Wo  = (const float*)d_in[3];
    const float* bo  = (const float*)d_in[4];
    float* out = (float*)d_out;

    __nv_bfloat16 *pxh, *pxl, *pw1h, *pw1l, *pwoh, *pwol;
    __nv_bfloat16 *pqkvh, *pqkvl, *path, *patl;
    cudaGetSymbolAddress((void**)&pxh,   g_xh);
    cudaGetSymbolAddress((void**)&pxl,   g_xl);
    cudaGetSymbolAddress((void**)&pw1h,  g_w1h);
    cudaGetSymbolAddress((void**)&pw1l,  g_w1l);
    cudaGetSymbolAddress((void**)&pwoh,  g_wot_h);
    cudaGetSymbolAddress((void**)&pwol,  g_wot_l);
    cudaGetSymbolAddress((void**)&pqkvh, g_qkvh);
    cudaGetSymbolAddress((void**)&pqkvl, g_qkvl);
    cudaGetSymbolAddress((void**)&path,  g_ath);
    cudaGetSymbolAddress((void**)&patl,  g_atl);

    cudaFuncSetAttribute(gemm_mma,
                         cudaFuncAttributeMaxDynamicSharedMemorySize, GEMM_SMEM);
    cudaFuncSetAttribute(gemm_mma_split,
                         cudaFuncAttributeMaxDynamicSharedMemorySize, GEMM_SMEM);
    cudaFuncSetAttribute(attn_mma,
                         cudaFuncAttributeMaxDynamicSharedMemorySize, AT_SMEM);

    // --- prep ---
    {
        int n4 = ROWS * DMODEL / 4;
        split_kernel<<<(n4 + 255) / 256, 256>>>(x, pxh, pxl, n4);
    }
    transpose_split<<<dim3(INNER / 32, DMODEL / 32),     dim3(32, 8)>>>(
        Wq,  pw1h, pw1l, DMODEL, INNER);
    transpose_split<<<dim3(2 * INNER / 32, DMODEL / 32), dim3(32, 8)>>>(
        Wkv, pw1h + (size_t)INNER * DMODEL, pw1l + (size_t)INNER * DMODEL,
        DMODEL, 2 * INNER);
    transpose_split<<<dim3(DMODEL / 32, INNER / 32),     dim3(32, 8)>>>(
        Wo,  pwoh, pwol, INNER, DMODEL);

    // --- fused projection: [q|kv] = x @ [Wq Wkv], q cols pre-scaled 0.125 ---
    gemm_mma_split<<<dim3(QKVW / 128, ROWS / 256), 256, GEMM_SMEM>>>(
        pxh, pxl, pw1h, pw1l, pqkvh, pqkvl, ROWS, QKVW, DMODEL, INNER, 0.125f);

    // --- attention ---
    attn_mma<<<dim3(SEQ / 128, BATCH * HEADS), 128, AT_SMEM>>>(
        pqkvh, pqkvl, path, patl);

    // --- out = att @ Wo + bo ---
    gemm_mma<<<dim3(DMODEL / 128, ROWS / 256), 256, GEMM_SMEM>>>(
        path, patl, pwoh, pwol, bo, out, ROWS, DMODEL, INNER);
}

// round 9
// speedup vs baseline: 3.6968x; 1.3053x over previous
#include <cuda_runtime.h>
#include <cuda_fp16.h>
#include <math.h>
#include <stdint.h>

// ---------------------------------------------------------------------------
// Problem constants
// ---------------------------------------------------------------------------
#define BATCH   2
#define SEQ     2048
#define DMODEL  1024
#define HEADS   16
#define DHEAD   64
#define INNER   (HEADS * DHEAD)      // 1024
#define ROWS    (BATCH * SEQ)        // 4096
#define QKVW    (3 * INNER)          // 3072
#define ATTN_EPS 1e-8f

// ---------------------------------------------------------------------------
// Scratch (device globals)
// ---------------------------------------------------------------------------
__device__ __half g_xh  [ROWS * DMODEL];          // x split hi/lo (fp16)
__device__ __half g_xl  [ROWS * DMODEL];
__device__ __half g_w1  [QKVW * DMODEL];          // [Wq^T; Wkv^T] fp16 single
__device__ __half g_wot [DMODEL * INNER];         // Wo^T fp16 single
__device__ __half g_qkvh [ROWS * QKVW];           // fused q|k|v hi/lo
__device__ __half g_qkvl [ROWS * QKVW];
__device__ __half g_ath [ROWS * INNER];           // attention out hi/lo
__device__ __half g_atl [ROWS * INNER];

// ---------------------------------------------------------------------------
// Helpers (base ISA only)
// ---------------------------------------------------------------------------
__device__ __forceinline__ uint32_t smem_u32(const void* p) {
    uint32_t a;
    asm("{ .reg .u64 t; cvta.to.shared.u64 t, %1; cvt.u32.u64 %0, t; }"
        : "=r"(a) : "l"(p));
    return a;
}

__device__ __forceinline__ void ldmatrix_x4(uint32_t& r0, uint32_t& r1,
                                            uint32_t& r2, uint32_t& r3,
                                            uint32_t addr) {
    asm volatile("ldmatrix.sync.aligned.m8n8.x4.shared.b16 {%0,%1,%2,%3}, [%4];"
                 : "=r"(r0), "=r"(r1), "=r"(r2), "=r"(r3) : "r"(addr));
}

__device__ __forceinline__ void ldmatrix_x4_trans(uint32_t& r0, uint32_t& r1,
                                                  uint32_t& r2, uint32_t& r3,
                                                  uint32_t addr) {
    asm volatile("ldmatrix.sync.aligned.m8n8.x4.trans.shared.b16 {%0,%1,%2,%3}, [%4];"
                 : "=r"(r0), "=r"(r1), "=r"(r2), "=r"(r3) : "r"(addr));
}

__device__ __forceinline__ void mma_f16(float* d, const uint32_t* a, const uint32_t* b) {
    asm volatile(
        "mma.sync.aligned.m16n8k16.row.col.f32.f16.f16.f32 "
        "{%0,%1,%2,%3}, {%4,%5,%6,%7}, {%8,%9}, {%0,%1,%2,%3};"
        : "+f"(d[0]), "+f"(d[1]), "+f"(d[2]), "+f"(d[3])
        : "r"(a[0]), "r"(a[1]), "r"(a[2]), "r"(a[3]), "r"(b[0]), "r"(b[1]));
}

__device__ __forceinline__ void cp_async16(uint32_t saddr, const void* gaddr) {
    asm volatile("cp.async.cg.shared.global [%0], [%1], 16;"
                 :: "r"(saddr), "l"(gaddr));
}
__device__ __forceinline__ void cp_commit() {
    asm volatile("cp.async.commit_group;" ::: "memory");
}
template <int N>
__device__ __forceinline__ void cp_wait() {
    asm volatile("cp.async.wait_group %0;" :: "n"(N) : "memory");
}

__device__ __forceinline__ uint32_t sw64(uint32_t byte) {
    return byte ^ ((byte >> 3) & 0x30);
}

__device__ __forceinline__ void split2h(float v, __half& h, __half& l) {
    h = __float2half_rn(v);
    l = __float2half_rn(v - __half2float(h));
}

// pack two floats into fp16x2 hi and fp16x2 lo (exact Dekker-style residual)
__device__ __forceinline__ void pack_split(float a, float b, uint32_t& hi, uint32_t& lo) {
    __half ha = __float2half_rn(a), hb = __float2half_rn(b);
    float ra = a - __half2float(ha), rb = b - __half2float(hb);
    __half2 H; H.x = ha; H.y = hb;
    __half2 L; L.x = __float2half_rn(ra); L.y = __float2half_rn(rb);
    hi = *(uint32_t*)&H;
    lo = *(uint32_t*)&L;
}

// ---------------------------------------------------------------------------
// Prep kernels
// ---------------------------------------------------------------------------
__global__ __launch_bounds__(256)
void split_kernel(const float* __restrict__ X,
                  __half* __restrict__ H, __half* __restrict__ L, int n4)
{
    int i = blockIdx.x * blockDim.x + threadIdx.x;
    if (i >= n4) return;
    float4 v = ((const float4*)X)[i];
    union { __half b[4]; uint2 u; } uh, ul;
    split2h(v.x, uh.b[0], ul.b[0]);
    split2h(v.y, uh.b[1], ul.b[1]);
    split2h(v.z, uh.b[2], ul.b[2]);
    split2h(v.w, uh.b[3], ul.b[3]);
    ((uint2*)H)[i] = uh.u;
    ((uint2*)L)[i] = ul.u;
}

// W[K,N] row-major -> T[N,K] fp16 (single precision level)
__global__ __launch_bounds__(256)
void transpose_half(const float* __restrict__ W, __half* __restrict__ T,
                    int K, int N)
{
    __shared__ float t[32][33];
    int n  = blockIdx.x * 32 + threadIdx.x;
    int k0 = blockIdx.y * 32 + threadIdx.y;
    #pragma unroll
    for (int i = 0; i < 32; i += 8)
        t[threadIdx.y + i][threadIdx.x] = W[(size_t)(k0 + i) * N + n];
    __syncthreads();
    int k  = blockIdx.y * 32 + threadIdx.x;
    int n0 = blockIdx.x * 32 + threadIdx.y;
    #pragma unroll
    for (int i = 0; i < 32; i += 8)
        T[(size_t)(n0 + i) * K + k] = __float2half_rn(t[threadIdx.x][threadIdx.y + i]);
}

// ---------------------------------------------------------------------------
// HMMA GEMM core (2-term fp16): C = (Ah+Al) @ Bh^T, Bh [N,K] fp16.
// 256x128 CTA tile, 256 thr (4x2 warps, 64x64 each), BK=32, 3-stage cp.async.
// Per-stage smem: AH 16K | AL 16K | BH 8K = 40K; 3 stages = 120K.
// ---------------------------------------------------------------------------
#define STG_BYTES   40960
#define OFF_AH      0
#define OFF_AL      16384
#define OFF_BH      32768
#define GEMM_SMEM   (3 * STG_BYTES)

struct GemmCtx {
    float acc[4][8][4];
    int wr, wc, lane;
};

__device__ __forceinline__ void gemm_core(
    const __half* __restrict__ Ah, const __half* __restrict__ Al,
    const __half* __restrict__ Bh,
    int N, int K, int row0, int col0, GemmCtx& g)
{
    extern __shared__ char smraw[];
    const uint32_t sbase = smem_u32(smraw);

    const int tid  = threadIdx.x;
    const int wid  = tid >> 5;
    const int lane = tid & 31;
    g.wr = wid & 3; g.wc = wid >> 2; g.lane = lane;

    const int nIter = K >> 5;
    const int lm_row = lane & 15;
    const int lm_koc = (lane >> 4) * 8;

    #pragma unroll
    for (int mf = 0; mf < 4; mf++)
        #pragma unroll
        for (int nf = 0; nf < 8; nf++)
            #pragma unroll
            for (int r = 0; r < 4; r++) g.acc[mf][nf][r] = 0.f;

    auto fill_stage = [&](int s, int kk0) {
        const uint32_t st = sbase + s * STG_BYTES;
        #pragma unroll
        for (int it = 0; it < 4; it++) {
            int idx = tid + it * 256;            // 0..1023 : A rows x chunks
            int r = idx >> 2, c = idx & 3;
            uint32_t off = sw64((uint32_t)(r * 64 + c * 16));
            size_t ga = (size_t)(row0 + r) * K + kk0 + c * 8;
            cp_async16(st + OFF_AH + off, Ah + ga);
            cp_async16(st + OFF_AL + off, Al + ga);
        }
        #pragma unroll
        for (int it = 0; it < 2; it++) {
            int idx = tid + it * 256;            // 0..511 : B rows x chunks
            int r = idx >> 2, c = idx & 3;
            uint32_t off = sw64((uint32_t)(r * 64 + c * 16));
            size_t gb = (size_t)(col0 + r) * K + kk0 + c * 8;
            cp_async16(st + OFF_BH + off, Bh + gb);
        }
    };

    fill_stage(0, 0);  cp_commit();
    fill_stage(1, 32); cp_commit();

    for (int kt = 0; kt < nIter; kt++) {
        const int s = kt % 3;
        const uint32_t st = sbase + s * STG_BYTES;

        cp_wait<1>();
        __syncthreads();

        if (kt + 2 < nIter) fill_stage((kt + 2) % 3, (kt + 2) * 32);
        cp_commit();

        #pragma unroll
        for (int ks = 0; ks < 2; ks++) {
            const int colb = (ks * 16 + lm_koc) * 2;
            uint32_t ah[4][4], al[4][4];

            #pragma unroll
            for (int mf = 0; mf < 4; mf++) {
                int r = g.wr * 64 + mf * 16 + lm_row;
                uint32_t off = sw64((uint32_t)(r * 64 + colb));
                ldmatrix_x4(ah[mf][0], ah[mf][1], ah[mf][2], ah[mf][3], st + OFF_AH + off);
                ldmatrix_x4(al[mf][0], al[mf][1], al[mf][2], al[mf][3], st + OFF_AL + off);
            }
            #pragma unroll
            for (int np = 0; np < 4; np++) {
                int r = g.wc * 64 + np * 16 + lm_row;
                uint32_t off = sw64((uint32_t)(r * 64 + colb));
                uint32_t r0, r1, r2, r3;
                uint32_t bh0[2], bh1[2];
                ldmatrix_x4(r0, r1, r2, r3, st + OFF_BH + off);
                bh0[0] = r0; bh0[1] = r2; bh1[0] = r1; bh1[1] = r3;
                #pragma unroll
                for (int mf = 0; mf < 4; mf++) {
                    mma_f16(g.acc[mf][2*np],   ah[mf], bh0);
                    mma_f16(g.acc[mf][2*np],   al[mf], bh0);
                    mma_f16(g.acc[mf][2*np+1], ah[mf], bh1);
                    mma_f16(g.acc[mf][2*np+1], al[mf], bh1);
                }
            }
        }
        __syncthreads();
    }
}

// fp32-output GEMM (+bias) — final projection
__global__ __launch_bounds__(256, 1)
void gemm_mma(const __half* __restrict__ Ah, const __half* __restrict__ Al,
              const __half* __restrict__ Bh,
              const float* __restrict__ bias, float* __restrict__ C,
              int M, int N, int K)
{
    GemmCtx g;
    const int row0 = blockIdx.y * 256;
    const int col0 = blockIdx.x * 128;
    gemm_core(Ah, Al, Bh, N, K, row0, col0, g);

    const int gq = g.lane >> 2;
    const int t4 = g.lane & 3;
    #pragma unroll
    for (int mf = 0; mf < 4; mf++) {
        int r0g = row0 + g.wr * 64 + mf * 16 + gq;
        #pragma unroll
        for (int nf = 0; nf < 8; nf++) {
            int cg = col0 + g.wc * 64 + nf * 8 + t4 * 2;
            float bx = bias[cg], by = bias[cg + 1];
            float2 v0 = { g.acc[mf][nf][0] + bx, g.acc[mf][nf][1] + by };
            float2 v1 = { g.acc[mf][nf][2] + bx, g.acc[mf][nf][3] + by };
            *(float2*)(C + (size_t)r0g * N + cg)       = v0;
            *(float2*)(C + (size_t)(r0g + 8) * N + cg) = v1;
        }
    }
}

// split-output GEMM: scale cols < scaleN by scaleV (exact pow2)
__global__ __launch_bounds__(256, 1)
void gemm_mma_split(const __half* __restrict__ Ah, const __half* __restrict__ Al,
                    const __half* __restrict__ Bh,
                    __half* __restrict__ Oh, __half* __restrict__ Ol,
                    int M, int N, int K, int scaleN, float scaleV)
{
    GemmCtx g;
    const int row0 = blockIdx.y * 256;
    const int col0 = blockIdx.x * 128;
    gemm_core(Ah, Al, Bh, N, K, row0, col0, g);

    const int gq = g.lane >> 2;
    const int t4 = g.lane & 3;
    #pragma unroll
    for (int mf = 0; mf < 4; mf++) {
        int r0g = row0 + g.wr * 64 + mf * 16 + gq;
        #pragma unroll
        for (int nf = 0; nf < 8; nf++) {
            int cg = col0 + g.wc * 64 + nf * 8 + t4 * 2;
            float sc = (cg < scaleN) ? scaleV : 1.0f;
            uint32_t h0, l0, h1, l1;
            pack_split(g.acc[mf][nf][0] * sc, g.acc[mf][nf][1] * sc, h0, l0);
            pack_split(g.acc[mf][nf][2] * sc, g.acc[mf][nf][3] * sc, h1, l1);
            *(uint32_t*)(Oh + (size_t)r0g * N + cg)       = h0;
            *(uint32_t*)(Ol + (size_t)r0g * N + cg)       = l0;
            *(uint32_t*)(Oh + (size_t)(r0g + 8) * N + cg) = h1;
            *(uint32_t*)(Ol + (size_t)(r0g + 8) * N + cg) = l1;
        }
    }
}

// ---------------------------------------------------------------------------
// HMMA flash attention (fp16): 4 warps x 32 q-rows (Br=128, Bc=64),
// S = 3-term (q hi/lo x k hi/lo), PV = 2-term (P hi/lo x V single),
// double-buffered K/V, ldmatrix.trans V, 2 CTAs/SM.
// Stage: KH 8K | KL 8K | VH 8K = 24K.
// ---------------------------------------------------------------------------
#define AT_Q_BYTES   32768
#define AT_STG_BYTES 24576
#define AT_SMEM      (1024 + AT_Q_BYTES + 2 * AT_STG_BYTES)

__global__ __launch_bounds__(128, 2)
void attn_mma(const __half* __restrict__ qkvh,
              const __half* __restrict__ qkvl,
              __half* __restrict__ goh, __half* __restrict__ gol)
{
    extern __shared__ char smraw[];
    const uint32_t b0a = smem_u32(smraw);
    const uint32_t sb = (b0a + 1023u) & ~1023u;

    const int tid = threadIdx.x;
    const int w = tid >> 5, lane = tid & 31;
    const int gq = lane >> 2, t4 = lane & 3;
    const int lm_row = lane & 15, lm_koc = (lane >> 4) * 8;
    const int vt = lane >> 3, vrl = lane & 7;
    const int b = blockIdx.y >> 4, h = blockIdx.y & 15;
    const int qt = gridDim.x - 1 - blockIdx.x;
    const int qstart = qt * 128;
    const int igmax = qstart + w * 32 + 31;

    const uint32_t QH = sb, QL = sb + 16384;
    const uint32_t ST0 = sb + AT_Q_BYTES;

    const size_t rowbase = (size_t)(b * SEQ) * QKVW + h * 64;

    // ---- Q fill ----
    #pragma unroll
    for (int it = 0; it < 16; it++) {
        int idx = tid + it * 128;
        int bs = idx >> 10, r = (idx >> 3) & 127, c = idx & 7;
        const __half* src = (bs ? qkvl : qkvh)
            + rowbase + (size_t)(qstart + r) * QKVW + c * 8;
        cp_async16((bs ? QL : QH) + (uint32_t)(r * 128 + ((c * 16) ^ ((r & 7) << 4))), src);
    }

    auto fill_kv = [&](int s, int jstart) {
        const uint32_t st = ST0 + s * AT_STG_BYTES;
        #pragma unroll
        for (int it = 0; it < 12; it++) {
            int idx = tid + it * 128;            // 0..1535
            int tile = idx >> 9;                 // 0:KH 1:KL 2:VH
            int r = (idx >> 3) & 63, c = idx & 7;
            const __half* base = (tile == 1) ? qkvl : qkvh;
            int col = ((tile == 2) ? 2048 : 1024) + c * 8;
            const __half* src = base + rowbase + (size_t)(jstart + r) * QKVW + col;
            cp_async16(st + (uint32_t)(tile * 8192 + r * 128 + ((c * 16) ^ ((r & 7) << 4))), src);
        }
    };

    fill_kv(0, 0);
    cp_commit();                                 // group: Q + KV(0)

    float o[2][8][4];
    float m[4] = { -INFINITY, -INFINITY, -INFINITY, -INFINITY };
    float lsum[4] = { 0.f, 0.f, 0.f, 0.f };
    #pragma unroll
    for (int mf = 0; mf < 2; mf++)
        #pragma unroll
        for (int nd = 0; nd < 8; nd++)
            #pragma unroll
            for (int r = 0; r < 4; r++) o[mf][nd][r] = 0.f;

    const int nT = 2 * qt + 2;
    for (int jt = 0; jt < nT; jt++) {
        const int jstart = jt * 64;
        const uint32_t st = ST0 + (jt & 1) * AT_STG_BYTES;
        const uint32_t KH = st, KL = st + 8192, VH = st + 16384;

        if (jt > 0) __syncthreads();
        if (jt + 1 < nT) {
            fill_kv((jt + 1) & 1, jstart + 64);
            cp_commit();
            cp_wait<1>();
        } else {
            cp_wait<0>();
        }
        __syncthreads();

        // ---- S = Q @ K^T (3-term: qh*kh + qh*kl + ql*kh) ----
        float s[2][8][4];
        #pragma unroll
        for (int mf = 0; mf < 2; mf++)
            #pragma unroll
            for (int nj = 0; nj < 8; nj++)
                #pragma unroll
                for (int r = 0; r < 4; r++) s[mf][nj][r] = 0.f;

        #pragma unroll
        for (int kd = 0; kd < 4; kd++) {
            const int cb = (kd * 16 + lm_koc) * 2;
            uint32_t qa[2][4], qb[2][4];
            #pragma unroll
            for (int mf = 0; mf < 2; mf++) {
                int r = w * 32 + mf * 16 + lm_row;
                uint32_t off = (uint32_t)(r * 128 + (cb ^ ((r & 7) << 4)));
                ldmatrix_x4(qa[mf][0], qa[mf][1], qa[mf][2], qa[mf][3], QH + off);
                ldmatrix_x4(qb[mf][0], qb[mf][1], qb[mf][2], qb[mf][3], QL + off);
            }
            #pragma unroll
            for (int jp = 0; jp < 4; jp++) {
                if (jstart + jp * 16 > igmax) continue;
                int r = jp * 16 + lm_row;
                uint32_t off = (uint32_t)(r * 128 + (cb ^ ((r & 7) << 4)));
                uint32_t r0, r1, r2, r3;
                uint32_t bh0[2], bh1[2], bl0[2], bl1[2];
                ldmatrix_x4(r0, r1, r2, r3, KH + off);
                bh0[0] = r0; bh0[1] = r2; bh1[0] = r1; bh1[1] = r3;
                ldmatrix_x4(r0, r1, r2, r3, KL + off);
                bl0[0] = r0; bl0[1] = r2; bl1[0] = r1; bl1[1] = r3;
                #pragma unroll
                for (int mf = 0; mf < 2; mf++) {
                    mma_f16(s[mf][2*jp],   qa[mf], bh0);
                    mma_f16(s[mf][2*jp],   qa[mf], bl0);
                    mma_f16(s[mf][2*jp],   qb[mf], bh0);
                    mma_f16(s[mf][2*jp+1], qa[mf], bh1);
                    mma_f16(s[mf][2*jp+1], qa[mf], bl1);
                    mma_f16(s[mf][2*jp+1], qb[mf], bh1);
                }
            }
        }

        // ---- online softmax ----
        float alpha[4];
        #pragma unroll
        for (int mf = 0; mf < 2; mf++) {
            #pragma unroll
            for (int hh = 0; hh < 2; hh++) {
                const int hr = 2 * mf + hh;
                float mx = -INFINITY;
                #pragma unroll
                for (int nj = 0; nj < 8; nj++)
                    mx = fmaxf(mx, fmaxf(s[mf][nj][2*hh], s[mf][nj][2*hh+1]));
                mx = fmaxf(mx, __shfl_xor_sync(0xffffffffu, mx, 1));
                mx = fmaxf(mx, __shfl_xor_sync(0xffffffffu, mx, 2));
                float mn = fmaxf(m[hr], mx);
                alpha[hr] = __expf(m[hr] - mn);
                m[hr] = mn;
                const int ig = qstart + w * 32 + mf * 16 + hh * 8 + gq;
                float rs = 0.f;
                #pragma unroll
                for (int nj = 0; nj < 8; nj++) {
                    int jg = jstart + nj * 8 + t4 * 2;
                    float p0 = (jg     <= ig) ? __expf(s[mf][nj][2*hh]   - mn) : 0.f;
                    float p1 = (jg + 1 <= ig) ? __expf(s[mf][nj][2*hh+1] - mn) : 0.f;
                    s[mf][nj][2*hh] = p0; s[mf][nj][2*hh+1] = p1;
                    rs += p0 + p1;
                }
                rs += __shfl_xor_sync(0xffffffffu, rs, 1);
                rs += __shfl_xor_sync(0xffffffffu, rs, 2);
                lsum[hr] = lsum[hr] * alpha[hr] + rs;
            }
            #pragma unroll
            for (int nd = 0; nd < 8; nd++) {
                o[mf][nd][0] *= alpha[2*mf];     o[mf][nd][1] *= alpha[2*mf];
                o[mf][nd][2] *= alpha[2*mf + 1]; o[mf][nd][3] *= alpha[2*mf + 1];
            }
        }

        // ---- O += P @ V (2-term: ph*vh + pl*vh) ----
        #pragma unroll
        for (int kj = 0; kj < 4; kj++) {
            if (jstart + kj * 16 > igmax) continue;
            uint32_t ph[2][4], pl[2][4];
            #pragma unroll
            for (int mf = 0; mf < 2; mf++) {
                pack_split(s[mf][2*kj][0],   s[mf][2*kj][1],   ph[mf][0], pl[mf][0]);
                pack_split(s[mf][2*kj][2],   s[mf][2*kj][3],   ph[mf][1], pl[mf][1]);
                pack_split(s[mf][2*kj+1][0], s[mf][2*kj+1][1], ph[mf][2], pl[mf][2]);
                pack_split(s[mf][2*kj+1][2], s[mf][2*kj+1][3], ph[mf][3], pl[mf][3]);
            }
            const int j = kj * 16 + (vt & 1) * 8 + vrl;
            const uint32_t jsw = (uint32_t)(j * 128);
            const int ch = (vt >> 1);
            #pragma unroll
            for (int ndp = 0; ndp < 4; ndp++) {
                int c = ndp * 2 + ch;
                uint32_t off = jsw + (uint32_t)((c * 16) ^ ((j & 7) << 4));
                uint32_t r0, r1, r2, r3;
                uint32_t bh0[2], bh1[2];
                ldmatrix_x4_trans(r0, r1, r2, r3, VH + off);
                bh0[0] = r0; bh0[1] = r1; bh1[0] = r2; bh1[1] = r3;
                #pragma unroll
                for (int mf = 0; mf < 2; mf++) {
                    mma_f16(o[mf][2*ndp],   ph[mf], bh0);
                    mma_f16(o[mf][2*ndp],   pl[mf], bh0);
                    mma_f16(o[mf][2*ndp+1], ph[mf], bh1);
                    mma_f16(o[mf][2*ndp+1], pl[mf], bh1);
                }
            }
        }
    }

    // ---- epilogue ----
    #pragma unroll
    for (int mf = 0; mf < 2; mf++) {
        const float inv0 = 1.0f / (lsum[2*mf]     + ATTN_EPS);
        const float inv1 = 1.0f / (lsum[2*mf + 1] + ATTN_EPS);
        const size_t base0 = (size_t)(b * SEQ + qstart + w * 32 + mf * 16 + gq) * INNER
                           + h * 64 + t4 * 2;
        const size_t base1 = base0 + (size_t)8 * INNER;
        #pragma unroll
        for (int nd = 0; nd < 8; nd++) {
            uint32_t h0, l0, h1, l1;
            pack_split(o[mf][nd][0] * inv0, o[mf][nd][1] * inv0, h0, l0);
            pack_split(o[mf][nd][2] * inv1, o[mf][nd][3] * inv1, h1, l1);
            *(uint32_t*)(goh + base0 + nd * 8) = h0;
            *(uint32_t*)(gol + base0 + nd * 8) = l0;
            *(uint32_t*)(goh + base1 + nd * 8) = h1;
            *(uint32_t*)(gol + base1 + nd * 8) = l1;
        }
    }
}

// ---------------------------------------------------------------------------
// Launch
// ---------------------------------------------------------------------------
extern "C" void kernel_launch(void* const* d_in, const int* in_sizes, int n_in,
                              void* d_out, int out_size)
{
    const float* x   = (const float*)d_in[0];
    const float* Wq  = (const float*)d_in[1];
    const float* Wkv = (const float*)d_in[2];
    const float* Wo  = (const float*)d_in[3];
    const float* bo  = (const float*)d_in[4];
    float* out = (float*)d_out;

    __half *pxh, *pxl, *pw1, *pwo, *pqkvh, *pqkvl, *path, *patl;
    cudaGetSymbolAddress((void**)&pxh,   g_xh);
    cudaGetSymbolAddress((void**)&pxl,   g_xl);
    cudaGetSymbolAddress((void**)&pw1,   g_w1);
    cudaGetSymbolAddress((void**)&pwo,   g_wot);
    cudaGetSymbolAddress((void**)&pqkvh, g_qkvh);
    cudaGetSymbolAddress((void**)&pqkvl, g_qkvl);
    cudaGetSymbolAddress((void**)&path,  g_ath);
    cudaGetSymbolAddress((void**)&patl,  g_atl);

    cudaFuncSetAttribute(gemm_mma,
                         cudaFuncAttributeMaxDynamicSharedMemorySize, GEMM_SMEM);
    cudaFuncSetAttribute(gemm_mma_split,
                         cudaFuncAttributeMaxDynamicSharedMemorySize, GEMM_SMEM);
    cudaFuncSetAttribute(attn_mma,
                         cudaFuncAttributeMaxDynamicSharedMemorySize, AT_SMEM);

    // --- prep: split x (fp16 hi/lo); transpose weights (fp16 single) ---
    {
        int n4 = ROWS * DMODEL / 4;
        split_kernel<<<(n4 + 255) / 256, 256>>>(x, pxh, pxl, n4);
    }
    transpose_half<<<dim3(INNER / 32, DMODEL / 32),     dim3(32, 8)>>>(
        Wq,  pw1, DMODEL, INNER);
    transpose_half<<<dim3(2 * INNER / 32, DMODEL / 32), dim3(32, 8)>>>(
        Wkv, pw1 + (size_t)INNER * DMODEL, DMODEL, 2 * INNER);
    transpose_half<<<dim3(DMODEL / 32, INNER / 32),     dim3(32, 8)>>>(
        Wo,  pwo, INNER, DMODEL);

    // --- fused projection: [q|kv] = x @ [Wq Wkv], q cols pre-scaled 0.125 ---
    gemm_mma_split<<<dim3(QKVW / 128, ROWS / 256), 256, GEMM_SMEM>>>(
        pxh, pxl, pw1, pqkvh, pqkvl, ROWS, QKVW, DMODEL, INNER, 0.125f);

    // --- attention ---
    attn_mma<<<dim3(SEQ / 128, BATCH * HEADS), 128, AT_SMEM>>>(
        pqkvh, pqkvl, path, patl);

    // --- out = att @ Wo + bo ---
    gemm_mma<<<dim3(DMODEL / 128, ROWS / 256), 256, GEMM_SMEM>>>(
        path, patl, pwo, bo, out, ROWS, DMODEL, INNER);
}

// round 10
// speedup vs baseline: 3.9158x; 1.0592x over previous
#include <cuda_runtime.h>
#include <cuda_fp16.h>
#include <math.h>
#include <stdint.h>

// ---------------------------------------------------------------------------
// Problem constants
// ---------------------------------------------------------------------------
#define BATCH   2
#define SEQ     2048
#define DMODEL  1024
#define HEADS   16
#define DHEAD   64
#define INNER   (HEADS * DHEAD)      // 1024
#define ROWS    (BATCH * SEQ)        // 4096
#define QKVW    (3 * INNER)          // 3072
#define ATTN_EPS 1e-8f

// ---------------------------------------------------------------------------
// Scratch (device globals)
// ---------------------------------------------------------------------------
__device__ __half g_xh  [ROWS * DMODEL];          // x split hi/lo (fp16)
__device__ __half g_xl  [ROWS * DMODEL];
__device__ __half g_w1  [QKVW * DMODEL];          // [Wq^T; Wkv^T] fp16 single
__device__ __half g_wot [DMODEL * INNER];         // Wo^T fp16 single
__device__ __half g_qkvh [ROWS * QKVW];           // fused q|k|v hi/lo
__device__ __half g_qkvl [ROWS * QKVW];
__device__ __half g_ath [ROWS * INNER];           // attention out hi/lo
__device__ __half g_atl [ROWS * INNER];

// ---------------------------------------------------------------------------
// Helpers (base ISA only)
// ---------------------------------------------------------------------------
__device__ __forceinline__ uint32_t smem_u32(const void* p) {
    uint32_t a;
    asm("{ .reg .u64 t; cvta.to.shared.u64 t, %1; cvt.u32.u64 %0, t; }"
        : "=r"(a) : "l"(p));
    return a;
}

__device__ __forceinline__ void ldmatrix_x4(uint32_t& r0, uint32_t& r1,
                                            uint32_t& r2, uint32_t& r3,
                                            uint32_t addr) {
    asm volatile("ldmatrix.sync.aligned.m8n8.x4.shared.b16 {%0,%1,%2,%3}, [%4];"
                 : "=r"(r0), "=r"(r1), "=r"(r2), "=r"(r3) : "r"(addr));
}

__device__ __forceinline__ void ldmatrix_x4_trans(uint32_t& r0, uint32_t& r1,
                                                  uint32_t& r2, uint32_t& r3,
                                                  uint32_t addr) {
    asm volatile("ldmatrix.sync.aligned.m8n8.x4.trans.shared.b16 {%0,%1,%2,%3}, [%4];"
                 : "=r"(r0), "=r"(r1), "=r"(r2), "=r"(r3) : "r"(addr));
}

__device__ __forceinline__ void mma_f16(float* d, const uint32_t* a, const uint32_t* b) {
    asm volatile(
        "mma.sync.aligned.m16n8k16.row.col.f32.f16.f16.f32 "
        "{%0,%1,%2,%3}, {%4,%5,%6,%7}, {%8,%9}, {%0,%1,%2,%3};"
        : "+f"(d[0]), "+f"(d[1]), "+f"(d[2]), "+f"(d[3])
        : "r"(a[0]), "r"(a[1]), "r"(a[2]), "r"(a[3]), "r"(b[0]), "r"(b[1]));
}

__device__ __forceinline__ void cp_async16(uint32_t saddr, const void* gaddr) {
    asm volatile("cp.async.cg.shared.global [%0], [%1], 16;"
                 :: "r"(saddr), "l"(gaddr));
}
__device__ __forceinline__ void cp_commit() {
    asm volatile("cp.async.commit_group;" ::: "memory");
}
template <int N>
__device__ __forceinline__ void cp_wait() {
    asm volatile("cp.async.wait_group %0;" :: "n"(N) : "memory");
}

__device__ __forceinline__ uint32_t sw64(uint32_t byte) {
    return byte ^ ((byte >> 3) & 0x30);
}

__device__ __forceinline__ void split2h(float v, __half& h, __half& l) {
    h = __float2half_rn(v);
    l = __float2half_rn(v - __half2float(h));
}

// pack two floats into fp16x2 hi and fp16x2 lo (exact Dekker-style residual)
__device__ __forceinline__ void pack_split(float a, float b, uint32_t& hi, uint32_t& lo) {
    __half ha = __float2half_rn(a), hb = __float2half_rn(b);
    float ra = a - __half2float(ha), rb = b - __half2float(hb);
    __half2 H; H.x = ha; H.y = hb;
    __half2 L; L.x = __float2half_rn(ra); L.y = __float2half_rn(rb);
    hi = *(uint32_t*)&H;
    lo = *(uint32_t*)&L;
}

// ---------------------------------------------------------------------------
// Prep kernels
// ---------------------------------------------------------------------------
__global__ __launch_bounds__(256)
void split_kernel(const float* __restrict__ X,
                  __half* __restrict__ H, __half* __restrict__ L, int n4)
{
    int i = blockIdx.x * blockDim.x + threadIdx.x;
    if (i >= n4) return;
    float4 v = ((const float4*)X)[i];
    union { __half b[4]; uint2 u; } uh, ul;
    split2h(v.x, uh.b[0], ul.b[0]);
    split2h(v.y, uh.b[1], ul.b[1]);
    split2h(v.z, uh.b[2], ul.b[2]);
    split2h(v.w, uh.b[3], ul.b[3]);
    ((uint2*)H)[i] = uh.u;
    ((uint2*)L)[i] = ul.u;
}

// W[K,N] row-major -> T[N,K] fp16 (single precision level)
__global__ __launch_bounds__(256)
void transpose_half(const float* __restrict__ W, __half* __restrict__ T,
                    int K, int N)
{
    __shared__ float t[32][33];
    int n  = blockIdx.x * 32 + threadIdx.x;
    int k0 = blockIdx.y * 32 + threadIdx.y;
    #pragma unroll
    for (int i = 0; i < 32; i += 8)
        t[threadIdx.y + i][threadIdx.x] = W[(size_t)(k0 + i) * N + n];
    __syncthreads();
    int k  = blockIdx.y * 32 + threadIdx.x;
    int n0 = blockIdx.x * 32 + threadIdx.y;
    #pragma unroll
    for (int i = 0; i < 32; i += 8)
        T[(size_t)(n0 + i) * K + k] = __float2half_rn(t[threadIdx.x][threadIdx.y + i]);
}

// ---------------------------------------------------------------------------
// HMMA GEMM core (2-term fp16): C = (Ah+Al) @ Bh^T, Bh [N,K] fp16.
// 256x128 CTA tile, 256 thr (4x2 warps, 64x64 each), BK=32, 3-stage cp.async.
// ---------------------------------------------------------------------------
#define STG_BYTES   40960
#define OFF_AH      0
#define OFF_AL      16384
#define OFF_BH      32768
#define GEMM_SMEM   (3 * STG_BYTES)

struct GemmCtx {
    float acc[4][8][4];
    int wr, wc, lane;
};

__device__ __forceinline__ void gemm_core(
    const __half* __restrict__ Ah, const __half* __restrict__ Al,
    const __half* __restrict__ Bh,
    int N, int K, int row0, int col0, GemmCtx& g)
{
    extern __shared__ char smraw[];
    const uint32_t sbase = smem_u32(smraw);

    const int tid  = threadIdx.x;
    const int wid  = tid >> 5;
    const int lane = tid & 31;
    g.wr = wid & 3; g.wc = wid >> 2; g.lane = lane;

    const int nIter = K >> 5;
    const int lm_row = lane & 15;
    const int lm_koc = (lane >> 4) * 8;

    #pragma unroll
    for (int mf = 0; mf < 4; mf++)
        #pragma unroll
        for (int nf = 0; nf < 8; nf++)
            #pragma unroll
            for (int r = 0; r < 4; r++) g.acc[mf][nf][r] = 0.f;

    auto fill_stage = [&](int s, int kk0) {
        const uint32_t st = sbase + s * STG_BYTES;
        #pragma unroll
        for (int it = 0; it < 4; it++) {
            int idx = tid + it * 256;
            int r = idx >> 2, c = idx & 3;
            uint32_t off = sw64((uint32_t)(r * 64 + c * 16));
            size_t ga = (size_t)(row0 + r) * K + kk0 + c * 8;
            cp_async16(st + OFF_AH + off, Ah + ga);
            cp_async16(st + OFF_AL + off, Al + ga);
        }
        #pragma unroll
        for (int it = 0; it < 2; it++) {
            int idx = tid + it * 256;
            int r = idx >> 2, c = idx & 3;
            uint32_t off = sw64((uint32_t)(r * 64 + c * 16));
            size_t gb = (size_t)(col0 + r) * K + kk0 + c * 8;
            cp_async16(st + OFF_BH + off, Bh + gb);
        }
    };

    fill_stage(0, 0);  cp_commit();
    fill_stage(1, 32); cp_commit();

    for (int kt = 0; kt < nIter; kt++) {
        const int s = kt % 3;
        const uint32_t st = sbase + s * STG_BYTES;

        cp_wait<1>();
        __syncthreads();

        if (kt + 2 < nIter) fill_stage((kt + 2) % 3, (kt + 2) * 32);
        cp_commit();

        #pragma unroll
        for (int ks = 0; ks < 2; ks++) {
            const int colb = (ks * 16 + lm_koc) * 2;
            uint32_t ah[4][4], al[4][4];

            #pragma unroll
            for (int mf = 0; mf < 4; mf++) {
                int r = g.wr * 64 + mf * 16 + lm_row;
                uint32_t off = sw64((uint32_t)(r * 64 + colb));
                ldmatrix_x4(ah[mf][0], ah[mf][1], ah[mf][2], ah[mf][3], st + OFF_AH + off);
                ldmatrix_x4(al[mf][0], al[mf][1], al[mf][2], al[mf][3], st + OFF_AL + off);
            }
            #pragma unroll
            for (int np = 0; np < 4; np++) {
                int r = g.wc * 64 + np * 16 + lm_row;
                uint32_t off = sw64((uint32_t)(r * 64 + colb));
                uint32_t r0, r1, r2, r3;
                uint32_t bh0[2], bh1[2];
                ldmatrix_x4(r0, r1, r2, r3, st + OFF_BH + off);
                bh0[0] = r0; bh0[1] = r2; bh1[0] = r1; bh1[1] = r3;
                #pragma unroll
                for (int mf = 0; mf < 4; mf++) {
                    mma_f16(g.acc[mf][2*np],   ah[mf], bh0);
                    mma_f16(g.acc[mf][2*np],   al[mf], bh0);
                    mma_f16(g.acc[mf][2*np+1], ah[mf], bh1);
                    mma_f16(g.acc[mf][2*np+1], al[mf], bh1);
                }
            }
        }
        __syncthreads();
    }
}

// fp32-output GEMM (+bias) — final projection
__global__ __launch_bounds__(256, 1)
void gemm_mma(const __half* __restrict__ Ah, const __half* __restrict__ Al,
              const __half* __restrict__ Bh,
              const float* __restrict__ bias, float* __restrict__ C,
              int M, int N, int K)
{
    GemmCtx g;
    const int row0 = blockIdx.y * 256;
    const int col0 = blockIdx.x * 128;
    gemm_core(Ah, Al, Bh, N, K, row0, col0, g);

    const int gq = g.lane >> 2;
    const int t4 = g.lane & 3;
    #pragma unroll
    for (int mf = 0; mf < 4; mf++) {
        int r0g = row0 + g.wr * 64 + mf * 16 + gq;
        #pragma unroll
        for (int nf = 0; nf < 8; nf++) {
            int cg = col0 + g.wc * 64 + nf * 8 + t4 * 2;
            float bx = bias[cg], by = bias[cg + 1];
            float2 v0 = { g.acc[mf][nf][0] + bx, g.acc[mf][nf][1] + by };
            float2 v1 = { g.acc[mf][nf][2] + bx, g.acc[mf][nf][3] + by };
            *(float2*)(C + (size_t)r0g * N + cg)       = v0;
            *(float2*)(C + (size_t)(r0g + 8) * N + cg) = v1;
        }
    }
}

// split-output GEMM: scale cols < scaleN by scaleV (exact pow2)
__global__ __launch_bounds__(256, 1)
void gemm_mma_split(const __half* __restrict__ Ah, const __half* __restrict__ Al,
                    const __half* __restrict__ Bh,
                    __half* __restrict__ Oh, __half* __restrict__ Ol,
                    int M, int N, int K, int scaleN, float scaleV)
{
    GemmCtx g;
    const int row0 = blockIdx.y * 256;
    const int col0 = blockIdx.x * 128;
    gemm_core(Ah, Al, Bh, N, K, row0, col0, g);

    const int gq = g.lane >> 2;
    const int t4 = g.lane & 3;
    #pragma unroll
    for (int mf = 0; mf < 4; mf++) {
        int r0g = row0 + g.wr * 64 + mf * 16 + gq;
        #pragma unroll
        for (int nf = 0; nf < 8; nf++) {
            int cg = col0 + g.wc * 64 + nf * 8 + t4 * 2;
            float sc = (cg < scaleN) ? scaleV : 1.0f;
            uint32_t h0, l0, h1, l1;
            pack_split(g.acc[mf][nf][0] * sc, g.acc[mf][nf][1] * sc, h0, l0);
            pack_split(g.acc[mf][nf][2] * sc, g.acc[mf][nf][3] * sc, h1, l1);
            *(uint32_t*)(Oh + (size_t)r0g * N + cg)       = h0;
            *(uint32_t*)(Ol + (size_t)r0g * N + cg)       = l0;
            *(uint32_t*)(Oh + (size_t)(r0g + 8) * N + cg) = h1;
            *(uint32_t*)(Ol + (size_t)(r0g + 8) * N + cg) = l1;
        }
    }
}

// ---------------------------------------------------------------------------
// HMMA flash attention (fp16): 4 warps x 32 q-rows (Br=128, Bc=64).
// S = 2-term ((qh+ql) x kh), PV = 2-term (P hi/lo x V single).
// QH fragments hoisted into registers for the whole KV loop; QL read per tile.
// Stage: KH 8K | VH 8K = 16K, double-buffered. 2 CTAs/SM.
// ---------------------------------------------------------------------------
#define AT_Q_BYTES   32768
#define AT_STG_BYTES 16384
#define AT_SMEM      (1024 + AT_Q_BYTES + 2 * AT_STG_BYTES)

__global__ __launch_bounds__(128, 2)
void attn_mma(const __half* __restrict__ qkvh,
              const __half* __restrict__ qkvl,
              __half* __restrict__ goh, __half* __restrict__ gol)
{
    extern __shared__ char smraw[];
    const uint32_t b0a = smem_u32(smraw);
    const uint32_t sb = (b0a + 1023u) & ~1023u;

    const int tid = threadIdx.x;
    const int w = tid >> 5, lane = tid & 31;
    const int gq = lane >> 2, t4 = lane & 3;
    const int lm_row = lane & 15, lm_koc = (lane >> 4) * 8;
    const int vt = lane >> 3, vrl = lane & 7;
    const int b = blockIdx.y >> 4, h = blockIdx.y & 15;
    const int qt = gridDim.x - 1 - blockIdx.x;
    const int qstart = qt * 128;
    const int igmax = qstart + w * 32 + 31;

    const uint32_t QH = sb, QL = sb + 16384;
    const uint32_t ST0 = sb + AT_Q_BYTES;

    const size_t rowbase = (size_t)(b * SEQ) * QKVW + h * 64;

    // ---- Q fill (own cp.async group) ----
    #pragma unroll
    for (int it = 0; it < 16; it++) {
        int idx = tid + it * 128;
        int bs = idx >> 10, r = (idx >> 3) & 127, c = idx & 7;
        const __half* src = (bs ? qkvl : qkvh)
            + rowbase + (size_t)(qstart + r) * QKVW + c * 8;
        cp_async16((bs ? QL : QH) + (uint32_t)(r * 128 + ((c * 16) ^ ((r & 7) << 4))), src);
    }
    cp_commit();

    // ---- K/V stage fill: KH + VH (single-precision k and v) ----
    auto fill_kv = [&](int s, int jstart) {
        const uint32_t st = ST0 + s * AT_STG_BYTES;
        #pragma unroll
        for (int it = 0; it < 8; it++) {
            int idx = tid + it * 128;            // 0..1023
            int tile = idx >> 9;                 // 0:KH 1:VH
            int r = (idx >> 3) & 63, c = idx & 7;
            int col = (tile ? 2048 : 1024) + c * 8;
            const __half* src = qkvh + rowbase + (size_t)(jstart + r) * QKVW + col;
            cp_async16(st + (uint32_t)(tile * 8192 + r * 128 + ((c * 16) ^ ((r & 7) << 4))), src);
        }
    };

    fill_kv(0, 0);
    cp_commit();

    // ---- wait for Q (one group may remain pending: KV0), hoist QH frags ----
    cp_wait<1>();
    __syncthreads();

    uint32_t qa[2][4][4];                        // [mf][kd][reg] Q-hi
    #pragma unroll
    for (int kd = 0; kd < 4; kd++) {
        const int cb = (kd * 16 + lm_koc) * 2;
        #pragma unroll
        for (int mf = 0; mf < 2; mf++) {
            int r = w * 32 + mf * 16 + lm_row;
            uint32_t off = (uint32_t)(r * 128 + (cb ^ ((r & 7) << 4)));
            ldmatrix_x4(qa[mf][kd][0], qa[mf][kd][1], qa[mf][kd][2], qa[mf][kd][3],
                        QH + off);
        }
    }

    float o[2][8][4];
    float m[4] = { -INFINITY, -INFINITY, -INFINITY, -INFINITY };
    float lsum[4] = { 0.f, 0.f, 0.f, 0.f };
    #pragma unroll
    for (int mf = 0; mf < 2; mf++)
        #pragma unroll
        for (int nd = 0; nd < 8; nd++)
            #pragma unroll
            for (int r = 0; r < 4; r++) o[mf][nd][r] = 0.f;

    const int nT = 2 * qt + 2;
    for (int jt = 0; jt < nT; jt++) {
        const int jstart = jt * 64;
        const uint32_t st = ST0 + (jt & 1) * AT_STG_BYTES;
        const uint32_t KH = st, VH = st + 8192;

        if (jt > 0) __syncthreads();
        if (jt + 1 < nT) {
            fill_kv((jt + 1) & 1, jstart + 64);
            cp_commit();
            cp_wait<1>();
        } else {
            cp_wait<0>();
        }
        __syncthreads();

        // ---- S = Q @ K^T (2-term: qh*kh + ql*kh) ----
        float s[2][8][4];
        #pragma unroll
        for (int mf = 0; mf < 2; mf++)
            #pragma unroll
            for (int nj = 0; nj < 8; nj++)
                #pragma unroll
                for (int r = 0; r < 4; r++) s[mf][nj][r] = 0.f;

        #pragma unroll
        for (int kd = 0; kd < 4; kd++) {
            const int cb = (kd * 16 + lm_koc) * 2;
            uint32_t qb[2][4];
            #pragma unroll
            for (int mf = 0; mf < 2; mf++) {
                int r = w * 32 + mf * 16 + lm_row;
                uint32_t off = (uint32_t)(r * 128 + (cb ^ ((r & 7) << 4)));
                ldmatrix_x4(qb[mf][0], qb[mf][1], qb[mf][2], qb[mf][3], QL + off);
            }
            #pragma unroll
            for (int jp = 0; jp < 4; jp++) {
                if (jstart + jp * 16 > igmax) continue;
                int r = jp * 16 + lm_row;
                uint32_t off = (uint32_t)(r * 128 + (cb ^ ((r & 7) << 4)));
                uint32_t r0, r1, r2, r3;
                uint32_t bh0[2], bh1[2];
                ldmatrix_x4(r0, r1, r2, r3, KH + off);
                bh0[0] = r0; bh0[1] = r2; bh1[0] = r1; bh1[1] = r3;
                #pragma unroll
                for (int mf = 0; mf < 2; mf++) {
                    mma_f16(s[mf][2*jp],   qa[mf][kd], bh0);
                    mma_f16(s[mf][2*jp],   qb[mf],     bh0);
                    mma_f16(s[mf][2*jp+1], qa[mf][kd], bh1);
                    mma_f16(s[mf][2*jp+1], qb[mf],     bh1);
                }
            }
        }

        // ---- online softmax ----
        float alpha[4];
        #pragma unroll
        for (int mf = 0; mf < 2; mf++) {
            #pragma unroll
            for (int hh = 0; hh < 2; hh++) {
                const int hr = 2 * mf + hh;
                float mx = -INFINITY;
                #pragma unroll
                for (int nj = 0; nj < 8; nj++)
                    mx = fmaxf(mx, fmaxf(s[mf][nj][2*hh], s[mf][nj][2*hh+1]));
                mx = fmaxf(mx, __shfl_xor_sync(0xffffffffu, mx, 1));
                mx = fmaxf(mx, __shfl_xor_sync(0xffffffffu, mx, 2));
                float mn = fmaxf(m[hr], mx);
                alpha[hr] = __expf(m[hr] - mn);
                m[hr] = mn;
                const int ig = qstart + w * 32 + mf * 16 + hh * 8 + gq;
                float rs = 0.f;
                #pragma unroll
                for (int nj = 0; nj < 8; nj++) {
                    int jg = jstart + nj * 8 + t4 * 2;
                    float p0 = (jg     <= ig) ? __expf(s[mf][nj][2*hh]   - mn) : 0.f;
                    float p1 = (jg + 1 <= ig) ? __expf(s[mf][nj][2*hh+1] - mn) : 0.f;
                    s[mf][nj][2*hh] = p0; s[mf][nj][2*hh+1] = p1;
                    rs += p0 + p1;
                }
                rs += __shfl_xor_sync(0xffffffffu, rs, 1);
                rs += __shfl_xor_sync(0xffffffffu, rs, 2);
                lsum[hr] = lsum[hr] * alpha[hr] + rs;
            }
            #pragma unroll
            for (int nd = 0; nd < 8; nd++) {
                o[mf][nd][0] *= alpha[2*mf];     o[mf][nd][1] *= alpha[2*mf];
                o[mf][nd][2] *= alpha[2*mf + 1]; o[mf][nd][3] *= alpha[2*mf + 1];
            }
        }

        // ---- O += P @ V (2-term: ph*vh + pl*vh) ----
        #pragma unroll
        for (int kj = 0; kj < 4; kj++) {
            if (jstart + kj * 16 > igmax) continue;
            uint32_t ph[2][4], pl[2][4];
            #pragma unroll
            for (int mf = 0; mf < 2; mf++) {
                pack_split(s[mf][2*kj][0],   s[mf][2*kj][1],   ph[mf][0], pl[mf][0]);
                pack_split(s[mf][2*kj][2],   s[mf][2*kj][3],   ph[mf][1], pl[mf][1]);
                pack_split(s[mf][2*kj+1][0], s[mf][2*kj+1][1], ph[mf][2], pl[mf][2]);
                pack_split(s[mf][2*kj+1][2], s[mf][2*kj+1][3], ph[mf][3], pl[mf][3]);
            }
            const int j = kj * 16 + (vt & 1) * 8 + vrl;
            const uint32_t jsw = (uint32_t)(j * 128);
            const int ch = (vt >> 1);
            #pragma unroll
            for (int ndp = 0; ndp < 4; ndp++) {
                int c = ndp * 2 + ch;
                uint32_t off = jsw + (uint32_t)((c * 16) ^ ((j & 7) << 4));
                uint32_t r0, r1, r2, r3;
                uint32_t bh0[2], bh1[2];
                ldmatrix_x4_trans(r0, r1, r2, r3, VH + off);
                bh0[0] = r0; bh0[1] = r1; bh1[0] = r2; bh1[1] = r3;
                #pragma unroll
                for (int mf = 0; mf < 2; mf++) {
                    mma_f16(o[mf][2*ndp],   ph[mf], bh0);
                    mma_f16(o[mf][2*ndp],   pl[mf], bh0);
                    mma_f16(o[mf][2*ndp+1], ph[mf], bh1);
                    mma_f16(o[mf][2*ndp+1], pl[mf], bh1);
                }
            }
        }
    }

    // ---- epilogue ----
    #pragma unroll
    for (int mf = 0; mf < 2; mf++) {
        const float inv0 = 1.0f / (lsum[2*mf]     + ATTN_EPS);
        const float inv1 = 1.0f / (lsum[2*mf + 1] + ATTN_EPS);
        const size_t base0 = (size_t)(b * SEQ + qstart + w * 32 + mf * 16 + gq) * INNER
                           + h * 64 + t4 * 2;
        const size_t base1 = base0 + (size_t)8 * INNER;
        #pragma unroll
        for (int nd = 0; nd < 8; nd++) {
            uint32_t h0, l0, h1, l1;
            pack_split(o[mf][nd][0] * inv0, o[mf][nd][1] * inv0, h0, l0);
            pack_split(o[mf][nd][2] * inv1, o[mf][nd][3] * inv1, h1, l1);
            *(uint32_t*)(goh + base0 + nd * 8) = h0;
            *(uint32_t*)(gol + base0 + nd * 8) = l0;
            *(uint32_t*)(goh + base1 + nd * 8) = h1;
            *(uint32_t*)(gol + base1 + nd * 8) = l1;
        }
    }
}

// ---------------------------------------------------------------------------
// Launch
// ---------------------------------------------------------------------------
extern "C" void kernel_launch(void* const* d_in, const int* in_sizes, int n_in,
                              void* d_out, int out_size)
{
    const float* x   = (const float*)d_in[0];
    const float* Wq  = (const float*)d_in[1];
    const float* Wkv = (const float*)d_in[2];
    const float* Wo  = (const float*)d_in[3];
    const float* bo  = (const float*)d_in[4];
    float* out = (float*)d_out;

    __half *pxh, *pxl, *pw1, *pwo, *pqkvh, *pqkvl, *path, *patl;
    cudaGetSymbolAddress((void**)&pxh,   g_xh);
    cudaGetSymbolAddress((void**)&pxl,   g_xl);
    cudaGetSymbolAddress((void**)&pw1,   g_w1);
    cudaGetSymbolAddress((void**)&pwo,   g_wot);
    cudaGetSymbolAddress((void**)&pqkvh, g_qkvh);
    cudaGetSymbolAddress((void**)&pqkvl, g_qkvl);
    cudaGetSymbolAddress((void**)&path,  g_ath);
    cudaGetSymbolAddress((void**)&patl,  g_atl);

    cudaFuncSetAttribute(gemm_mma,
                         cudaFuncAttributeMaxDynamicSharedMemorySize, GEMM_SMEM);
    cudaFuncSetAttribute(gemm_mma_split,
                         cudaFuncAttributeMaxDynamicSharedMemorySize, GEMM_SMEM);
    cudaFuncSetAttribute(attn_mma,
                         cudaFuncAttributeMaxDynamicSharedMemorySize, AT_SMEM);

    // --- prep: split x (fp16 hi/lo); transpose weights (fp16 single) ---
    {
        int n4 = ROWS * DMODEL / 4;
        split_kernel<<<(n4 + 255) / 256, 256>>>(x, pxh, pxl, n4);
    }
    transpose_half<<<dim3(INNER / 32, DMODEL / 32),     dim3(32, 8)>>>(
        Wq,  pw1, DMODEL, INNER);
    transpose_half<<<dim3(2 * INNER / 32, DMODEL / 32), dim3(32, 8)>>>(
        Wkv, pw1 + (size_t)INNER * DMODEL, DMODEL, 2 * INNER);
    transpose_half<<<dim3(DMODEL / 32, INNER / 32),     dim3(32, 8)>>>(
        Wo,  pwo, INNER, DMODEL);

    // --- fused projection: [q|kv] = x @ [Wq Wkv], q cols pre-scaled 0.125 ---
    gemm_mma_split<<<dim3(QKVW / 128, ROWS / 256), 256, GEMM_SMEM>>>(
        pxh, pxl, pw1, pqkvh, pqkvl, ROWS, QKVW, DMODEL, INNER, 0.125f);

    // --- attention ---
    attn_mma<<<dim3(SEQ / 128, BATCH * HEADS), 128, AT_SMEM>>>(
        pqkvh, pqkvl, path, patl);

    // --- out = att @ Wo + bo ---
    gemm_mma<<<dim3(DMODEL / 128, ROWS / 256), 256, GEMM_SMEM>>>(
        path, patl, pwo, bo, out, ROWS, DMODEL, INNER);
}

// round 11
// speedup vs baseline: 4.7319x; 1.2084x over previous
#include <cuda_runtime.h>
#include <cuda_fp16.h>
#include <math.h>
#include <stdint.h>

// ---------------------------------------------------------------------------
// Problem constants
// ---------------------------------------------------------------------------
#define BATCH   2
#define SEQ     2048
#define DMODEL  1024
#define HEADS   16
#define DHEAD   64
#define INNER   (HEADS * DHEAD)      // 1024
#define ROWS    (BATCH * SEQ)        // 4096
#define QKVW    (3 * INNER)          // 3072
#define ATTN_EPS 1e-8f

// ---------------------------------------------------------------------------
// Scratch (device globals)
// ---------------------------------------------------------------------------
__device__ __half g_xh  [ROWS * DMODEL];          // x split hi/lo (fp16)
__device__ __half g_xl  [ROWS * DMODEL];
__device__ __half g_w1  [QKVW * DMODEL];          // [Wq^T; Wkv^T] fp16 single
__device__ __half g_wot [DMODEL * INNER];         // Wo^T fp16 single
__device__ __half g_qkvh [ROWS * QKVW];           // fused q|k|v hi
__device__ __half g_qkvl [ROWS * QKVW];           // q|k lo (v region unused)
__device__ __half g_ath [ROWS * INNER];           // attention out (single fp16)

// ---------------------------------------------------------------------------
// Helpers (base ISA only)
// ---------------------------------------------------------------------------
__device__ __forceinline__ uint32_t smem_u32(const void* p) {
    uint32_t a;
    asm("{ .reg .u64 t; cvta.to.shared.u64 t, %1; cvt.u32.u64 %0, t; }"
        : "=r"(a) : "l"(p));
    return a;
}

__device__ __forceinline__ void ldmatrix_x4(uint32_t& r0, uint32_t& r1,
                                            uint32_t& r2, uint32_t& r3,
                                            uint32_t addr) {
    asm volatile("ldmatrix.sync.aligned.m8n8.x4.shared.b16 {%0,%1,%2,%3}, [%4];"
                 : "=r"(r0), "=r"(r1), "=r"(r2), "=r"(r3) : "r"(addr));
}

__device__ __forceinline__ void ldmatrix_x4_trans(uint32_t& r0, uint32_t& r1,
                                                  uint32_t& r2, uint32_t& r3,
                                                  uint32_t addr) {
    asm volatile("ldmatrix.sync.aligned.m8n8.x4.trans.shared.b16 {%0,%1,%2,%3}, [%4];"
                 : "=r"(r0), "=r"(r1), "=r"(r2), "=r"(r3) : "r"(addr));
}

__device__ __forceinline__ void mma_f16(float* d, const uint32_t* a, const uint32_t* b) {
    asm volatile(
        "mma.sync.aligned.m16n8k16.row.col.f32.f16.f16.f32 "
        "{%0,%1,%2,%3}, {%4,%5,%6,%7}, {%8,%9}, {%0,%1,%2,%3};"
        : "+f"(d[0]), "+f"(d[1]), "+f"(d[2]), "+f"(d[3])
        : "r"(a[0]), "r"(a[1]), "r"(a[2]), "r"(a[3]), "r"(b[0]), "r"(b[1]));
}

__device__ __forceinline__ void cp_async16(uint32_t saddr, const void* gaddr) {
    asm volatile("cp.async.cg.shared.global [%0], [%1], 16;"
                 :: "r"(saddr), "l"(gaddr));
}
__device__ __forceinline__ void cp_commit() {
    asm volatile("cp.async.commit_group;" ::: "memory");
}
template <int N>
__device__ __forceinline__ void cp_wait() {
    asm volatile("cp.async.wait_group %0;" :: "n"(N) : "memory");
}

__device__ __forceinline__ uint32_t sw64(uint32_t byte) {
    return byte ^ ((byte >> 3) & 0x30);
}

__device__ __forceinline__ void split2h(float v, __half& h, __half& l) {
    h = __float2half_rn(v);
    l = __float2half_rn(v - __half2float(h));
}

// pack two floats into fp16x2 hi and fp16x2 lo (exact Dekker-style residual)
__device__ __forceinline__ void pack_split(float a, float b, uint32_t& hi, uint32_t& lo) {
    __half ha = __float2half_rn(a), hb = __float2half_rn(b);
    float ra = a - __half2float(ha), rb = b - __half2float(hb);
    __half2 H; H.x = ha; H.y = hb;
    __half2 L; L.x = __float2half_rn(ra); L.y = __float2half_rn(rb);
    hi = *(uint32_t*)&H;
    lo = *(uint32_t*)&L;
}

__device__ __forceinline__ uint32_t pack2(float a, float b) {
    __half2 H = __floats2half2_rn(a, b);
    return *(uint32_t*)&H;
}

// ---------------------------------------------------------------------------
// Prep kernels
// ---------------------------------------------------------------------------
__global__ __launch_bounds__(256)
void split_kernel(const float* __restrict__ X,
                  __half* __restrict__ H, __half* __restrict__ L, int n4)
{
    int i = blockIdx.x * blockDim.x + threadIdx.x;
    if (i >= n4) return;
    float4 v = ((const float4*)X)[i];
    union { __half b[4]; uint2 u; } uh, ul;
    split2h(v.x, uh.b[0], ul.b[0]);
    split2h(v.y, uh.b[1], ul.b[1]);
    split2h(v.z, uh.b[2], ul.b[2]);
    split2h(v.w, uh.b[3], ul.b[3]);
    ((uint2*)H)[i] = uh.u;
    ((uint2*)L)[i] = ul.u;
}

// W[K,N] row-major -> T[N,K] fp16 (single precision level)
__global__ __launch_bounds__(256)
void transpose_half(const float* __restrict__ W, __half* __restrict__ T,
                    int K, int N)
{
    __shared__ float t[32][33];
    int n  = blockIdx.x * 32 + threadIdx.x;
    int k0 = blockIdx.y * 32 + threadIdx.y;
    #pragma unroll
    for (int i = 0; i < 32; i += 8)
        t[threadIdx.y + i][threadIdx.x] = W[(size_t)(k0 + i) * N + n];
    __syncthreads();
    int k  = blockIdx.y * 32 + threadIdx.x;
    int n0 = blockIdx.x * 32 + threadIdx.y;
    #pragma unroll
    for (int i = 0; i < 32; i += 8)
        T[(size_t)(n0 + i) * K + k] = __float2half_rn(t[threadIdx.x][threadIdx.y + i]);
}

// ---------------------------------------------------------------------------
// HMMA GEMM core, templated on #A-terms: C = (Ah [+ Al]) @ Bh^T, Bh [N,K].
// 256x128 CTA tile, 256 thr (4x2 warps, 64x64 each), BK=32, 3-stage cp.async.
// ---------------------------------------------------------------------------
#define STG_BYTES   40960
#define OFF_AH      0
#define OFF_AL      16384
#define OFF_BH      32768
#define GEMM_SMEM   (3 * STG_BYTES)

struct GemmCtx {
    float acc[4][8][4];
    int wr, wc, lane;
};

template <int AT>
__device__ __forceinline__ void gemm_core(
    const __half* __restrict__ Ah, const __half* __restrict__ Al,
    const __half* __restrict__ Bh,
    int K, int row0, int col0, GemmCtx& g)
{
    extern __shared__ char smraw[];
    const uint32_t sbase = smem_u32(smraw);

    const int tid  = threadIdx.x;
    const int wid  = tid >> 5;
    const int lane = tid & 31;
    g.wr = wid & 3; g.wc = wid >> 2; g.lane = lane;

    const int nIter = K >> 5;
    const int lm_row = lane & 15;
    const int lm_koc = (lane >> 4) * 8;

    #pragma unroll
    for (int mf = 0; mf < 4; mf++)
        #pragma unroll
        for (int nf = 0; nf < 8; nf++)
            #pragma unroll
            for (int r = 0; r < 4; r++) g.acc[mf][nf][r] = 0.f;

    auto fill_stage = [&](int s, int kk0) {
        const uint32_t st = sbase + s * STG_BYTES;
        #pragma unroll
        for (int it = 0; it < 4; it++) {
            int idx = tid + it * 256;
            int r = idx >> 2, c = idx & 3;
            uint32_t off = sw64((uint32_t)(r * 64 + c * 16));
            size_t ga = (size_t)(row0 + r) * K + kk0 + c * 8;
            cp_async16(st + OFF_AH + off, Ah + ga);
            if (AT == 2) cp_async16(st + OFF_AL + off, Al + ga);
        }
        #pragma unroll
        for (int it = 0; it < 2; it++) {
            int idx = tid + it * 256;
            int r = idx >> 2, c = idx & 3;
            uint32_t off = sw64((uint32_t)(r * 64 + c * 16));
            size_t gb = (size_t)(col0 + r) * K + kk0 + c * 8;
            cp_async16(st + OFF_BH + off, Bh + gb);
        }
    };

    fill_stage(0, 0);  cp_commit();
    fill_stage(1, 32); cp_commit();

    for (int kt = 0; kt < nIter; kt++) {
        const int s = kt % 3;
        const uint32_t st = sbase + s * STG_BYTES;

        cp_wait<1>();
        __syncthreads();

        if (kt + 2 < nIter) fill_stage((kt + 2) % 3, (kt + 2) * 32);
        cp_commit();

        #pragma unroll
        for (int ks = 0; ks < 2; ks++) {
            const int colb = (ks * 16 + lm_koc) * 2;
            uint32_t ah[4][4], al[4][4];

            #pragma unroll
            for (int mf = 0; mf < 4; mf++) {
                int r = g.wr * 64 + mf * 16 + lm_row;
                uint32_t off = sw64((uint32_t)(r * 64 + colb));
                ldmatrix_x4(ah[mf][0], ah[mf][1], ah[mf][2], ah[mf][3], st + OFF_AH + off);
                if (AT == 2)
                    ldmatrix_x4(al[mf][0], al[mf][1], al[mf][2], al[mf][3], st + OFF_AL + off);
            }
            #pragma unroll
            for (int np = 0; np < 4; np++) {
                int r = g.wc * 64 + np * 16 + lm_row;
                uint32_t off = sw64((uint32_t)(r * 64 + colb));
                uint32_t r0, r1, r2, r3;
                uint32_t bh0[2], bh1[2];
                ldmatrix_x4(r0, r1, r2, r3, st + OFF_BH + off);
                bh0[0] = r0; bh0[1] = r2; bh1[0] = r1; bh1[1] = r3;
                #pragma unroll
                for (int mf = 0; mf < 4; mf++) {
                    mma_f16(g.acc[mf][2*np],   ah[mf], bh0);
                    if (AT == 2) mma_f16(g.acc[mf][2*np], al[mf], bh0);
                    mma_f16(g.acc[mf][2*np+1], ah[mf], bh1);
                    if (AT == 2) mma_f16(g.acc[mf][2*np+1], al[mf], bh1);
                }
            }
        }
        __syncthreads();
    }
}

// fp32-output GEMM (+bias) — final projection, 1-term A
__global__ __launch_bounds__(256, 1)
void gemm_out(const __half* __restrict__ Ah, const __half* __restrict__ Bh,
              const float* __restrict__ bias, float* __restrict__ C,
              int N, int K)
{
    GemmCtx g;
    const int row0 = blockIdx.y * 256;
    const int col0 = blockIdx.x * 128;
    gemm_core<1>(Ah, nullptr, Bh, K, row0, col0, g);

    const int gq = g.lane >> 2;
    const int t4 = g.lane & 3;
    #pragma unroll
    for (int mf = 0; mf < 4; mf++) {
        int r0g = row0 + g.wr * 64 + mf * 16 + gq;
        #pragma unroll
        for (int nf = 0; nf < 8; nf++) {
            int cg = col0 + g.wc * 64 + nf * 8 + t4 * 2;
            float bx = bias[cg], by = bias[cg + 1];
            float2 v0 = { g.acc[mf][nf][0] + bx, g.acc[mf][nf][1] + by };
            float2 v1 = { g.acc[mf][nf][2] + bx, g.acc[mf][nf][3] + by };
            *(float2*)(C + (size_t)r0g * N + cg)       = v0;
            *(float2*)(C + (size_t)(r0g + 8) * N + cg) = v1;
        }
    }
}

// split-output GEMM (templated #A-terms): writes hi (and lo if Ol != null)
// into column slice [0,Nw) of a buffer with row stride ldO.
template <int AT>
__global__ __launch_bounds__(256, 1)
void gemm_split(const __half* __restrict__ Ah, const __half* __restrict__ Al,
                const __half* __restrict__ Bh,
                __half* __restrict__ Oh, __half* __restrict__ Ol,
                int ldO, int K, int scaleN, float scaleV)
{
    GemmCtx g;
    const int row0 = blockIdx.y * 256;
    const int col0 = blockIdx.x * 128;
    gemm_core<AT>(Ah, Al, Bh, K, row0, col0, g);

    const int gq = g.lane >> 2;
    const int t4 = g.lane & 3;
    #pragma unroll
    for (int mf = 0; mf < 4; mf++) {
        int r0g = row0 + g.wr * 64 + mf * 16 + gq;
        #pragma unroll
        for (int nf = 0; nf < 8; nf++) {
            int cg = col0 + g.wc * 64 + nf * 8 + t4 * 2;
            float sc = (cg < scaleN) ? scaleV : 1.0f;
            float a0 = g.acc[mf][nf][0] * sc, a1 = g.acc[mf][nf][1] * sc;
            float a2 = g.acc[mf][nf][2] * sc, a3 = g.acc[mf][nf][3] * sc;
            if (Ol) {
                uint32_t h0, l0, h1, l1;
                pack_split(a0, a1, h0, l0);
                pack_split(a2, a3, h1, l1);
                *(uint32_t*)(Oh + (size_t)r0g * ldO + cg)       = h0;
                *(uint32_t*)(Ol + (size_t)r0g * ldO + cg)       = l0;
                *(uint32_t*)(Oh + (size_t)(r0g + 8) * ldO + cg) = h1;
                *(uint32_t*)(Ol + (size_t)(r0g + 8) * ldO + cg) = l1;
            } else {
                *(uint32_t*)(Oh + (size_t)r0g * ldO + cg)       = pack2(a0, a1);
                *(uint32_t*)(Oh + (size_t)(r0g + 8) * ldO + cg) = pack2(a2, a3);
            }
        }
    }
}

// ---------------------------------------------------------------------------
// HMMA flash attention (fp16): 4 warps x 32 q-rows (Br=128, Bc=64).
// S = 2-term ((qh+ql) x kh), PV = 1-term (P-hi x V).
// QH fragments hoisted across the KV loop; QL read per tile.
// Stage: KH 8K | VH 8K = 16K, double-buffered. 2 CTAs/SM.
// Output: single fp16.
// ---------------------------------------------------------------------------
#define AT_Q_BYTES   32768
#define AT_STG_BYTES 16384
#define AT_SMEM      (1024 + AT_Q_BYTES + 2 * AT_STG_BYTES)

__global__ __launch_bounds__(128, 2)
void attn_mma(const __half* __restrict__ qkvh,
              const __half* __restrict__ qkvl,
              __half* __restrict__ goh)
{
    extern __shared__ char smraw[];
    const uint32_t b0a = smem_u32(smraw);
    const uint32_t sb = (b0a + 1023u) & ~1023u;

    const int tid = threadIdx.x;
    const int w = tid >> 5, lane = tid & 31;
    const int gq = lane >> 2, t4 = lane & 3;
    const int lm_row = lane & 15, lm_koc = (lane >> 4) * 8;
    const int vt = lane >> 3, vrl = lane & 7;
    const int b = blockIdx.y >> 4, h = blockIdx.y & 15;
    const int qt = gridDim.x - 1 - blockIdx.x;
    const int qstart = qt * 128;
    const int igmax = qstart + w * 32 + 31;

    const uint32_t QH = sb, QL = sb + 16384;
    const uint32_t ST0 = sb + AT_Q_BYTES;

    const size_t rowbase = (size_t)(b * SEQ) * QKVW + h * 64;

    // ---- Q fill (own cp.async group) ----
    #pragma unroll
    for (int it = 0; it < 16; it++) {
        int idx = tid + it * 128;
        int bs = idx >> 10, r = (idx >> 3) & 127, c = idx & 7;
        const __half* src = (bs ? qkvl : qkvh)
            + rowbase + (size_t)(qstart + r) * QKVW + c * 8;
        cp_async16((bs ? QL : QH) + (uint32_t)(r * 128 + ((c * 16) ^ ((r & 7) << 4))), src);
    }
    cp_commit();

    // ---- K/V stage fill: KH + VH ----
    auto fill_kv = [&](int s, int jstart) {
        const uint32_t st = ST0 + s * AT_STG_BYTES;
        #pragma unroll
        for (int it = 0; it < 8; it++) {
            int idx = tid + it * 128;            // 0..1023
            int tile = idx >> 9;                 // 0:KH 1:VH
            int r = (idx >> 3) & 63, c = idx & 7;
            int col = (tile ? 2048 : 1024) + c * 8;
            const __half* src = qkvh + rowbase + (size_t)(jstart + r) * QKVW + col;
            cp_async16(st + (uint32_t)(tile * 8192 + r * 128 + ((c * 16) ^ ((r & 7) << 4))), src);
        }
    };

    fill_kv(0, 0);
    cp_commit();

    // ---- wait for Q (KV0 may stay pending), hoist QH frags ----
    cp_wait<1>();
    __syncthreads();

    uint32_t qa[2][4][4];                        // [mf][kd][reg] Q-hi
    #pragma unroll
    for (int kd = 0; kd < 4; kd++) {
        const int cb = (kd * 16 + lm_koc) * 2;
        #pragma unroll
        for (int mf = 0; mf < 2; mf++) {
            int r = w * 32 + mf * 16 + lm_row;
            uint32_t off = (uint32_t)(r * 128 + (cb ^ ((r & 7) << 4)));
            ldmatrix_x4(qa[mf][kd][0], qa[mf][kd][1], qa[mf][kd][2], qa[mf][kd][3],
                        QH + off);
        }
    }

    float o[2][8][4];
    float m[4] = { -INFINITY, -INFINITY, -INFINITY, -INFINITY };
    float lsum[4] = { 0.f, 0.f, 0.f, 0.f };
    #pragma unroll
    for (int mf = 0; mf < 2; mf++)
        #pragma unroll
        for (int nd = 0; nd < 8; nd++)
            #pragma unroll
            for (int r = 0; r < 4; r++) o[mf][nd][r] = 0.f;

    const int nT = 2 * qt + 2;
    for (int jt = 0; jt < nT; jt++) {
        const int jstart = jt * 64;
        const uint32_t st = ST0 + (jt & 1) * AT_STG_BYTES;
        const uint32_t KH = st, VH = st + 8192;

        if (jt > 0) __syncthreads();
        if (jt + 1 < nT) {
            fill_kv((jt + 1) & 1, jstart + 64);
            cp_commit();
            cp_wait<1>();
        } else {
            cp_wait<0>();
        }
        __syncthreads();

        // ---- S = Q @ K^T (2-term: qh*kh + ql*kh) ----
        float s[2][8][4];
        #pragma unroll
        for (int mf = 0; mf < 2; mf++)
            #pragma unroll
            for (int nj = 0; nj < 8; nj++)
                #pragma unroll
                for (int r = 0; r < 4; r++) s[mf][nj][r] = 0.f;

        #pragma unroll
        for (int kd = 0; kd < 4; kd++) {
            const int cb = (kd * 16 + lm_koc) * 2;
            uint32_t qb[2][4];
            #pragma unroll
            for (int mf = 0; mf < 2; mf++) {
                int r = w * 32 + mf * 16 + lm_row;
                uint32_t off = (uint32_t)(r * 128 + (cb ^ ((r & 7) << 4)));
                ldmatrix_x4(qb[mf][0], qb[mf][1], qb[mf][2], qb[mf][3], QL + off);
            }
            #pragma unroll
            for (int jp = 0; jp < 4; jp++) {
                if (jstart + jp * 16 > igmax) continue;
                int r = jp * 16 + lm_row;
                uint32_t off = (uint32_t)(r * 128 + (cb ^ ((r & 7) << 4)));
                uint32_t r0, r1, r2, r3;
                uint32_t bh0[2], bh1[2];
                ldmatrix_x4(r0, r1, r2, r3, KH + off);
                bh0[0] = r0; bh0[1] = r2; bh1[0] = r1; bh1[1] = r3;
                #pragma unroll
                for (int mf = 0; mf < 2; mf++) {
                    mma_f16(s[mf][2*jp],   qa[mf][kd], bh0);
                    mma_f16(s[mf][2*jp],   qb[mf],     bh0);
                    mma_f16(s[mf][2*jp+1], qa[mf][kd], bh1);
                    mma_f16(s[mf][2*jp+1], qb[mf],     bh1);
                }
            }
        }

        // ---- online softmax ----
        float alpha[4];
        #pragma unroll
        for (int mf = 0; mf < 2; mf++) {
            #pragma unroll
            for (int hh = 0; hh < 2; hh++) {
                const int hr = 2 * mf + hh;
                float mx = -INFINITY;
                #pragma unroll
                for (int nj = 0; nj < 8; nj++)
                    mx = fmaxf(mx, fmaxf(s[mf][nj][2*hh], s[mf][nj][2*hh+1]));
                mx = fmaxf(mx, __shfl_xor_sync(0xffffffffu, mx, 1));
                mx = fmaxf(mx, __shfl_xor_sync(0xffffffffu, mx, 2));
                float mn = fmaxf(m[hr], mx);
                alpha[hr] = __expf(m[hr] - mn);
                m[hr] = mn;
                const int ig = qstart + w * 32 + mf * 16 + hh * 8 + gq;
                float rs = 0.f;
                #pragma unroll
                for (int nj = 0; nj < 8; nj++) {
                    int jg = jstart + nj * 8 + t4 * 2;
                    float p0 = (jg     <= ig) ? __expf(s[mf][nj][2*hh]   - mn) : 0.f;
                    float p1 = (jg + 1 <= ig) ? __expf(s[mf][nj][2*hh+1] - mn) : 0.f;
                    s[mf][nj][2*hh] = p0; s[mf][nj][2*hh+1] = p1;
                    rs += p0 + p1;
                }
                rs += __shfl_xor_sync(0xffffffffu, rs, 1);
                rs += __shfl_xor_sync(0xffffffffu, rs, 2);
                lsum[hr] = lsum[hr] * alpha[hr] + rs;
            }
            #pragma unroll
            for (int nd = 0; nd < 8; nd++) {
                o[mf][nd][0] *= alpha[2*mf];     o[mf][nd][1] *= alpha[2*mf];
                o[mf][nd][2] *= alpha[2*mf + 1]; o[mf][nd][3] *= alpha[2*mf + 1];
            }
        }

        // ---- O += P @ V (1-term: P-hi x V) ----
        #pragma unroll
        for (int kj = 0; kj < 4; kj++) {
            if (jstart + kj * 16 > igmax) continue;
            uint32_t ph[2][4];
            #pragma unroll
            for (int mf = 0; mf < 2; mf++) {
                ph[mf][0] = pack2(s[mf][2*kj][0],   s[mf][2*kj][1]);
                ph[mf][1] = pack2(s[mf][2*kj][2],   s[mf][2*kj][3]);
                ph[mf][2] = pack2(s[mf][2*kj+1][0], s[mf][2*kj+1][1]);
                ph[mf][3] = pack2(s[mf][2*kj+1][2], s[mf][2*kj+1][3]);
            }
            const int j = kj * 16 + (vt & 1) * 8 + vrl;
            const uint32_t jsw = (uint32_t)(j * 128);
            const int ch = (vt >> 1);
            #pragma unroll
            for (int ndp = 0; ndp < 4; ndp++) {
                int c = ndp * 2 + ch;
                uint32_t off = jsw + (uint32_t)((c * 16) ^ ((j & 7) << 4));
                uint32_t r0, r1, r2, r3;
                uint32_t bh0[2], bh1[2];
                ldmatrix_x4_trans(r0, r1, r2, r3, VH + off);
                bh0[0] = r0; bh0[1] = r1; bh1[0] = r2; bh1[1] = r3;
                #pragma unroll
                for (int mf = 0; mf < 2; mf++) {
                    mma_f16(o[mf][2*ndp],   ph[mf], bh0);
                    mma_f16(o[mf][2*ndp+1], ph[mf], bh1);
                }
            }
        }
    }

    // ---- epilogue: normalize, single fp16 store ----
    #pragma unroll
    for (int mf = 0; mf < 2; mf++) {
        const float inv0 = 1.0f / (lsum[2*mf]     + ATTN_EPS);
        const float inv1 = 1.0f / (lsum[2*mf + 1] + ATTN_EPS);
        const size_t base0 = (size_t)(b * SEQ + qstart + w * 32 + mf * 16 + gq) * INNER
                           + h * 64 + t4 * 2;
        const size_t base1 = base0 + (size_t)8 * INNER;
        #pragma unroll
        for (int nd = 0; nd < 8; nd++) {
            *(uint32_t*)(goh + base0 + nd * 8) = pack2(o[mf][nd][0] * inv0,
                                                       o[mf][nd][1] * inv0);
            *(uint32_t*)(goh + base1 + nd * 8) = pack2(o[mf][nd][2] * inv1,
                                                       o[mf][nd][3] * inv1);
        }
    }
}

// ---------------------------------------------------------------------------
// Launch
// ---------------------------------------------------------------------------
extern "C" void kernel_launch(void* const* d_in, const int* in_sizes, int n_in,
                              void* d_out, int out_size)
{
    const float* x   = (const float*)d_in[0];
    const float* Wq  = (const float*)d_in[1];
    const float* Wkv = (const float*)d_in[2];
    const float* Wo  = (const float*)d_in[3];
    const float* bo  = (const float*)d_in[4];
    float* out = (float*)d_out;

    __half *pxh, *pxl, *pw1, *pwo, *pqkvh, *pqkvl, *path;
    cudaGetSymbolAddress((void**)&pxh,   g_xh);
    cudaGetSymbolAddress((void**)&pxl,   g_xl);
    cudaGetSymbolAddress((void**)&pw1,   g_w1);
    cudaGetSymbolAddress((void**)&pwo,   g_wot);
    cudaGetSymbolAddress((void**)&pqkvh, g_qkvh);
    cudaGetSymbolAddress((void**)&pqkvl, g_qkvl);
    cudaGetSymbolAddress((void**)&path,  g_ath);

    cudaFuncSetAttribute(gemm_out,
                         cudaFuncAttributeMaxDynamicSharedMemorySize, GEMM_SMEM);
    cudaFuncSetAttribute(gemm_split<1>,
                         cudaFuncAttributeMaxDynamicSharedMemorySize, GEMM_SMEM);
    cudaFuncSetAttribute(gemm_split<2>,
                         cudaFuncAttributeMaxDynamicSharedMemorySize, GEMM_SMEM);
    cudaFuncSetAttribute(attn_mma,
                         cudaFuncAttributeMaxDynamicSharedMemorySize, AT_SMEM);

    // --- prep: split x (fp16 hi/lo); transpose weights (fp16 single) ---
    {
        int n4 = ROWS * DMODEL / 4;
        split_kernel<<<(n4 + 255) / 256, 256>>>(x, pxh, pxl, n4);
    }
    transpose_half<<<dim3(INNER / 32, DMODEL / 32),     dim3(32, 8)>>>(
        Wq,  pw1, DMODEL, INNER);
    transpose_half<<<dim3(2 * INNER / 32, DMODEL / 32), dim3(32, 8)>>>(
        Wkv, pw1 + (size_t)INNER * DMODEL, DMODEL, 2 * INNER);
    transpose_half<<<dim3(DMODEL / 32, INNER / 32),     dim3(32, 8)>>>(
        Wo,  pwo, INNER, DMODEL);

    // --- projections into fused q|k|v buffer (row stride 3072) ---
    // qk: 2-term, cols [0,2048), q cols scaled by 0.125, hi+lo out
    gemm_split<2><<<dim3(2 * INNER / 128, ROWS / 256), 256, GEMM_SMEM>>>(
        pxh, pxl, pw1, pqkvh, pqkvl, QKVW, DMODEL, INNER, 0.125f);
    // v: 1-term, cols [2048,3072), hi only
    gemm_split<1><<<dim3(INNER / 128, ROWS / 256), 256, GEMM_SMEM>>>(
        pxh, nullptr, pw1 + (size_t)(2 * INNER) * DMODEL,
        pqkvh + 2 * INNER, nullptr, QKVW, DMODEL, 0, 1.0f);

    // --- attention (S 2-term, PV 1-term, single fp16 out) ---
    attn_mma<<<dim3(SEQ / 128, BATCH * HEADS), 128, AT_SMEM>>>(
        pqkvh, pqkvl, path);

    // --- out = att @ Wo + bo (1-term) ---
    gemm_out<<<dim3(DMODEL / 128, ROWS / 256), 256, GEMM_SMEM>>>(
        path, pwo, bo, out, DMODEL, INNER);
}

// round 12
// speedup vs baseline: 4.7889x; 1.0121x over previous
#include <cuda_runtime.h>
#include <cuda_fp16.h>
#include <math.h>
#include <stdint.h>

// ---------------------------------------------------------------------------
// Problem constants
// ---------------------------------------------------------------------------
#define BATCH   2
#define SEQ     2048
#define DMODEL  1024
#define HEADS   16
#define DHEAD   64
#define INNER   (HEADS * DHEAD)      // 1024
#define ROWS    (BATCH * SEQ)        // 4096
#define QKVW    (3 * INNER)          // 3072
#define ATTN_EPS 1e-8f

// ---------------------------------------------------------------------------
// Scratch (device globals)
// ---------------------------------------------------------------------------
__device__ __half g_xh  [ROWS * DMODEL];          // x split hi/lo (fp16)
__device__ __half g_xl  [ROWS * DMODEL];
__device__ __half g_w1  [QKVW * DMODEL];          // [Wq^T; Wkv^T] fp16 single
__device__ __half g_wot [DMODEL * INNER];         // Wo^T fp16 single
__device__ __half g_qkvh [ROWS * QKVW];           // fused q|k|v hi
__device__ __half g_qkvl [ROWS * QKVW];           // q|k lo (v region unused)
__device__ __half g_ath [ROWS * INNER];           // attention out (single fp16)

// ---------------------------------------------------------------------------
// Helpers (base ISA only)
// ---------------------------------------------------------------------------
__device__ __forceinline__ uint32_t smem_u32(const void* p) {
    uint32_t a;
    asm("{ .reg .u64 t; cvta.to.shared.u64 t, %1; cvt.u32.u64 %0, t; }"
        : "=r"(a) : "l"(p));
    return a;
}

__device__ __forceinline__ void ldmatrix_x4(uint32_t& r0, uint32_t& r1,
                                            uint32_t& r2, uint32_t& r3,
                                            uint32_t addr) {
    asm volatile("ldmatrix.sync.aligned.m8n8.x4.shared.b16 {%0,%1,%2,%3}, [%4];"
                 : "=r"(r0), "=r"(r1), "=r"(r2), "=r"(r3) : "r"(addr));
}

__device__ __forceinline__ void ldmatrix_x4_trans(uint32_t& r0, uint32_t& r1,
                                                  uint32_t& r2, uint32_t& r3,
                                                  uint32_t addr) {
    asm volatile("ldmatrix.sync.aligned.m8n8.x4.trans.shared.b16 {%0,%1,%2,%3}, [%4];"
                 : "=r"(r0), "=r"(r1), "=r"(r2), "=r"(r3) : "r"(addr));
}

__device__ __forceinline__ void mma_f16(float* d, const uint32_t* a, const uint32_t* b) {
    asm volatile(
        "mma.sync.aligned.m16n8k16.row.col.f32.f16.f16.f32 "
        "{%0,%1,%2,%3}, {%4,%5,%6,%7}, {%8,%9}, {%0,%1,%2,%3};"
        : "+f"(d[0]), "+f"(d[1]), "+f"(d[2]), "+f"(d[3])
        : "r"(a[0]), "r"(a[1]), "r"(a[2]), "r"(a[3]), "r"(b[0]), "r"(b[1]));
}

__device__ __forceinline__ void cp_async16(uint32_t saddr, const void* gaddr) {
    asm volatile("cp.async.cg.shared.global [%0], [%1], 16;"
                 :: "r"(saddr), "l"(gaddr));
}
__device__ __forceinline__ void cp_commit() {
    asm volatile("cp.async.commit_group;" ::: "memory");
}
template <int N>
__device__ __forceinline__ void cp_wait() {
    asm volatile("cp.async.wait_group %0;" :: "n"(N) : "memory");
}

__device__ __forceinline__ uint32_t sw64(uint32_t byte) {
    return byte ^ ((byte >> 3) & 0x30);
}

__device__ __forceinline__ void split2h(float v, __half& h, __half& l) {
    h = __float2half_rn(v);
    l = __float2half_rn(v - __half2float(h));
}

__device__ __forceinline__ void pack_split(float a, float b, uint32_t& hi, uint32_t& lo) {
    __half ha = __float2half_rn(a), hb = __float2half_rn(b);
    float ra = a - __half2float(ha), rb = b - __half2float(hb);
    __half2 H; H.x = ha; H.y = hb;
    __half2 L; L.x = __float2half_rn(ra); L.y = __float2half_rn(rb);
    hi = *(uint32_t*)&H;
    lo = *(uint32_t*)&L;
}

__device__ __forceinline__ uint32_t pack2(float a, float b) {
    __half2 H = __floats2half2_rn(a, b);
    return *(uint32_t*)&H;
}

// ---------------------------------------------------------------------------
// Fused prep kernel: blocks [0,4096) split x into fp16 hi/lo;
// blocks [4096,8192) transpose Wq / Wkv / Wo into fp16 [N,K].
// ---------------------------------------------------------------------------
#define PREP_SPLIT_BLOCKS 4096    // ROWS*DMODEL/4 / 256
#define PREP_TOTAL_BLOCKS 8192

__global__ __launch_bounds__(256)
void prep_kernel(const float* __restrict__ x,
                 __half* __restrict__ xh, __half* __restrict__ xl,
                 const float* __restrict__ Wq, const float* __restrict__ Wkv,
                 const float* __restrict__ Wo,
                 __half* __restrict__ w1, __half* __restrict__ wot)
{
    __shared__ float t[32][33];
    int bid = blockIdx.x;
    const int tid = threadIdx.x;

    if (bid < PREP_SPLIT_BLOCKS) {
        int i = bid * 256 + tid;
        float4 v = ((const float4*)x)[i];
        union { __half b[4]; uint2 u; } uh, ul;
        split2h(v.x, uh.b[0], ul.b[0]);
        split2h(v.y, uh.b[1], ul.b[1]);
        split2h(v.z, uh.b[2], ul.b[2]);
        split2h(v.w, uh.b[3], ul.b[3]);
        ((uint2*)xh)[i] = uh.u;
        ((uint2*)xl)[i] = ul.u;
        return;
    }

    bid -= PREP_SPLIT_BLOCKS;
    const float* W;
    __half* T;
    int K, N;
    if (bid < 1024)      { W = Wq;  T = w1;                              K = DMODEL; N = INNER; }
    else if (bid < 3072) { bid -= 1024; W = Wkv; T = w1 + (size_t)INNER * DMODEL; K = DMODEL; N = 2 * INNER; }
    else                 { bid -= 3072; W = Wo;  T = wot;                K = INNER;  N = DMODEL; }

    const int nbx = N / 32;
    const int bx = bid % nbx, by = bid / nbx;
    const int tx = tid & 31, ty = tid >> 5;

    int n  = bx * 32 + tx;
    int k0 = by * 32 + ty;
    #pragma unroll
    for (int i = 0; i < 32; i += 8)
        t[ty + i][tx] = W[(size_t)(k0 + i) * N + n];
    __syncthreads();
    int k  = by * 32 + tx;
    int n0 = bx * 32 + ty;
    #pragma unroll
    for (int i = 0; i < 32; i += 8)
        T[(size_t)(n0 + i) * K + k] = __float2half_rn(t[tx][ty + i]);
}

// ---------------------------------------------------------------------------
// HMMA GEMM core, templated on #A-terms: C = (Ah [+ Al]) @ Bh^T, Bh [N,K].
// 256x128 CTA tile, 256 thr (4x2 warps, 64x64 each), BK=32, 3-stage cp.async.
// ---------------------------------------------------------------------------
#define STG_BYTES   40960
#define OFF_AH      0
#define OFF_AL      16384
#define OFF_BH      32768
#define GEMM_SMEM   (3 * STG_BYTES)

struct GemmCtx {
    float acc[4][8][4];
    int wr, wc, lane;
};

template <int AT>
__device__ __forceinline__ void gemm_core(
    const __half* __restrict__ Ah, const __half* __restrict__ Al,
    const __half* __restrict__ Bh,
    int K, int row0, int col0, GemmCtx& g)
{
    extern __shared__ char smraw[];
    const uint32_t sbase = smem_u32(smraw);

    const int tid  = threadIdx.x;
    const int wid  = tid >> 5;
    const int lane = tid & 31;
    g.wr = wid & 3; g.wc = wid >> 2; g.lane = lane;

    const int nIter = K >> 5;
    const int lm_row = lane & 15;
    const int lm_koc = (lane >> 4) * 8;

    #pragma unroll
    for (int mf = 0; mf < 4; mf++)
        #pragma unroll
        for (int nf = 0; nf < 8; nf++)
            #pragma unroll
            for (int r = 0; r < 4; r++) g.acc[mf][nf][r] = 0.f;

    auto fill_stage = [&](int s, int kk0) {
        const uint32_t st = sbase + s * STG_BYTES;
        #pragma unroll
        for (int it = 0; it < 4; it++) {
            int idx = tid + it * 256;
            int r = idx >> 2, c = idx & 3;
            uint32_t off = sw64((uint32_t)(r * 64 + c * 16));
            size_t ga = (size_t)(row0 + r) * K + kk0 + c * 8;
            cp_async16(st + OFF_AH + off, Ah + ga);
            if (AT == 2) cp_async16(st + OFF_AL + off, Al + ga);
        }
        #pragma unroll
        for (int it = 0; it < 2; it++) {
            int idx = tid + it * 256;
            int r = idx >> 2, c = idx & 3;
            uint32_t off = sw64((uint32_t)(r * 64 + c * 16));
            size_t gb = (size_t)(col0 + r) * K + kk0 + c * 8;
            cp_async16(st + OFF_BH + off, Bh + gb);
        }
    };

    fill_stage(0, 0);  cp_commit();
    fill_stage(1, 32); cp_commit();

    for (int kt = 0; kt < nIter; kt++) {
        const int s = kt % 3;
        const uint32_t st = sbase + s * STG_BYTES;

        cp_wait<1>();
        __syncthreads();

        if (kt + 2 < nIter) fill_stage((kt + 2) % 3, (kt + 2) * 32);
        cp_commit();

        #pragma unroll
        for (int ks = 0; ks < 2; ks++) {
            const int colb = (ks * 16 + lm_koc) * 2;
            uint32_t ah[4][4], al[4][4];

            #pragma unroll
            for (int mf = 0; mf < 4; mf++) {
                int r = g.wr * 64 + mf * 16 + lm_row;
                uint32_t off = sw64((uint32_t)(r * 64 + colb));
                ldmatrix_x4(ah[mf][0], ah[mf][1], ah[mf][2], ah[mf][3], st + OFF_AH + off);
                if (AT == 2)
                    ldmatrix_x4(al[mf][0], al[mf][1], al[mf][2], al[mf][3], st + OFF_AL + off);
            }
            #pragma unroll
            for (int np = 0; np < 4; np++) {
                int r = g.wc * 64 + np * 16 + lm_row;
                uint32_t off = sw64((uint32_t)(r * 64 + colb));
                uint32_t r0, r1, r2, r3;
                uint32_t bh0[2], bh1[2];
                ldmatrix_x4(r0, r1, r2, r3, st + OFF_BH + off);
                bh0[0] = r0; bh0[1] = r2; bh1[0] = r1; bh1[1] = r3;
                #pragma unroll
                for (int mf = 0; mf < 4; mf++) {
                    mma_f16(g.acc[mf][2*np],   ah[mf], bh0);
                    if (AT == 2) mma_f16(g.acc[mf][2*np], al[mf], bh0);
                    mma_f16(g.acc[mf][2*np+1], ah[mf], bh1);
                    if (AT == 2) mma_f16(g.acc[mf][2*np+1], al[mf], bh1);
                }
            }
        }
        __syncthreads();
    }
}

// ---------------------------------------------------------------------------
// Merged q|k|v projection: one launch over N=3072.
//  cols [0,2048)  : 2-term (x hi+lo), hi/lo split out, q cols scaled 0.125
//  cols [2048,3072): 1-term (x hi only), hi out
// ---------------------------------------------------------------------------
__global__ __launch_bounds__(256, 1)
void gemm_qkv(const __half* __restrict__ Ah, const __half* __restrict__ Al,
              const __half* __restrict__ W,
              __half* __restrict__ Oh, __half* __restrict__ Ol)
{
    const int row0 = blockIdx.y * 256;
    const int col0 = blockIdx.x * 128;

    if (col0 < 2 * INNER) {
        GemmCtx g;
        gemm_core<2>(Ah, Al, W, DMODEL, row0, col0, g);
        const int gq = g.lane >> 2;
        const int t4 = g.lane & 3;
        #pragma unroll
        for (int mf = 0; mf < 4; mf++) {
            int r0g = row0 + g.wr * 64 + mf * 16 + gq;
            #pragma unroll
            for (int nf = 0; nf < 8; nf++) {
                int cg = col0 + g.wc * 64 + nf * 8 + t4 * 2;
                float sc = (cg < INNER) ? 0.125f : 1.0f;
                uint32_t h0, l0, h1, l1;
                pack_split(g.acc[mf][nf][0] * sc, g.acc[mf][nf][1] * sc, h0, l0);
                pack_split(g.acc[mf][nf][2] * sc, g.acc[mf][nf][3] * sc, h1, l1);
                *(uint32_t*)(Oh + (size_t)r0g * QKVW + cg)       = h0;
                *(uint32_t*)(Ol + (size_t)r0g * QKVW + cg)       = l0;
                *(uint32_t*)(Oh + (size_t)(r0g + 8) * QKVW + cg) = h1;
                *(uint32_t*)(Ol + (size_t)(r0g + 8) * QKVW + cg) = l1;
            }
        }
    } else {
        GemmCtx g;
        gemm_core<1>(Ah, nullptr, W, DMODEL, row0, col0, g);
        const int gq = g.lane >> 2;
        const int t4 = g.lane & 3;
        #pragma unroll
        for (int mf = 0; mf < 4; mf++) {
            int r0g = row0 + g.wr * 64 + mf * 16 + gq;
            #pragma unroll
            for (int nf = 0; nf < 8; nf++) {
                int cg = col0 + g.wc * 64 + nf * 8 + t4 * 2;
                *(uint32_t*)(Oh + (size_t)r0g * QKVW + cg)
                    = pack2(g.acc[mf][nf][0], g.acc[mf][nf][1]);
                *(uint32_t*)(Oh + (size_t)(r0g + 8) * QKVW + cg)
                    = pack2(g.acc[mf][nf][2], g.acc[mf][nf][3]);
            }
        }
    }
}

// fp32-output GEMM (+bias) — final projection, 1-term A
__global__ __launch_bounds__(256, 1)
void gemm_out(const __half* __restrict__ Ah, const __half* __restrict__ Bh,
              const float* __restrict__ bias, float* __restrict__ C,
              int N, int K)
{
    GemmCtx g;
    const int row0 = blockIdx.y * 256;
    const int col0 = blockIdx.x * 128;
    gemm_core<1>(Ah, nullptr, Bh, K, row0, col0, g);

    const int gq = g.lane >> 2;
    const int t4 = g.lane & 3;
    #pragma unroll
    for (int mf = 0; mf < 4; mf++) {
        int r0g = row0 + g.wr * 64 + mf * 16 + gq;
        #pragma unroll
        for (int nf = 0; nf < 8; nf++) {
            int cg = col0 + g.wc * 64 + nf * 8 + t4 * 2;
            float bx = bias[cg], by = bias[cg + 1];
            float2 v0 = { g.acc[mf][nf][0] + bx, g.acc[mf][nf][1] + by };
            float2 v1 = { g.acc[mf][nf][2] + bx, g.acc[mf][nf][3] + by };
            *(float2*)(C + (size_t)r0g * N + cg)       = v0;
            *(float2*)(C + (size_t)(r0g + 8) * N + cg) = v1;
        }
    }
}

// ---------------------------------------------------------------------------
// HMMA flash attention (fp16): 4 warps x 32 q-rows (Br=128, Bc=64).
// S = 2-term ((qh+ql) x kh), PV = 1-term (P-hi x V).
// QH fragments hoisted across the KV loop; QL read per tile.
// Stage: KH 8K | VH 8K = 16K, double-buffered. 2 CTAs/SM.
// ---------------------------------------------------------------------------
#define AT_Q_BYTES   32768
#define AT_STG_BYTES 16384
#define AT_SMEM      (1024 + AT_Q_BYTES + 2 * AT_STG_BYTES)

__global__ __launch_bounds__(128, 2)
void attn_mma(const __half* __restrict__ qkvh,
              const __half* __restrict__ qkvl,
              __half* __restrict__ goh)
{
    extern __shared__ char smraw[];
    const uint32_t b0a = smem_u32(smraw);
    const uint32_t sb = (b0a + 1023u) & ~1023u;

    const int tid = threadIdx.x;
    const int w = tid >> 5, lane = tid & 31;
    const int gq = lane >> 2, t4 = lane & 3;
    const int lm_row = lane & 15, lm_koc = (lane >> 4) * 8;
    const int vt = lane >> 3, vrl = lane & 7;
    const int b = blockIdx.y >> 4, h = blockIdx.y & 15;
    const int qt = gridDim.x - 1 - blockIdx.x;
    const int qstart = qt * 128;
    const int igmax = qstart + w * 32 + 31;

    const uint32_t QH = sb, QL = sb + 16384;
    const uint32_t ST0 = sb + AT_Q_BYTES;

    const size_t rowbase = (size_t)(b * SEQ) * QKVW + h * 64;

    // ---- Q fill (own cp.async group) ----
    #pragma unroll
    for (int it = 0; it < 16; it++) {
        int idx = tid + it * 128;
        int bs = idx >> 10, r = (idx >> 3) & 127, c = idx & 7;
        const __half* src = (bs ? qkvl : qkvh)
            + rowbase + (size_t)(qstart + r) * QKVW + c * 8;
        cp_async16((bs ? QL : QH) + (uint32_t)(r * 128 + ((c * 16) ^ ((r & 7) << 4))), src);
    }
    cp_commit();

    // ---- K/V stage fill: KH + VH ----
    auto fill_kv = [&](int s, int jstart) {
        const uint32_t st = ST0 + s * AT_STG_BYTES;
        #pragma unroll
        for (int it = 0; it < 8; it++) {
            int idx = tid + it * 128;            // 0..1023
            int tile = idx >> 9;                 // 0:KH 1:VH
            int r = (idx >> 3) & 63, c = idx & 7;
            int col = (tile ? 2048 : 1024) + c * 8;
            const __half* src = qkvh + rowbase + (size_t)(jstart + r) * QKVW + col;
            cp_async16(st + (uint32_t)(tile * 8192 + r * 128 + ((c * 16) ^ ((r & 7) << 4))), src);
        }
    };

    fill_kv(0, 0);
    cp_commit();

    // ---- wait for Q (KV0 may stay pending), hoist QH frags ----
    cp_wait<1>();
    __syncthreads();

    uint32_t qa[2][4][4];                        // [mf][kd][reg] Q-hi
    #pragma unroll
    for (int kd = 0; kd < 4; kd++) {
        const int cb = (kd * 16 + lm_koc) * 2;
        #pragma unroll
        for (int mf = 0; mf < 2; mf++) {
            int r = w * 32 + mf * 16 + lm_row;
            uint32_t off = (uint32_t)(r * 128 + (cb ^ ((r & 7) << 4)));
            ldmatrix_x4(qa[mf][kd][0], qa[mf][kd][1], qa[mf][kd][2], qa[mf][kd][3],
                        QH + off);
        }
    }

    float o[2][8][4];
    float m[4] = { -INFINITY, -INFINITY, -INFINITY, -INFINITY };
    float lsum[4] = { 0.f, 0.f, 0.f, 0.f };
    #pragma unroll
    for (int mf = 0; mf < 2; mf++)
        #pragma unroll
        for (int nd = 0; nd < 8; nd++)
            #pragma unroll
            for (int r = 0; r < 4; r++) o[mf][nd][r] = 0.f;

    const int nT = 2 * qt + 2;
    for (int jt = 0; jt < nT; jt++) {
        const int jstart = jt * 64;
        const uint32_t st = ST0 + (jt & 1) * AT_STG_BYTES;
        const uint32_t KH = st, VH = st + 8192;

        if (jt > 0) __syncthreads();
        if (jt + 1 < nT) {
            fill_kv((jt + 1) & 1, jstart + 64);
            cp_commit();
            cp_wait<1>();
        } else {
            cp_wait<0>();
        }
        __syncthreads();

        // ---- S = Q @ K^T (2-term: qh*kh + ql*kh) ----
        float s[2][8][4];
        #pragma unroll
        for (int mf = 0; mf < 2; mf++)
            #pragma unroll
            for (int nj = 0; nj < 8; nj++)
                #pragma unroll
                for (int r = 0; r < 4; r++) s[mf][nj][r] = 0.f;

        #pragma unroll
        for (int kd = 0; kd < 4; kd++) {
            const int cb = (kd * 16 + lm_koc) * 2;
            uint32_t qb[2][4];
            #pragma unroll
            for (int mf = 0; mf < 2; mf++) {
                int r = w * 32 + mf * 16 + lm_row;
                uint32_t off = (uint32_t)(r * 128 + (cb ^ ((r & 7) << 4)));
                ldmatrix_x4(qb[mf][0], qb[mf][1], qb[mf][2], qb[mf][3], QL + off);
            }
            #pragma unroll
            for (int jp = 0; jp < 4; jp++) {
                if (jstart + jp * 16 > igmax) continue;
                int r = jp * 16 + lm_row;
                uint32_t off = (uint32_t)(r * 128 + (cb ^ ((r & 7) << 4)));
                uint32_t r0, r1, r2, r3;
                uint32_t bh0[2], bh1[2];
                ldmatrix_x4(r0, r1, r2, r3, KH + off);
                bh0[0] = r0; bh0[1] = r2; bh1[0] = r1; bh1[1] = r3;
                #pragma unroll
                for (int mf = 0; mf < 2; mf++) {
                    mma_f16(s[mf][2*jp],   qa[mf][kd], bh0);
                    mma_f16(s[mf][2*jp],   qb[mf],     bh0);
                    mma_f16(s[mf][2*jp+1], qa[mf][kd], bh1);
                    mma_f16(s[mf][2*jp+1], qb[mf],     bh1);
                }
            }
        }

        // ---- online softmax ----
        float alpha[4];
        #pragma unroll
        for (int mf = 0; mf < 2; mf++) {
            #pragma unroll
            for (int hh = 0; hh < 2; hh++) {
                const int hr = 2 * mf + hh;
                float mx = -INFINITY;
                #pragma unroll
                for (int nj = 0; nj < 8; nj++)
                    mx = fmaxf(mx, fmaxf(s[mf][nj][2*hh], s[mf][nj][2*hh+1]));
                mx = fmaxf(mx, __shfl_xor_sync(0xffffffffu, mx, 1));
                mx = fmaxf(mx, __shfl_xor_sync(0xffffffffu, mx, 2));
                float mn = fmaxf(m[hr], mx);
                alpha[hr] = __expf(m[hr] - mn);
                m[hr] = mn;
                const int ig = qstart + w * 32 + mf * 16 + hh * 8 + gq;
                float rs = 0.f;
                #pragma unroll
                for (int nj = 0; nj < 8; nj++) {
                    int jg = jstart + nj * 8 + t4 * 2;
                    float p0 = (jg     <= ig) ? __expf(s[mf][nj][2*hh]   - mn) : 0.f;
                    float p1 = (jg + 1 <= ig) ? __expf(s[mf][nj][2*hh+1] - mn) : 0.f;
                    s[mf][nj][2*hh] = p0; s[mf][nj][2*hh+1] = p1;
                    rs += p0 + p1;
                }
                rs += __shfl_xor_sync(0xffffffffu, rs, 1);
                rs += __shfl_xor_sync(0xffffffffu, rs, 2);
                lsum[hr] = lsum[hr] * alpha[hr] + rs;
            }
            #pragma unroll
            for (int nd = 0; nd < 8; nd++) {
                o[mf][nd][0] *= alpha[2*mf];     o[mf][nd][1] *= alpha[2*mf];
                o[mf][nd][2] *= alpha[2*mf + 1]; o[mf][nd][3] *= alpha[2*mf + 1];
            }
        }

        // ---- O += P @ V (1-term: P-hi x V) ----
        #pragma unroll
        for (int kj = 0; kj < 4; kj++) {
            if (jstart + kj * 16 > igmax) continue;
            uint32_t ph[2][4];
            #pragma unroll
            for (int mf = 0; mf < 2; mf++) {
                ph[mf][0] = pack2(s[mf][2*kj][0],   s[mf][2*kj][1]);
                ph[mf][1] = pack2(s[mf][2*kj][2],   s[mf][2*kj][3]);
                ph[mf][2] = pack2(s[mf][2*kj+1][0], s[mf][2*kj+1][1]);
                ph[mf][3] = pack2(s[mf][2*kj+1][2], s[mf][2*kj+1][3]);
            }
            const int j = kj * 16 + (vt & 1) * 8 + vrl;
            const uint32_t jsw = (uint32_t)(j * 128);
            const int ch = (vt >> 1);
            #pragma unroll
            for (int ndp = 0; ndp < 4; ndp++) {
                int c = ndp * 2 + ch;
                uint32_t off = jsw + (uint32_t)((c * 16) ^ ((j & 7) << 4));
                uint32_t r0, r1, r2, r3;
                uint32_t bh0[2], bh1[2];
                ldmatrix_x4_trans(r0, r1, r2, r3, VH + off);
                bh0[0] = r0; bh0[1] = r1; bh1[0] = r2; bh1[1] = r3;
                #pragma unroll
                for (int mf = 0; mf < 2; mf++) {
                    mma_f16(o[mf][2*ndp],   ph[mf], bh0);
                    mma_f16(o[mf][2*ndp+1], ph[mf], bh1);
                }
            }
        }
    }

    // ---- epilogue: normalize, single fp16 store ----
    #pragma unroll
    for (int mf = 0; mf < 2; mf++) {
        const float inv0 = 1.0f / (lsum[2*mf]     + ATTN_EPS);
        const float inv1 = 1.0f / (lsum[2*mf + 1] + ATTN_EPS);
        const size_t base0 = (size_t)(b * SEQ + qstart + w * 32 + mf * 16 + gq) * INNER
                           + h * 64 + t4 * 2;
        const size_t base1 = base0 + (size_t)8 * INNER;
        #pragma unroll
        for (int nd = 0; nd < 8; nd++) {
            *(uint32_t*)(goh + base0 + nd * 8) = pack2(o[mf][nd][0] * inv0,
                                                       o[mf][nd][1] * inv0);
            *(uint32_t*)(goh + base1 + nd * 8) = pack2(o[mf][nd][2] * inv1,
                                                       o[mf][nd][3] * inv1);
        }
    }
}

// ---------------------------------------------------------------------------
// Launch
// ---------------------------------------------------------------------------
extern "C" void kernel_launch(void* const* d_in, const int* in_sizes, int n_in,
                              void* d_out, int out_size)
{
    const float* x   = (const float*)d_in[0];
    const float* Wq  = (const float*)d_in[1];
    const float* Wkv = (const float*)d_in[2];
    const float* Wo  = (const float*)d_in[3];
    const float* bo  = (const float*)d_in[4];
    float* out = (float*)d_out;

    __half *pxh, *pxl, *pw1, *pwo, *pqkvh, *pqkvl, *path;
    cudaGetSymbolAddress((void**)&pxh,   g_xh);
    cudaGetSymbolAddress((void**)&pxl,   g_xl);
    cudaGetSymbolAddress((void**)&pw1,   g_w1);
    cudaGetSymbolAddress((void**)&pwo,   g_wot);
    cudaGetSymbolAddress((void**)&pqkvh, g_qkvh);
    cudaGetSymbolAddress((void**)&pqkvl, g_qkvl);
    cudaGetSymbolAddress((void**)&path,  g_ath);

    cudaFuncSetAttribute(gemm_qkv,
                         cudaFuncAttributeMaxDynamicSharedMemorySize, GEMM_SMEM);
    cudaFuncSetAttribute(gemm_out,
                         cudaFuncAttributeMaxDynamicSharedMemorySize, GEMM_SMEM);
    cudaFuncSetAttribute(attn_mma,
                         cudaFuncAttributeMaxDynamicSharedMemorySize, AT_SMEM);

    // --- fused prep: x split + all three weight transposes, one launch ---
    prep_kernel<<<PREP_TOTAL_BLOCKS, 256>>>(x, pxh, pxl, Wq, Wkv, Wo, pw1, pwo);

    // --- merged projection: q|k (2-term, hi/lo) + v (1-term, hi) ---
    gemm_qkv<<<dim3(QKVW / 128, ROWS / 256), 256, GEMM_SMEM>>>(
        pxh, pxl, pw1, pqkvh, pqkvl);

    // --- attention (S 2-term, PV 1-term, single fp16 out) ---
    attn_mma<<<dim3(SEQ / 128, BATCH * HEADS), 128, AT_SMEM>>>(
        pqkvh, pqkvl, path);

    // --- out = att @ Wo + bo (1-term) ---
    gemm_out<<<dim3(DMODEL / 128, ROWS / 256), 256, GEMM_SMEM>>>(
        path, pwo, bo, out, DMODEL, INNER);
}

// round 13
// speedup vs baseline: 4.9167x; 1.0267x over previous
#include <cuda_runtime.h>
#include <cuda_fp16.h>
#include <math.h>
#include <stdint.h>

// ---------------------------------------------------------------------------
// Problem constants
// ---------------------------------------------------------------------------
#define BATCH   2
#define SEQ     2048
#define DMODEL  1024
#define HEADS   16
#define DHEAD   64
#define INNER   (HEADS * DHEAD)      // 1024
#define ROWS    (BATCH * SEQ)        // 4096
#define QKVW    (3 * INNER)          // 3072
#define ATTN_EPS 1e-8f

// ---------------------------------------------------------------------------
// Scratch (device globals)
// ---------------------------------------------------------------------------
__device__ __half g_xh  [ROWS * DMODEL];          // x split hi/lo (fp16)
__device__ __half g_xl  [ROWS * DMODEL];
__device__ __half g_w1  [QKVW * DMODEL];          // [Wq^T; Wkv^T] fp16 single
__device__ __half g_wot [DMODEL * INNER];         // Wo^T fp16 single
__device__ __half g_qkvh [ROWS * QKVW];           // fused q|k|v hi
__device__ __half g_qkvl [ROWS * QKVW];           // q|k lo (v region unused)
__device__ __half g_ath [ROWS * INNER];           // attention out (single fp16)

// ---------------------------------------------------------------------------
// Helpers (base ISA only)
// ---------------------------------------------------------------------------
__device__ __forceinline__ uint32_t smem_u32(const void* p) {
    uint32_t a;
    asm("{ .reg .u64 t; cvta.to.shared.u64 t, %1; cvt.u32.u64 %0, t; }"
        : "=r"(a) : "l"(p));
    return a;
}

__device__ __forceinline__ void ldmatrix_x4(uint32_t& r0, uint32_t& r1,
                                            uint32_t& r2, uint32_t& r3,
                                            uint32_t addr) {
    asm volatile("ldmatrix.sync.aligned.m8n8.x4.shared.b16 {%0,%1,%2,%3}, [%4];"
                 : "=r"(r0), "=r"(r1), "=r"(r2), "=r"(r3) : "r"(addr));
}

__device__ __forceinline__ void ldmatrix_x4_trans(uint32_t& r0, uint32_t& r1,
                                                  uint32_t& r2, uint32_t& r3,
                                                  uint32_t addr) {
    asm volatile("ldmatrix.sync.aligned.m8n8.x4.trans.shared.b16 {%0,%1,%2,%3}, [%4];"
                 : "=r"(r0), "=r"(r1), "=r"(r2), "=r"(r3) : "r"(addr));
}

__device__ __forceinline__ void mma_f16(float* d, const uint32_t* a, const uint32_t* b) {
    asm volatile(
        "mma.sync.aligned.m16n8k16.row.col.f32.f16.f16.f32 "
        "{%0,%1,%2,%3}, {%4,%5,%6,%7}, {%8,%9}, {%0,%1,%2,%3};"
        : "+f"(d[0]), "+f"(d[1]), "+f"(d[2]), "+f"(d[3])
        : "r"(a[0]), "r"(a[1]), "r"(a[2]), "r"(a[3]), "r"(b[0]), "r"(b[1]));
}

__device__ __forceinline__ void cp_async16(uint32_t saddr, const void* gaddr) {
    asm volatile("cp.async.cg.shared.global [%0], [%1], 16;"
                 :: "r"(saddr), "l"(gaddr));
}
__device__ __forceinline__ void cp_commit() {
    asm volatile("cp.async.commit_group;" ::: "memory");
}
template <int N>
__device__ __forceinline__ void cp_wait() {
    asm volatile("cp.async.wait_group %0;" :: "n"(N) : "memory");
}

__device__ __forceinline__ uint32_t sw64(uint32_t byte) {
    return byte ^ ((byte >> 3) & 0x30);
}

__device__ __forceinline__ void split2h(float v, __half& h, __half& l) {
    h = __float2half_rn(v);
    l = __float2half_rn(v - __half2float(h));
}

__device__ __forceinline__ void pack_split(float a, float b, uint32_t& hi, uint32_t& lo) {
    __half ha = __float2half_rn(a), hb = __float2half_rn(b);
    float ra = a - __half2float(ha), rb = b - __half2float(hb);
    __half2 H; H.x = ha; H.y = hb;
    __half2 L; L.x = __float2half_rn(ra); L.y = __float2half_rn(rb);
    hi = *(uint32_t*)&H;
    lo = *(uint32_t*)&L;
}

__device__ __forceinline__ uint32_t pack2(float a, float b) {
    __half2 H = __floats2half2_rn(a, b);
    return *(uint32_t*)&H;
}

// ---------------------------------------------------------------------------
// Fused prep kernel: blocks [0,4096) split x into fp16 hi/lo;
// blocks [4096,8192) transpose Wq / Wkv / Wo into fp16 [N,K].
// ---------------------------------------------------------------------------
#define PREP_SPLIT_BLOCKS 4096
#define PREP_TOTAL_BLOCKS 8192

__global__ __launch_bounds__(256)
void prep_kernel(const float* __restrict__ x,
                 __half* __restrict__ xh, __half* __restrict__ xl,
                 const float* __restrict__ Wq, const float* __restrict__ Wkv,
                 const float* __restrict__ Wo,
                 __half* __restrict__ w1, __half* __restrict__ wot)
{
    __shared__ float t[32][33];
    int bid = blockIdx.x;
    const int tid = threadIdx.x;

    if (bid < PREP_SPLIT_BLOCKS) {
        int i = bid * 256 + tid;
        float4 v = ((const float4*)x)[i];
        union { __half b[4]; uint2 u; } uh, ul;
        split2h(v.x, uh.b[0], ul.b[0]);
        split2h(v.y, uh.b[1], ul.b[1]);
        split2h(v.z, uh.b[2], ul.b[2]);
        split2h(v.w, uh.b[3], ul.b[3]);
        ((uint2*)xh)[i] = uh.u;
        ((uint2*)xl)[i] = ul.u;
        return;
    }

    bid -= PREP_SPLIT_BLOCKS;
    const float* W;
    __half* T;
    int K, N;
    if (bid < 1024)      { W = Wq;  T = w1;                              K = DMODEL; N = INNER; }
    else if (bid < 3072) { bid -= 1024; W = Wkv; T = w1 + (size_t)INNER * DMODEL; K = DMODEL; N = 2 * INNER; }
    else                 { bid -= 3072; W = Wo;  T = wot;                K = INNER;  N = DMODEL; }

    const int nbx = N / 32;
    const int bx = bid % nbx, by = bid / nbx;
    const int tx = tid & 31, ty = tid >> 5;

    int n  = bx * 32 + tx;
    int k0 = by * 32 + ty;
    #pragma unroll
    for (int i = 0; i < 32; i += 8)
        t[ty + i][tx] = W[(size_t)(k0 + i) * N + n];
    __syncthreads();
    int k  = by * 32 + tx;
    int n0 = bx * 32 + ty;
    #pragma unroll
    for (int i = 0; i < 32; i += 8)
        T[(size_t)(n0 + i) * K + k] = __float2half_rn(t[tx][ty + i]);
}

// ---------------------------------------------------------------------------
// HMMA GEMM core, 128x128 CTA tile, 256 thr (2x4 warps, 64x32 each), BK=32,
// 3-stage cp.async; templated on #A-terms. Stage: AH 8K [+AL 8K] + BH 8K.
// 2-term smem = 72KB, 1-term = 48KB -> 2 CTAs/SM (16 warps) for both.
// ---------------------------------------------------------------------------
#define STG2_BYTES  24576
#define STG1_BYTES  16384
#define GEMM2_SMEM  (3 * STG2_BYTES)
#define GEMM1_SMEM  (3 * STG1_BYTES)

struct GemmCtx {
    float acc[4][4][4];
    int wr, wc, lane;
};

template <int AT>
__device__ __forceinline__ void gemm_core(
    const __half* __restrict__ Ah, const __half* __restrict__ Al,
    const __half* __restrict__ Bh,
    int K, int row0, int col0, GemmCtx& g)
{
    extern __shared__ char smraw[];
    const uint32_t sbase = smem_u32(smraw);
    const int STG = (AT == 2) ? STG2_BYTES : STG1_BYTES;
    const int OFF_AL = 8192;
    const int OFF_BH = (AT == 2) ? 16384 : 8192;

    const int tid  = threadIdx.x;
    const int wid  = tid >> 5;
    const int lane = tid & 31;
    g.wr = wid >> 2; g.wc = wid & 3; g.lane = lane;   // 2 x 4 warp grid

    const int nIter = K >> 5;
    const int lm_row = lane & 15;
    const int lm_koc = (lane >> 4) * 8;

    #pragma unroll
    for (int mf = 0; mf < 4; mf++)
        #pragma unroll
        for (int nf = 0; nf < 4; nf++)
            #pragma unroll
            for (int r = 0; r < 4; r++) g.acc[mf][nf][r] = 0.f;

    auto fill_stage = [&](int s, int kk0) {
        const uint32_t st = sbase + s * STG;
        #pragma unroll
        for (int it = 0; it < 2; it++) {
            int idx = tid + it * 256;            // 0..511 : A rows x chunks
            int r = idx >> 2, c = idx & 3;
            uint32_t off = sw64((uint32_t)(r * 64 + c * 16));
            size_t ga = (size_t)(row0 + r) * K + kk0 + c * 8;
            cp_async16(st + off, Ah + ga);
            if (AT == 2) cp_async16(st + OFF_AL + off, Al + ga);
        }
        #pragma unroll
        for (int it = 0; it < 2; it++) {
            int idx = tid + it * 256;            // 0..511 : B rows x chunks
            int r = idx >> 2, c = idx & 3;
            uint32_t off = sw64((uint32_t)(r * 64 + c * 16));
            size_t gb = (size_t)(col0 + r) * K + kk0 + c * 8;
            cp_async16(st + OFF_BH + off, Bh + gb);
        }
    };

    fill_stage(0, 0);  cp_commit();
    fill_stage(1, 32); cp_commit();

    for (int kt = 0; kt < nIter; kt++) {
        const int s = kt % 3;
        const uint32_t st = sbase + s * STG;

        cp_wait<1>();
        __syncthreads();

        if (kt + 2 < nIter) fill_stage((kt + 2) % 3, (kt + 2) * 32);
        cp_commit();

        #pragma unroll
        for (int ks = 0; ks < 2; ks++) {
            const int colb = (ks * 16 + lm_koc) * 2;
            uint32_t ah[4][4], al[4][4];

            #pragma unroll
            for (int mf = 0; mf < 4; mf++) {
                int r = g.wr * 64 + mf * 16 + lm_row;
                uint32_t off = sw64((uint32_t)(r * 64 + colb));
                ldmatrix_x4(ah[mf][0], ah[mf][1], ah[mf][2], ah[mf][3], st + off);
                if (AT == 2)
                    ldmatrix_x4(al[mf][0], al[mf][1], al[mf][2], al[mf][3],
                                st + OFF_AL + off);
            }
            #pragma unroll
            for (int np = 0; np < 2; np++) {
                int r = g.wc * 32 + np * 16 + lm_row;
                uint32_t off = sw64((uint32_t)(r * 64 + colb));
                uint32_t r0, r1, r2, r3;
                uint32_t bh0[2], bh1[2];
                ldmatrix_x4(r0, r1, r2, r3, st + OFF_BH + off);
                bh0[0] = r0; bh0[1] = r2; bh1[0] = r1; bh1[1] = r3;
                #pragma unroll
                for (int mf = 0; mf < 4; mf++) {
                    mma_f16(g.acc[mf][2*np],   ah[mf], bh0);
                    if (AT == 2) mma_f16(g.acc[mf][2*np], al[mf], bh0);
                    mma_f16(g.acc[mf][2*np+1], ah[mf], bh1);
                    if (AT == 2) mma_f16(g.acc[mf][2*np+1], al[mf], bh1);
                }
            }
        }
        __syncthreads();
    }
}

// ---------------------------------------------------------------------------
// Merged q|k|v projection (one launch, N=3072):
//  cols [0,2048)  : 2-term (x hi+lo), hi/lo split out, q cols scaled 0.125
//  cols [2048,3072): 1-term (x hi only), hi out
// ---------------------------------------------------------------------------
__global__ __launch_bounds__(256, 2)
void gemm_qkv(const __half* __restrict__ Ah, const __half* __restrict__ Al,
              const __half* __restrict__ W,
              __half* __restrict__ Oh, __half* __restrict__ Ol)
{
    const int row0 = blockIdx.y * 128;
    const int col0 = blockIdx.x * 128;

    if (col0 < 2 * INNER) {
        GemmCtx g;
        gemm_core<2>(Ah, Al, W, DMODEL, row0, col0, g);
        const int gq = g.lane >> 2;
        const int t4 = g.lane & 3;
        #pragma unroll
        for (int mf = 0; mf < 4; mf++) {
            int r0g = row0 + g.wr * 64 + mf * 16 + gq;
            #pragma unroll
            for (int nf = 0; nf < 4; nf++) {
                int cg = col0 + g.wc * 32 + nf * 8 + t4 * 2;
                float sc = (cg < INNER) ? 0.125f : 1.0f;
                uint32_t h0, l0, h1, l1;
                pack_split(g.acc[mf][nf][0] * sc, g.acc[mf][nf][1] * sc, h0, l0);
                pack_split(g.acc[mf][nf][2] * sc, g.acc[mf][nf][3] * sc, h1, l1);
                *(uint32_t*)(Oh + (size_t)r0g * QKVW + cg)       = h0;
                *(uint32_t*)(Ol + (size_t)r0g * QKVW + cg)       = l0;
                *(uint32_t*)(Oh + (size_t)(r0g + 8) * QKVW + cg) = h1;
                *(uint32_t*)(Ol + (size_t)(r0g + 8) * QKVW + cg) = l1;
            }
        }
    } else {
        GemmCtx g;
        gemm_core<1>(Ah, nullptr, W, DMODEL, row0, col0, g);
        const int gq = g.lane >> 2;
        const int t4 = g.lane & 3;
        #pragma unroll
        for (int mf = 0; mf < 4; mf++) {
            int r0g = row0 + g.wr * 64 + mf * 16 + gq;
            #pragma unroll
            for (int nf = 0; nf < 4; nf++) {
                int cg = col0 + g.wc * 32 + nf * 8 + t4 * 2;
                *(uint32_t*)(Oh + (size_t)r0g * QKVW + cg)
                    = pack2(g.acc[mf][nf][0], g.acc[mf][nf][1]);
                *(uint32_t*)(Oh + (size_t)(r0g + 8) * QKVW + cg)
                    = pack2(g.acc[mf][nf][2], g.acc[mf][nf][3]);
            }
        }
    }
}

// fp32-output GEMM (+bias) — final projection, 1-term A
__global__ __launch_bounds__(256, 2)
void gemm_out(const __half* __restrict__ Ah, const __half* __restrict__ Bh,
              const float* __restrict__ bias, float* __restrict__ C,
              int N, int K)
{
    GemmCtx g;
    const int row0 = blockIdx.y * 128;
    const int col0 = blockIdx.x * 128;
    gemm_core<1>(Ah, nullptr, Bh, K, row0, col0, g);

    const int gq = g.lane >> 2;
    const int t4 = g.lane & 3;
    #pragma unroll
    for (int mf = 0; mf < 4; mf++) {
        int r0g = row0 + g.wr * 64 + mf * 16 + gq;
        #pragma unroll
        for (int nf = 0; nf < 4; nf++) {
            int cg = col0 + g.wc * 32 + nf * 8 + t4 * 2;
            float bx = bias[cg], by = bias[cg + 1];
            float2 v0 = { g.acc[mf][nf][0] + bx, g.acc[mf][nf][1] + by };
            float2 v1 = { g.acc[mf][nf][2] + bx, g.acc[mf][nf][3] + by };
            *(float2*)(C + (size_t)r0g * N + cg)       = v0;
            *(float2*)(C + (size_t)(r0g + 8) * N + cg) = v1;
        }
    }
}

// ---------------------------------------------------------------------------
// HMMA flash attention (fp16): 4 warps x 32 q-rows (Br=128, Bc=64).
// S = 2-term ((qh+ql) x kh), PV = 1-term (P-hi x V).
// QH fragments hoisted across the KV loop; QL read per tile.
// Stage: KH 8K | VH 8K = 16K, double-buffered. 2 CTAs/SM. (unchanged)
// ---------------------------------------------------------------------------
#define AT_Q_BYTES   32768
#define AT_STG_BYTES 16384
#define AT_SMEM      (1024 + AT_Q_BYTES + 2 * AT_STG_BYTES)

__global__ __launch_bounds__(128, 2)
void attn_mma(const __half* __restrict__ qkvh,
              const __half* __restrict__ qkvl,
              __half* __restrict__ goh)
{
    extern __shared__ char smraw[];
    const uint32_t b0a = smem_u32(smraw);
    const uint32_t sb = (b0a + 1023u) & ~1023u;

    const int tid = threadIdx.x;
    const int w = tid >> 5, lane = tid & 31;
    const int gq = lane >> 2, t4 = lane & 3;
    const int lm_row = lane & 15, lm_koc = (lane >> 4) * 8;
    const int vt = lane >> 3, vrl = lane & 7;
    const int b = blockIdx.y >> 4, h = blockIdx.y & 15;
    const int qt = gridDim.x - 1 - blockIdx.x;
    const int qstart = qt * 128;
    const int igmax = qstart + w * 32 + 31;

    const uint32_t QH = sb, QL = sb + 16384;
    const uint32_t ST0 = sb + AT_Q_BYTES;

    const size_t rowbase = (size_t)(b * SEQ) * QKVW + h * 64;

    // ---- Q fill (own cp.async group) ----
    #pragma unroll
    for (int it = 0; it < 16; it++) {
        int idx = tid + it * 128;
        int bs = idx >> 10, r = (idx >> 3) & 127, c = idx & 7;
        const __half* src = (bs ? qkvl : qkvh)
            + rowbase + (size_t)(qstart + r) * QKVW + c * 8;
        cp_async16((bs ? QL : QH) + (uint32_t)(r * 128 + ((c * 16) ^ ((r & 7) << 4))), src);
    }
    cp_commit();

    // ---- K/V stage fill: KH + VH ----
    auto fill_kv = [&](int s, int jstart) {
        const uint32_t st = ST0 + s * AT_STG_BYTES;
        #pragma unroll
        for (int it = 0; it < 8; it++) {
            int idx = tid + it * 128;            // 0..1023
            int tile = idx >> 9;                 // 0:KH 1:VH
            int r = (idx >> 3) & 63, c = idx & 7;
            int col = (tile ? 2048 : 1024) + c * 8;
            const __half* src = qkvh + rowbase + (size_t)(jstart + r) * QKVW + col;
            cp_async16(st + (uint32_t)(tile * 8192 + r * 128 + ((c * 16) ^ ((r & 7) << 4))), src);
        }
    };

    fill_kv(0, 0);
    cp_commit();

    // ---- wait for Q (KV0 may stay pending), hoist QH frags ----
    cp_wait<1>();
    __syncthreads();

    uint32_t qa[2][4][4];                        // [mf][kd][reg] Q-hi
    #pragma unroll
    for (int kd = 0; kd < 4; kd++) {
        const int cb = (kd * 16 + lm_koc) * 2;
        #pragma unroll
        for (int mf = 0; mf < 2; mf++) {
            int r = w * 32 + mf * 16 + lm_row;
            uint32_t off = (uint32_t)(r * 128 + (cb ^ ((r & 7) << 4)));
            ldmatrix_x4(qa[mf][kd][0], qa[mf][kd][1], qa[mf][kd][2], qa[mf][kd][3],
                        QH + off);
        }
    }

    float o[2][8][4];
    float m[4] = { -INFINITY, -INFINITY, -INFINITY, -INFINITY };
    float lsum[4] = { 0.f, 0.f, 0.f, 0.f };
    #pragma unroll
    for (int mf = 0; mf < 2; mf++)
        #pragma unroll
        for (int nd = 0; nd < 8; nd++)
            #pragma unroll
            for (int r = 0; r < 4; r++) o[mf][nd][r] = 0.f;

    const int nT = 2 * qt + 2;
    for (int jt = 0; jt < nT; jt++) {
        const int jstart = jt * 64;
        const uint32_t st = ST0 + (jt & 1) * AT_STG_BYTES;
        const uint32_t KH = st, VH = st + 8192;

        if (jt > 0) __syncthreads();
        if (jt + 1 < nT) {
            fill_kv((jt + 1) & 1, jstart + 64);
            cp_commit();
            cp_wait<1>();
        } else {
            cp_wait<0>();
        }
        __syncthreads();

        // ---- S = Q @ K^T (2-term: qh*kh + ql*kh) ----
        float s[2][8][4];
        #pragma unroll
        for (int mf = 0; mf < 2; mf++)
            #pragma unroll
            for (int nj = 0; nj < 8; nj++)
                #pragma unroll
                for (int r = 0; r < 4; r++) s[mf][nj][r] = 0.f;

        #pragma unroll
        for (int kd = 0; kd < 4; kd++) {
            const int cb = (kd * 16 + lm_koc) * 2;
            uint32_t qb[2][4];
            #pragma unroll
            for (int mf = 0; mf < 2; mf++) {
                int r = w * 32 + mf * 16 + lm_row;
                uint32_t off = (uint32_t)(r * 128 + (cb ^ ((r & 7) << 4)));
                ldmatrix_x4(qb[mf][0], qb[mf][1], qb[mf][2], qb[mf][3], QL + off);
            }
            #pragma unroll
            for (int jp = 0; jp < 4; jp++) {
                if (jstart + jp * 16 > igmax) continue;
                int r = jp * 16 + lm_row;
                uint32_t off = (uint32_t)(r * 128 + (cb ^ ((r & 7) << 4)));
                uint32_t r0, r1, r2, r3;
                uint32_t bh0[2], bh1[2];
                ldmatrix_x4(r0, r1, r2, r3, KH + off);
                bh0[0] = r0; bh0[1] = r2; bh1[0] = r1; bh1[1] = r3;
                #pragma unroll
                for (int mf = 0; mf < 2; mf++) {
                    mma_f16(s[mf][2*jp],   qa[mf][kd], bh0);
                    mma_f16(s[mf][2*jp],   qb[mf],     bh0);
                    mma_f16(s[mf][2*jp+1], qa[mf][kd], bh1);
                    mma_f16(s[mf][2*jp+1], qb[mf],     bh1);
                }
            }
        }

        // ---- online softmax ----
        float alpha[4];
        #pragma unroll
        for (int mf = 0; mf < 2; mf++) {
            #pragma unroll
            for (int hh = 0; hh < 2; hh++) {
                const int hr = 2 * mf + hh;
                float mx = -INFINITY;
                #pragma unroll
                for (int nj = 0; nj < 8; nj++)
                    mx = fmaxf(mx, fmaxf(s[mf][nj][2*hh], s[mf][nj][2*hh+1]));
                mx = fmaxf(mx, __shfl_xor_sync(0xffffffffu, mx, 1));
                mx = fmaxf(mx, __shfl_xor_sync(0xffffffffu, mx, 2));
                float mn = fmaxf(m[hr], mx);
                alpha[hr] = __expf(m[hr] - mn);
                m[hr] = mn;
                const int ig = qstart + w * 32 + mf * 16 + hh * 8 + gq;
                float rs = 0.f;
                #pragma unroll
                for (int nj = 0; nj < 8; nj++) {
                    int jg = jstart + nj * 8 + t4 * 2;
                    float p0 = (jg     <= ig) ? __expf(s[mf][nj][2*hh]   - mn) : 0.f;
                    float p1 = (jg + 1 <= ig) ? __expf(s[mf][nj][2*hh+1] - mn) : 0.f;
                    s[mf][nj][2*hh] = p0; s[mf][nj][2*hh+1] = p1;
                    rs += p0 + p1;
                }
                rs += __shfl_xor_sync(0xffffffffu, rs, 1);
                rs += __shfl_xor_sync(0xffffffffu, rs, 2);
                lsum[hr] = lsum[hr] * alpha[hr] + rs;
            }
            #pragma unroll
            for (int nd = 0; nd < 8; nd++) {
                o[mf][nd][0] *= alpha[2*mf];     o[mf][nd][1] *= alpha[2*mf];
                o[mf][nd][2] *= alpha[2*mf + 1]; o[mf][nd][3] *= alpha[2*mf + 1];
            }
        }

        // ---- O += P @ V (1-term: P-hi x V) ----
        #pragma unroll
        for (int kj = 0; kj < 4; kj++) {
            if (jstart + kj * 16 > igmax) continue;
            uint32_t ph[2][4];
            #pragma unroll
            for (int mf = 0; mf < 2; mf++) {
                ph[mf][0] = pack2(s[mf][2*kj][0],   s[mf][2*kj][1]);
                ph[mf][1] = pack2(s[mf][2*kj][2],   s[mf][2*kj][3]);
                ph[mf][2] = pack2(s[mf][2*kj+1][0], s[mf][2*kj+1][1]);
                ph[mf][3] = pack2(s[mf][2*kj+1][2], s[mf][2*kj+1][3]);
            }
            const int j = kj * 16 + (vt & 1) * 8 + vrl;
            const uint32_t jsw = (uint32_t)(j * 128);
            const int ch = (vt >> 1);
            #pragma unroll
            for (int ndp = 0; ndp < 4; ndp++) {
                int c = ndp * 2 + ch;
                uint32_t off = jsw + (uint32_t)((c * 16) ^ ((j & 7) << 4));
                uint32_t r0, r1, r2, r3;
                uint32_t bh0[2], bh1[2];
                ldmatrix_x4_trans(r0, r1, r2, r3, VH + off);
                bh0[0] = r0; bh0[1] = r1; bh1[0] = r2; bh1[1] = r3;
                #pragma unroll
                for (int mf = 0; mf < 2; mf++) {
                    mma_f16(o[mf][2*ndp],   ph[mf], bh0);
                    mma_f16(o[mf][2*ndp+1], ph[mf], bh1);
                }
            }
        }
    }

    // ---- epilogue: normalize, single fp16 store ----
    #pragma unroll
    for (int mf = 0; mf < 2; mf++) {
        const float inv0 = 1.0f / (lsum[2*mf]     + ATTN_EPS);
        const float inv1 = 1.0f / (lsum[2*mf + 1] + ATTN_EPS);
        const size_t base0 = (size_t)(b * SEQ + qstart + w * 32 + mf * 16 + gq) * INNER
                           + h * 64 + t4 * 2;
        const size_t base1 = base0 + (size_t)8 * INNER;
        #pragma unroll
        for (int nd = 0; nd < 8; nd++) {
            *(uint32_t*)(goh + base0 + nd * 8) = pack2(o[mf][nd][0] * inv0,
                                                       o[mf][nd][1] * inv0);
            *(uint32_t*)(goh + base1 + nd * 8) = pack2(o[mf][nd][2] * inv1,
                                                       o[mf][nd][3] * inv1);
        }
    }
}

// ---------------------------------------------------------------------------
// Launch
// ---------------------------------------------------------------------------
extern "C" void kernel_launch(void* const* d_in, const int* in_sizes, int n_in,
                              void* d_out, int out_size)
{
    const float* x   = (const float*)d_in[0];
    const float* Wq  = (const float*)d_in[1];
    const float* Wkv = (const float*)d_in[2];
    const float* Wo  = (const float*)d_in[3];
    const float* bo  = (const float*)d_in[4];
    float* out = (float*)d_out;

    __half *pxh, *pxl, *pw1, *pwo, *pqkvh, *pqkvl, *path;
    cudaGetSymbolAddress((void**)&pxh,   g_xh);
    cudaGetSymbolAddress((void**)&pxl,   g_xl);
    cudaGetSymbolAddress((void**)&pw1,   g_w1);
    cudaGetSymbolAddress((void**)&pwo,   g_wot);
    cudaGetSymbolAddress((void**)&pqkvh, g_qkvh);
    cudaGetSymbolAddress((void**)&pqkvl, g_qkvl);
    cudaGetSymbolAddress((void**)&path,  g_ath);

    cudaFuncSetAttribute(gemm_qkv,
                         cudaFuncAttributeMaxDynamicSharedMemorySize, GEMM2_SMEM);
    cudaFuncSetAttribute(gemm_out,
                         cudaFuncAttributeMaxDynamicSharedMemorySize, GEMM1_SMEM);
    cudaFuncSetAttribute(attn_mma,
                         cudaFuncAttributeMaxDynamicSharedMemorySize, AT_SMEM);

    // --- fused prep: x split + all three weight transposes, one launch ---
    prep_kernel<<<PREP_TOTAL_BLOCKS, 256>>>(x, pxh, pxl, Wq, Wkv, Wo, pw1, pwo);

    // --- merged projection: q|k (2-term, hi/lo) + v (1-term, hi) ---
    gemm_qkv<<<dim3(QKVW / 128, ROWS / 128), 256, GEMM2_SMEM>>>(
        pxh, pxl, pw1, pqkvh, pqkvl);

    // --- attention (S 2-term, PV 1-term, single fp16 out) ---
    attn_mma<<<dim3(SEQ / 128, BATCH * HEADS), 128, AT_SMEM>>>(
        pqkvh, pqkvl, path);

    // --- out = att @ Wo + bo (1-term) ---
    gemm_out<<<dim3(DMODEL / 128, ROWS / 128), 256, GEMM1_SMEM>>>(
        path, pwo, bo, out, DMODEL, INNER);
}

// round 14
// speedup vs baseline: 5.8257x; 1.1849x over previous
#include <cuda_runtime.h>
#include <cuda_fp16.h>
#include <math.h>
#include <stdint.h>

// ---------------------------------------------------------------------------
// Problem constants
// ---------------------------------------------------------------------------
#define BATCH   2
#define SEQ     2048
#define DMODEL  1024
#define HEADS   16
#define DHEAD   64
#define INNER   (HEADS * DHEAD)      // 1024
#define ROWS    (BATCH * SEQ)        // 4096
#define QKVW    (3 * INNER)          // 3072
#define ATTN_EPS 1e-8f

// ---------------------------------------------------------------------------
// Scratch (device globals)
// ---------------------------------------------------------------------------
__device__ __half g_xh  [ROWS * DMODEL];          // x fp16 (single)
__device__ __half g_w1  [QKVW * DMODEL];          // [Wq^T; Wkv^T] fp16
__device__ __half g_wot [DMODEL * INNER];         // Wo^T fp16
__device__ __half g_qkvh [ROWS * QKVW];           // fused q|k|v hi
__device__ __half g_qkvl [ROWS * QKVW];           // q|k lo (v region unused)
__device__ __half g_ath [ROWS * INNER];           // attention out (fp16)

// ---------------------------------------------------------------------------
// Helpers (base ISA only)
// ---------------------------------------------------------------------------
__device__ __forceinline__ uint32_t smem_u32(const void* p) {
    uint32_t a;
    asm("{ .reg .u64 t; cvta.to.shared.u64 t, %1; cvt.u32.u64 %0, t; }"
        : "=r"(a) : "l"(p));
    return a;
}

__device__ __forceinline__ void ldmatrix_x4(uint32_t& r0, uint32_t& r1,
                                            uint32_t& r2, uint32_t& r3,
                                            uint32_t addr) {
    asm volatile("ldmatrix.sync.aligned.m8n8.x4.shared.b16 {%0,%1,%2,%3}, [%4];"
                 : "=r"(r0), "=r"(r1), "=r"(r2), "=r"(r3) : "r"(addr));
}

__device__ __forceinline__ void ldmatrix_x4_trans(uint32_t& r0, uint32_t& r1,
                                                  uint32_t& r2, uint32_t& r3,
                                                  uint32_t addr) {
    asm volatile("ldmatrix.sync.aligned.m8n8.x4.trans.shared.b16 {%0,%1,%2,%3}, [%4];"
                 : "=r"(r0), "=r"(r1), "=r"(r2), "=r"(r3) : "r"(addr));
}

__device__ __forceinline__ void mma_f16(float* d, const uint32_t* a, const uint32_t* b) {
    asm volatile(
        "mma.sync.aligned.m16n8k16.row.col.f32.f16.f16.f32 "
        "{%0,%1,%2,%3}, {%4,%5,%6,%7}, {%8,%9}, {%0,%1,%2,%3};"
        : "+f"(d[0]), "+f"(d[1]), "+f"(d[2]), "+f"(d[3])
        : "r"(a[0]), "r"(a[1]), "r"(a[2]), "r"(a[3]), "r"(b[0]), "r"(b[1]));
}

__device__ __forceinline__ void cp_async16(uint32_t saddr, const void* gaddr) {
    asm volatile("cp.async.cg.shared.global [%0], [%1], 16;"
                 :: "r"(saddr), "l"(gaddr));
}
__device__ __forceinline__ void cp_commit() {
    asm volatile("cp.async.commit_group;" ::: "memory");
}
template <int N>
__device__ __forceinline__ void cp_wait() {
    asm volatile("cp.async.wait_group %0;" :: "n"(N) : "memory");
}

__device__ __forceinline__ uint32_t sw64(uint32_t byte) {
    return byte ^ ((byte >> 3) & 0x30);
}

__device__ __forceinline__ void pack_split(float a, float b, uint32_t& hi, uint32_t& lo) {
    __half ha = __float2half_rn(a), hb = __float2half_rn(b);
    float ra = a - __half2float(ha), rb = b - __half2float(hb);
    __half2 H; H.x = ha; H.y = hb;
    __half2 L; L.x = __float2half_rn(ra); L.y = __float2half_rn(rb);
    hi = *(uint32_t*)&H;
    lo = *(uint32_t*)&L;
}

__device__ __forceinline__ uint32_t pack2(float a, float b) {
    __half2 H = __floats2half2_rn(a, b);
    return *(uint32_t*)&H;
}

// ---------------------------------------------------------------------------
// Fused prep kernel: blocks [0,4096) convert x -> fp16 (single);
// blocks [4096,8192) transpose Wq / Wkv / Wo into fp16 [N,K].
// ---------------------------------------------------------------------------
#define PREP_SPLIT_BLOCKS 4096
#define PREP_TOTAL_BLOCKS 8192

__global__ __launch_bounds__(256)
void prep_kernel(const float* __restrict__ x,
                 __half* __restrict__ xh,
                 const float* __restrict__ Wq, const float* __restrict__ Wkv,
                 const float* __restrict__ Wo,
                 __half* __restrict__ w1, __half* __restrict__ wot)
{
    __shared__ float t[32][33];
    int bid = blockIdx.x;
    const int tid = threadIdx.x;

    if (bid < PREP_SPLIT_BLOCKS) {
        int i = bid * 256 + tid;
        float4 v = ((const float4*)x)[i];
        union { __half b[4]; uint2 u; } uh;
        uh.b[0] = __float2half_rn(v.x);
        uh.b[1] = __float2half_rn(v.y);
        uh.b[2] = __float2half_rn(v.z);
        uh.b[3] = __float2half_rn(v.w);
        ((uint2*)xh)[i] = uh.u;
        return;
    }

    bid -= PREP_SPLIT_BLOCKS;
    const float* W;
    __half* T;
    int K, N;
    if (bid < 1024)      { W = Wq;  T = w1;                              K = DMODEL; N = INNER; }
    else if (bid < 3072) { bid -= 1024; W = Wkv; T = w1 + (size_t)INNER * DMODEL; K = DMODEL; N = 2 * INNER; }
    else                 { bid -= 3072; W = Wo;  T = wot;                K = INNER;  N = DMODEL; }

    const int nbx = N / 32;
    const int bx = bid % nbx, by = bid / nbx;
    const int tx = tid & 31, ty = tid >> 5;

    int n  = bx * 32 + tx;
    int k0 = by * 32 + ty;
    #pragma unroll
    for (int i = 0; i < 32; i += 8)
        t[ty + i][tx] = W[(size_t)(k0 + i) * N + n];
    __syncthreads();
    int k  = by * 32 + tx;
    int n0 = bx * 32 + ty;
    #pragma unroll
    for (int i = 0; i < 32; i += 8)
        T[(size_t)(n0 + i) * K + k] = __float2half_rn(t[tx][ty + i]);
}

// ---------------------------------------------------------------------------
// HMMA GEMM core (1-term): C = Ah @ Bh^T, Bh [N,K] fp16.
// 128x128 CTA tile, 256 thr (2x4 warps, 64x32 each), BK=32, 3-stage cp.async.
// Stage = AH 8K + BH 8K = 16K; 3 stages = 48K -> 2 CTAs/SM.
// ---------------------------------------------------------------------------
#define STG1_BYTES  16384
#define OFF_BH1     8192
#define GEMM1_SMEM  (3 * STG1_BYTES)

struct GemmCtx {
    float acc[4][4][4];
    int wr, wc, lane;
};

__device__ __forceinline__ void gemm_core1(
    const __half* __restrict__ Ah, const __half* __restrict__ Bh,
    int K, int row0, int col0, GemmCtx& g)
{
    extern __shared__ char smraw[];
    const uint32_t sbase = smem_u32(smraw);

    const int tid  = threadIdx.x;
    const int wid  = tid >> 5;
    const int lane = tid & 31;
    g.wr = wid >> 2; g.wc = wid & 3; g.lane = lane;   // 2 x 4 warp grid

    const int nIter = K >> 5;
    const int lm_row = lane & 15;
    const int lm_koc = (lane >> 4) * 8;

    #pragma unroll
    for (int mf = 0; mf < 4; mf++)
        #pragma unroll
        for (int nf = 0; nf < 4; nf++)
            #pragma unroll
            for (int r = 0; r < 4; r++) g.acc[mf][nf][r] = 0.f;

    auto fill_stage = [&](int s, int kk0) {
        const uint32_t st = sbase + s * STG1_BYTES;
        #pragma unroll
        for (int it = 0; it < 2; it++) {
            int idx = tid + it * 256;
            int r = idx >> 2, c = idx & 3;
            uint32_t off = sw64((uint32_t)(r * 64 + c * 16));
            size_t ga = (size_t)(row0 + r) * K + kk0 + c * 8;
            cp_async16(st + off, Ah + ga);
        }
        #pragma unroll
        for (int it = 0; it < 2; it++) {
            int idx = tid + it * 256;
            int r = idx >> 2, c = idx & 3;
            uint32_t off = sw64((uint32_t)(r * 64 + c * 16));
            size_t gb = (size_t)(col0 + r) * K + kk0 + c * 8;
            cp_async16(st + OFF_BH1 + off, Bh + gb);
        }
    };

    fill_stage(0, 0);  cp_commit();
    fill_stage(1, 32); cp_commit();

    for (int kt = 0; kt < nIter; kt++) {
        const int s = kt % 3;
        const uint32_t st = sbase + s * STG1_BYTES;

        cp_wait<1>();
        __syncthreads();

        if (kt + 2 < nIter) fill_stage((kt + 2) % 3, (kt + 2) * 32);
        cp_commit();

        #pragma unroll
        for (int ks = 0; ks < 2; ks++) {
            const int colb = (ks * 16 + lm_koc) * 2;
            uint32_t ah[4][4];

            #pragma unroll
            for (int mf = 0; mf < 4; mf++) {
                int r = g.wr * 64 + mf * 16 + lm_row;
                uint32_t off = sw64((uint32_t)(r * 64 + colb));
                ldmatrix_x4(ah[mf][0], ah[mf][1], ah[mf][2], ah[mf][3], st + off);
            }
            #pragma unroll
            for (int np = 0; np < 2; np++) {
                int r = g.wc * 32 + np * 16 + lm_row;
                uint32_t off = sw64((uint32_t)(r * 64 + colb));
                uint32_t r0, r1, r2, r3;
                uint32_t bh0[2], bh1[2];
                ldmatrix_x4(r0, r1, r2, r3, st + OFF_BH1 + off);
                bh0[0] = r0; bh0[1] = r2; bh1[0] = r1; bh1[1] = r3;
                #pragma unroll
                for (int mf = 0; mf < 4; mf++) {
                    mma_f16(g.acc[mf][2*np],   ah[mf], bh0);
                    mma_f16(g.acc[mf][2*np+1], ah[mf], bh1);
                }
            }
        }
        __syncthreads();
    }
}

// ---------------------------------------------------------------------------
// Merged q|k|v projection (one launch, all 1-term A = x-hi):
//  cols [0,2048)  : hi/lo split out (accumulator split), q cols scaled 0.125
//  cols [2048,3072): hi out only (v)
// ---------------------------------------------------------------------------
__global__ __launch_bounds__(256, 2)
void gemm_qkv(const __half* __restrict__ Ah, const __half* __restrict__ W,
              __half* __restrict__ Oh, __half* __restrict__ Ol)
{
    const int row0 = blockIdx.y * 128;
    const int col0 = blockIdx.x * 128;

    GemmCtx g;
    gemm_core1(Ah, W, DMODEL, row0, col0, g);

    const int gq = g.lane >> 2;
    const int t4 = g.lane & 3;

    if (col0 < 2 * INNER) {
        #pragma unroll
        for (int mf = 0; mf < 4; mf++) {
            int r0g = row0 + g.wr * 64 + mf * 16 + gq;
            #pragma unroll
            for (int nf = 0; nf < 4; nf++) {
                int cg = col0 + g.wc * 32 + nf * 8 + t4 * 2;
                float sc = (cg < INNER) ? 0.125f : 1.0f;
                uint32_t h0, l0, h1, l1;
                pack_split(g.acc[mf][nf][0] * sc, g.acc[mf][nf][1] * sc, h0, l0);
                pack_split(g.acc[mf][nf][2] * sc, g.acc[mf][nf][3] * sc, h1, l1);
                *(uint32_t*)(Oh + (size_t)r0g * QKVW + cg)       = h0;
                *(uint32_t*)(Ol + (size_t)r0g * QKVW + cg)       = l0;
                *(uint32_t*)(Oh + (size_t)(r0g + 8) * QKVW + cg) = h1;
                *(uint32_t*)(Ol + (size_t)(r0g + 8) * QKVW + cg) = l1;
            }
        }
    } else {
        #pragma unroll
        for (int mf = 0; mf < 4; mf++) {
            int r0g = row0 + g.wr * 64 + mf * 16 + gq;
            #pragma unroll
            for (int nf = 0; nf < 4; nf++) {
                int cg = col0 + g.wc * 32 + nf * 8 + t4 * 2;
                *(uint32_t*)(Oh + (size_t)r0g * QKVW + cg)
                    = pack2(g.acc[mf][nf][0], g.acc[mf][nf][1]);
                *(uint32_t*)(Oh + (size_t)(r0g + 8) * QKVW + cg)
                    = pack2(g.acc[mf][nf][2], g.acc[mf][nf][3]);
            }
        }
    }
}

// fp32-output GEMM (+bias) — final projection, 1-term A
__global__ __launch_bounds__(256, 2)
void gemm_out(const __half* __restrict__ Ah, const __half* __restrict__ Bh,
              const float* __restrict__ bias, float* __restrict__ C,
              int N, int K)
{
    GemmCtx g;
    const int row0 = blockIdx.y * 128;
    const int col0 = blockIdx.x * 128;
    gemm_core1(Ah, Bh, K, row0, col0, g);

    const int gq = g.lane >> 2;
    const int t4 = g.lane & 3;
    #pragma unroll
    for (int mf = 0; mf < 4; mf++) {
        int r0g = row0 + g.wr * 64 + mf * 16 + gq;
        #pragma unroll
        for (int nf = 0; nf < 4; nf++) {
            int cg = col0 + g.wc * 32 + nf * 8 + t4 * 2;
            float bx = bias[cg], by = bias[cg + 1];
            float2 v0 = { g.acc[mf][nf][0] + bx, g.acc[mf][nf][1] + by };
            float2 v1 = { g.acc[mf][nf][2] + bx, g.acc[mf][nf][3] + by };
            *(float2*)(C + (size_t)r0g * N + cg)       = v0;
            *(float2*)(C + (size_t)(r0g + 8) * N + cg) = v1;
        }
    }
}

// ---------------------------------------------------------------------------
// HMMA flash attention (fp16): 4 warps x 32 q-rows (Br=128, Bc=64).
// S = 2-term ((qh+ql) x kh), PV = 1-term (P-hi x V).
// QH fragments hoisted across the KV loop; QL read per tile.
// Stage: KH 8K | VH 8K = 16K, double-buffered. 2 CTAs/SM. (unchanged)
// ---------------------------------------------------------------------------
#define AT_Q_BYTES   32768
#define AT_STG_BYTES 16384
#define AT_SMEM      (1024 + AT_Q_BYTES + 2 * AT_STG_BYTES)

__global__ __launch_bounds__(128, 2)
void attn_mma(const __half* __restrict__ qkvh,
              const __half* __restrict__ qkvl,
              __half* __restrict__ goh)
{
    extern __shared__ char smraw[];
    const uint32_t b0a = smem_u32(smraw);
    const uint32_t sb = (b0a + 1023u) & ~1023u;

    const int tid = threadIdx.x;
    const int w = tid >> 5, lane = tid & 31;
    const int gq = lane >> 2, t4 = lane & 3;
    const int lm_row = lane & 15, lm_koc = (lane >> 4) * 8;
    const int vt = lane >> 3, vrl = lane & 7;
    const int b = blockIdx.y >> 4, h = blockIdx.y & 15;
    const int qt = gridDim.x - 1 - blockIdx.x;
    const int qstart = qt * 128;
    const int igmax = qstart + w * 32 + 31;

    const uint32_t QH = sb, QL = sb + 16384;
    const uint32_t ST0 = sb + AT_Q_BYTES;

    const size_t rowbase = (size_t)(b * SEQ) * QKVW + h * 64;

    // ---- Q fill (own cp.async group) ----
    #pragma unroll
    for (int it = 0; it < 16; it++) {
        int idx = tid + it * 128;
        int bs = idx >> 10, r = (idx >> 3) & 127, c = idx & 7;
        const __half* src = (bs ? qkvl : qkvh)
            + rowbase + (size_t)(qstart + r) * QKVW + c * 8;
        cp_async16((bs ? QL : QH) + (uint32_t)(r * 128 + ((c * 16) ^ ((r & 7) << 4))), src);
    }
    cp_commit();

    // ---- K/V stage fill: KH + VH ----
    auto fill_kv = [&](int s, int jstart) {
        const uint32_t st = ST0 + s * AT_STG_BYTES;
        #pragma unroll
        for (int it = 0; it < 8; it++) {
            int idx = tid + it * 128;            // 0..1023
            int tile = idx >> 9;                 // 0:KH 1:VH
            int r = (idx >> 3) & 63, c = idx & 7;
            int col = (tile ? 2048 : 1024) + c * 8;
            const __half* src = qkvh + rowbase + (size_t)(jstart + r) * QKVW + col;
            cp_async16(st + (uint32_t)(tile * 8192 + r * 128 + ((c * 16) ^ ((r & 7) << 4))), src);
        }
    };

    fill_kv(0, 0);
    cp_commit();

    // ---- wait for Q (KV0 may stay pending), hoist QH frags ----
    cp_wait<1>();
    __syncthreads();

    uint32_t qa[2][4][4];                        // [mf][kd][reg] Q-hi
    #pragma unroll
    for (int kd = 0; kd < 4; kd++) {
        const int cb = (kd * 16 + lm_koc) * 2;
        #pragma unroll
        for (int mf = 0; mf < 2; mf++) {
            int r = w * 32 + mf * 16 + lm_row;
            uint32_t off = (uint32_t)(r * 128 + (cb ^ ((r & 7) << 4)));
            ldmatrix_x4(qa[mf][kd][0], qa[mf][kd][1], qa[mf][kd][2], qa[mf][kd][3],
                        QH + off);
        }
    }

    float o[2][8][4];
    float m[4] = { -INFINITY, -INFINITY, -INFINITY, -INFINITY };
    float lsum[4] = { 0.f, 0.f, 0.f, 0.f };
    #pragma unroll
    for (int mf = 0; mf < 2; mf++)
        #pragma unroll
        for (int nd = 0; nd < 8; nd++)
            #pragma unroll
            for (int r = 0; r < 4; r++) o[mf][nd][r] = 0.f;

    const int nT = 2 * qt + 2;
    for (int jt = 0; jt < nT; jt++) {
        const int jstart = jt * 64;
        const uint32_t st = ST0 + (jt & 1) * AT_STG_BYTES;
        const uint32_t KH = st, VH = st + 8192;

        if (jt > 0) __syncthreads();
        if (jt + 1 < nT) {
            fill_kv((jt + 1) & 1, jstart + 64);
            cp_commit();
            cp_wait<1>();
        } else {
            cp_wait<0>();
        }
        __syncthreads();

        // ---- S = Q @ K^T (2-term: qh*kh + ql*kh) ----
        float s[2][8][4];
        #pragma unroll
        for (int mf = 0; mf < 2; mf++)
            #pragma unroll
            for (int nj = 0; nj < 8; nj++)
                #pragma unroll
                for (int r = 0; r < 4; r++) s[mf][nj][r] = 0.f;

        #pragma unroll
        for (int kd = 0; kd < 4; kd++) {
            const int cb = (kd * 16 + lm_koc) * 2;
            uint32_t qb[2][4];
            #pragma unroll
            for (int mf = 0; mf < 2; mf++) {
                int r = w * 32 + mf * 16 + lm_row;
                uint32_t off = (uint32_t)(r * 128 + (cb ^ ((r & 7) << 4)));
                ldmatrix_x4(qb[mf][0], qb[mf][1], qb[mf][2], qb[mf][3], QL + off);
            }
            #pragma unroll
            for (int jp = 0; jp < 4; jp++) {
                if (jstart + jp * 16 > igmax) continue;
                int r = jp * 16 + lm_row;
                uint32_t off = (uint32_t)(r * 128 + (cb ^ ((r & 7) << 4)));
                uint32_t r0, r1, r2, r3;
                uint32_t bh0[2], bh1[2];
                ldmatrix_x4(r0, r1, r2, r3, KH + off);
                bh0[0] = r0; bh0[1] = r2; bh1[0] = r1; bh1[1] = r3;
                #pragma unroll
                for (int mf = 0; mf < 2; mf++) {
                    mma_f16(s[mf][2*jp],   qa[mf][kd], bh0);
                    mma_f16(s[mf][2*jp],   qb[mf],     bh0);
                    mma_f16(s[mf][2*jp+1], qa[mf][kd], bh1);
                    mma_f16(s[mf][2*jp+1], qb[mf],     bh1);
                }
            }
        }

        // ---- online softmax ----
        float alpha[4];
        #pragma unroll
        for (int mf = 0; mf < 2; mf++) {
            #pragma unroll
            for (int hh = 0; hh < 2; hh++) {
                const int hr = 2 * mf + hh;
                float mx = -INFINITY;
                #pragma unroll
                for (int nj = 0; nj < 8; nj++)
                    mx = fmaxf(mx, fmaxf(s[mf][nj][2*hh], s[mf][nj][2*hh+1]));
                mx = fmaxf(mx, __shfl_xor_sync(0xffffffffu, mx, 1));
                mx = fmaxf(mx, __shfl_xor_sync(0xffffffffu, mx, 2));
                float mn = fmaxf(m[hr], mx);
                alpha[hr] = __expf(m[hr] - mn);
                m[hr] = mn;
                const int ig = qstart + w * 32 + mf * 16 + hh * 8 + gq;
                float rs = 0.f;
                #pragma unroll
                for (int nj = 0; nj < 8; nj++) {
                    int jg = jstart + nj * 8 + t4 * 2;
                    float p0 = (jg     <= ig) ? __expf(s[mf][nj][2*hh]   - mn) : 0.f;
                    float p1 = (jg + 1 <= ig) ? __expf(s[mf][nj][2*hh+1] - mn) : 0.f;
                    s[mf][nj][2*hh] = p0; s[mf][nj][2*hh+1] = p1;
                    rs += p0 + p1;
                }
                rs += __shfl_xor_sync(0xffffffffu, rs, 1);
                rs += __shfl_xor_sync(0xffffffffu, rs, 2);
                lsum[hr] = lsum[hr] * alpha[hr] + rs;
            }
            #pragma unroll
            for (int nd = 0; nd < 8; nd++) {
                o[mf][nd][0] *= alpha[2*mf];     o[mf][nd][1] *= alpha[2*mf];
                o[mf][nd][2] *= alpha[2*mf + 1]; o[mf][nd][3] *= alpha[2*mf + 1];
            }
        }

        // ---- O += P @ V (1-term: P-hi x V) ----
        #pragma unroll
        for (int kj = 0; kj < 4; kj++) {
            if (jstart + kj * 16 > igmax) continue;
            uint32_t ph[2][4];
            #pragma unroll
            for (int mf = 0; mf < 2; mf++) {
                ph[mf][0] = pack2(s[mf][2*kj][0],   s[mf][2*kj][1]);
                ph[mf][1] = pack2(s[mf][2*kj][2],   s[mf][2*kj][3]);
                ph[mf][2] = pack2(s[mf][2*kj+1][0], s[mf][2*kj+1][1]);
                ph[mf][3] = pack2(s[mf][2*kj+1][2], s[mf][2*kj+1][3]);
            }
            const int j = kj * 16 + (vt & 1) * 8 + vrl;
            const uint32_t jsw = (uint32_t)(j * 128);
            const int ch = (vt >> 1);
            #pragma unroll
            for (int ndp = 0; ndp < 4; ndp++) {
                int c = ndp * 2 + ch;
                uint32_t off = jsw + (uint32_t)((c * 16) ^ ((j & 7) << 4));
                uint32_t r0, r1, r2, r3;
                uint32_t bh0[2], bh1[2];
                ldmatrix_x4_trans(r0, r1, r2, r3, VH + off);
                bh0[0] = r0; bh0[1] = r1; bh1[0] = r2; bh1[1] = r3;
                #pragma unroll
                for (int mf = 0; mf < 2; mf++) {
                    mma_f16(o[mf][2*ndp],   ph[mf], bh0);
                    mma_f16(o[mf][2*ndp+1], ph[mf], bh1);
                }
            }
        }
    }

    // ---- epilogue: normalize, single fp16 store ----
    #pragma unroll
    for (int mf = 0; mf < 2; mf++) {
        const float inv0 = 1.0f / (lsum[2*mf]     + ATTN_EPS);
        const float inv1 = 1.0f / (lsum[2*mf + 1] + ATTN_EPS);
        const size_t base0 = (size_t)(b * SEQ + qstart + w * 32 + mf * 16 + gq) * INNER
                           + h * 64 + t4 * 2;
        const size_t base1 = base0 + (size_t)8 * INNER;
        #pragma unroll
        for (int nd = 0; nd < 8; nd++) {
            *(uint32_t*)(goh + base0 + nd * 8) = pack2(o[mf][nd][0] * inv0,
                                                       o[mf][nd][1] * inv0);
            *(uint32_t*)(goh + base1 + nd * 8) = pack2(o[mf][nd][2] * inv1,
                                                       o[mf][nd][3] * inv1);
        }
    }
}

// ---------------------------------------------------------------------------
// Launch
// ---------------------------------------------------------------------------
extern "C" void kernel_launch(void* const* d_in, const int* in_sizes, int n_in,
                              void* d_out, int out_size)
{
    const float* x   = (const float*)d_in[0];
    const float* Wq  = (const float*)d_in[1];
    const float* Wkv = (const float*)d_in[2];
    const float* Wo  = (const float*)d_in[3];
    const float* bo  = (const float*)d_in[4];
    float* out = (float*)d_out;

    __half *pxh, *pw1, *pwo, *pqkvh, *pqkvl, *path;
    cudaGetSymbolAddress((void**)&pxh,   g_xh);
    cudaGetSymbolAddress((void**)&pw1,   g_w1);
    cudaGetSymbolAddress((void**)&pwo,   g_wot);
    cudaGetSymbolAddress((void**)&pqkvh, g_qkvh);
    cudaGetSymbolAddress((void**)&pqkvl, g_qkvl);
    cudaGetSymbolAddress((void**)&path,  g_ath);

    cudaFuncSetAttribute(gemm_qkv,
                         cudaFuncAttributeMaxDynamicSharedMemorySize, GEMM1_SMEM);
    cudaFuncSetAttribute(gemm_out,
                         cudaFuncAttributeMaxDynamicSharedMemorySize, GEMM1_SMEM);
    cudaFuncSetAttribute(attn_mma,
                         cudaFuncAttributeMaxDynamicSharedMemorySize, AT_SMEM);

    // --- fused prep: x -> fp16 + all three weight transposes, one launch ---
    prep_kernel<<<PREP_TOTAL_BLOCKS, 256>>>(x, pxh, Wq, Wkv, Wo, pw1, pwo);

    // --- merged projection: q|k|v, 1-term A; q/k outputs split hi/lo ---
    gemm_qkv<<<dim3(QKVW / 128, ROWS / 128), 256, GEMM1_SMEM>>>(
        pxh, pw1, pqkvh, pqkvl);

    // --- attention (S 2-term, PV 1-term, single fp16 out) ---
    attn_mma<<<dim3(SEQ / 128, BATCH * HEADS), 128, AT_SMEM>>>(
        pqkvh, pqkvl, path);

    // --- out = att @ Wo + bo (1-term) ---
    gemm_out<<<dim3(DMODEL / 128, ROWS / 128), 256, GEMM1_SMEM>>>(
        path, pwo, bo, out, DMODEL, INNER);
}

// round 15
// speedup vs baseline: 6.6134x; 1.1352x over previous
#include <cuda_runtime.h>
#include <cuda_fp16.h>
#include <math.h>
#include <stdint.h>

// ---------------------------------------------------------------------------
// Problem constants
// ---------------------------------------------------------------------------
#define BATCH   2
#define SEQ     2048
#define DMODEL  1024
#define HEADS   16
#define DHEAD   64
#define INNER   (HEADS * DHEAD)      // 1024
#define ROWS    (BATCH * SEQ)        // 4096
#define QKVW    (3 * INNER)          // 3072
#define ATTN_EPS 1e-8f

// ---------------------------------------------------------------------------
// Scratch (device globals)
// ---------------------------------------------------------------------------
__device__ __half g_xh  [ROWS * DMODEL];          // x fp16
__device__ __half g_w1  [QKVW * DMODEL];          // [Wq^T; Wkv^T] fp16
__device__ __half g_wot [DMODEL * INNER];         // Wo^T fp16
__device__ __half g_qkv [ROWS * QKVW];            // fused q|k|v fp16
__device__ __half g_ath [ROWS * INNER];           // attention out fp16

// ---------------------------------------------------------------------------
// Helpers (base ISA only)
// ---------------------------------------------------------------------------
__device__ __forceinline__ uint32_t smem_u32(const void* p) {
    uint32_t a;
    asm("{ .reg .u64 t; cvta.to.shared.u64 t, %1; cvt.u32.u64 %0, t; }"
        : "=r"(a) : "l"(p));
    return a;
}

__device__ __forceinline__ void ldmatrix_x4(uint32_t& r0, uint32_t& r1,
                                            uint32_t& r2, uint32_t& r3,
                                            uint32_t addr) {
    asm volatile("ldmatrix.sync.aligned.m8n8.x4.shared.b16 {%0,%1,%2,%3}, [%4];"
                 : "=r"(r0), "=r"(r1), "=r"(r2), "=r"(r3) : "r"(addr));
}

__device__ __forceinline__ void ldmatrix_x4_trans(uint32_t& r0, uint32_t& r1,
                                                  uint32_t& r2, uint32_t& r3,
                                                  uint32_t addr) {
    asm volatile("ldmatrix.sync.aligned.m8n8.x4.trans.shared.b16 {%0,%1,%2,%3}, [%4];"
                 : "=r"(r0), "=r"(r1), "=r"(r2), "=r"(r3) : "r"(addr));
}

__device__ __forceinline__ void mma_f16(float* d, const uint32_t* a, const uint32_t* b) {
    asm volatile(
        "mma.sync.aligned.m16n8k16.row.col.f32.f16.f16.f32 "
        "{%0,%1,%2,%3}, {%4,%5,%6,%7}, {%8,%9}, {%0,%1,%2,%3};"
        : "+f"(d[0]), "+f"(d[1]), "+f"(d[2]), "+f"(d[3])
        : "r"(a[0]), "r"(a[1]), "r"(a[2]), "r"(a[3]), "r"(b[0]), "r"(b[1]));
}

__device__ __forceinline__ void cp_async16(uint32_t saddr, const void* gaddr) {
    asm volatile("cp.async.cg.shared.global [%0], [%1], 16;"
                 :: "r"(saddr), "l"(gaddr));
}
__device__ __forceinline__ void cp_commit() {
    asm volatile("cp.async.commit_group;" ::: "memory");
}
template <int N>
__device__ __forceinline__ void cp_wait() {
    asm volatile("cp.async.wait_group %0;" :: "n"(N) : "memory");
}

__device__ __forceinline__ uint32_t sw64(uint32_t byte) {
    return byte ^ ((byte >> 3) & 0x30);
}

__device__ __forceinline__ uint32_t pack2(float a, float b) {
    __half2 H = __floats2half2_rn(a, b);
    return *(uint32_t*)&H;
}

// ---------------------------------------------------------------------------
// Fused prep kernel: blocks [0,4096) convert x -> fp16;
// blocks [4096,8192) transpose Wq / Wkv / Wo into fp16 [N,K].
// ---------------------------------------------------------------------------
#define PREP_SPLIT_BLOCKS 4096
#define PREP_TOTAL_BLOCKS 8192

__global__ __launch_bounds__(256)
void prep_kernel(const float* __restrict__ x,
                 __half* __restrict__ xh,
                 const float* __restrict__ Wq, const float* __restrict__ Wkv,
                 const float* __restrict__ Wo,
                 __half* __restrict__ w1, __half* __restrict__ wot)
{
    __shared__ float t[32][33];
    int bid = blockIdx.x;
    const int tid = threadIdx.x;

    if (bid < PREP_SPLIT_BLOCKS) {
        int i = bid * 256 + tid;
        float4 v = ((const float4*)x)[i];
        union { __half b[4]; uint2 u; } uh;
        uh.b[0] = __float2half_rn(v.x);
        uh.b[1] = __float2half_rn(v.y);
        uh.b[2] = __float2half_rn(v.z);
        uh.b[3] = __float2half_rn(v.w);
        ((uint2*)xh)[i] = uh.u;
        return;
    }

    bid -= PREP_SPLIT_BLOCKS;
    const float* W;
    __half* T;
    int K, N;
    if (bid < 1024)      { W = Wq;  T = w1;                              K = DMODEL; N = INNER; }
    else if (bid < 3072) { bid -= 1024; W = Wkv; T = w1 + (size_t)INNER * DMODEL; K = DMODEL; N = 2 * INNER; }
    else                 { bid -= 3072; W = Wo;  T = wot;                K = INNER;  N = DMODEL; }

    const int nbx = N / 32;
    const int bx = bid % nbx, by = bid / nbx;
    const int tx = tid & 31, ty = tid >> 5;

    int n  = bx * 32 + tx;
    int k0 = by * 32 + ty;
    #pragma unroll
    for (int i = 0; i < 32; i += 8)
        t[ty + i][tx] = W[(size_t)(k0 + i) * N + n];
    __syncthreads();
    int k  = by * 32 + tx;
    int n0 = bx * 32 + ty;
    #pragma unroll
    for (int i = 0; i < 32; i += 8)
        T[(size_t)(n0 + i) * K + k] = __float2half_rn(t[tx][ty + i]);
}

// ---------------------------------------------------------------------------
// HMMA GEMM core (1-term): C = Ah @ Bh^T, Bh [N,K] fp16.
// 128x128 CTA tile, 256 thr (2x4 warps, 64x32 each), BK=32, 3-stage cp.async.
// Stage = AH 8K + BH 8K = 16K; 3 stages = 48K -> 2 CTAs/SM.
// ---------------------------------------------------------------------------
#define STG1_BYTES  16384
#define OFF_BH1     8192
#define GEMM1_SMEM  (3 * STG1_BYTES)

struct GemmCtx {
    float acc[4][4][4];
    int wr, wc, lane;
};

__device__ __forceinline__ void gemm_core1(
    const __half* __restrict__ Ah, const __half* __restrict__ Bh,
    int K, int row0, int col0, GemmCtx& g)
{
    extern __shared__ char smraw[];
    const uint32_t sbase = smem_u32(smraw);

    const int tid  = threadIdx.x;
    const int wid  = tid >> 5;
    const int lane = tid & 31;
    g.wr = wid >> 2; g.wc = wid & 3; g.lane = lane;   // 2 x 4 warp grid

    const int nIter = K >> 5;
    const int lm_row = lane & 15;
    const int lm_koc = (lane >> 4) * 8;

    #pragma unroll
    for (int mf = 0; mf < 4; mf++)
        #pragma unroll
        for (int nf = 0; nf < 4; nf++)
            #pragma unroll
            for (int r = 0; r < 4; r++) g.acc[mf][nf][r] = 0.f;

    auto fill_stage = [&](int s, int kk0) {
        const uint32_t st = sbase + s * STG1_BYTES;
        #pragma unroll
        for (int it = 0; it < 2; it++) {
            int idx = tid + it * 256;
            int r = idx >> 2, c = idx & 3;
            uint32_t off = sw64((uint32_t)(r * 64 + c * 16));
            size_t ga = (size_t)(row0 + r) * K + kk0 + c * 8;
            cp_async16(st + off, Ah + ga);
        }
        #pragma unroll
        for (int it = 0; it < 2; it++) {
            int idx = tid + it * 256;
            int r = idx >> 2, c = idx & 3;
            uint32_t off = sw64((uint32_t)(r * 64 + c * 16));
            size_t gb = (size_t)(col0 + r) * K + kk0 + c * 8;
            cp_async16(st + OFF_BH1 + off, Bh + gb);
        }
    };

    fill_stage(0, 0);  cp_commit();
    fill_stage(1, 32); cp_commit();

    for (int kt = 0; kt < nIter; kt++) {
        const int s = kt % 3;
        const uint32_t st = sbase + s * STG1_BYTES;

        cp_wait<1>();
        __syncthreads();

        if (kt + 2 < nIter) fill_stage((kt + 2) % 3, (kt + 2) * 32);
        cp_commit();

        #pragma unroll
        for (int ks = 0; ks < 2; ks++) {
            const int colb = (ks * 16 + lm_koc) * 2;
            uint32_t ah[4][4];

            #pragma unroll
            for (int mf = 0; mf < 4; mf++) {
                int r = g.wr * 64 + mf * 16 + lm_row;
                uint32_t off = sw64((uint32_t)(r * 64 + colb));
                ldmatrix_x4(ah[mf][0], ah[mf][1], ah[mf][2], ah[mf][3], st + off);
            }
            #pragma unroll
            for (int np = 0; np < 2; np++) {
                int r = g.wc * 32 + np * 16 + lm_row;
                uint32_t off = sw64((uint32_t)(r * 64 + colb));
                uint32_t r0, r1, r2, r3;
                uint32_t bh0[2], bh1[2];
                ldmatrix_x4(r0, r1, r2, r3, st + OFF_BH1 + off);
                bh0[0] = r0; bh0[1] = r2; bh1[0] = r1; bh1[1] = r3;
                #pragma unroll
                for (int mf = 0; mf < 4; mf++) {
                    mma_f16(g.acc[mf][2*np],   ah[mf], bh0);
                    mma_f16(g.acc[mf][2*np+1], ah[mf], bh1);
                }
            }
        }
        __syncthreads();
    }
}

// ---------------------------------------------------------------------------
// Merged q|k|v projection (one launch, 1-term, fp16 out; q cols scaled 0.125)
// ---------------------------------------------------------------------------
__global__ __launch_bounds__(256, 2)
void gemm_qkv(const __half* __restrict__ Ah, const __half* __restrict__ W,
              __half* __restrict__ O)
{
    const int row0 = blockIdx.y * 128;
    const int col0 = blockIdx.x * 128;

    GemmCtx g;
    gemm_core1(Ah, W, DMODEL, row0, col0, g);

    const int gq = g.lane >> 2;
    const int t4 = g.lane & 3;
    const float sc = (col0 < INNER) ? 0.125f : 1.0f;   // q tiles never straddle
    #pragma unroll
    for (int mf = 0; mf < 4; mf++) {
        int r0g = row0 + g.wr * 64 + mf * 16 + gq;
        #pragma unroll
        for (int nf = 0; nf < 4; nf++) {
            int cg = col0 + g.wc * 32 + nf * 8 + t4 * 2;
            *(uint32_t*)(O + (size_t)r0g * QKVW + cg)
                = pack2(g.acc[mf][nf][0] * sc, g.acc[mf][nf][1] * sc);
            *(uint32_t*)(O + (size_t)(r0g + 8) * QKVW + cg)
                = pack2(g.acc[mf][nf][2] * sc, g.acc[mf][nf][3] * sc);
        }
    }
}

// fp32-output GEMM (+bias) — final projection, 1-term A
__global__ __launch_bounds__(256, 2)
void gemm_out(const __half* __restrict__ Ah, const __half* __restrict__ Bh,
              const float* __restrict__ bias, float* __restrict__ C,
              int N, int K)
{
    GemmCtx g;
    const int row0 = blockIdx.y * 128;
    const int col0 = blockIdx.x * 128;
    gemm_core1(Ah, Bh, K, row0, col0, g);

    const int gq = g.lane >> 2;
    const int t4 = g.lane & 3;
    #pragma unroll
    for (int mf = 0; mf < 4; mf++) {
        int r0g = row0 + g.wr * 64 + mf * 16 + gq;
        #pragma unroll
        for (int nf = 0; nf < 4; nf++) {
            int cg = col0 + g.wc * 32 + nf * 8 + t4 * 2;
            float bx = bias[cg], by = bias[cg + 1];
            float2 v0 = { g.acc[mf][nf][0] + bx, g.acc[mf][nf][1] + by };
            float2 v1 = { g.acc[mf][nf][2] + bx, g.acc[mf][nf][3] + by };
            *(float2*)(C + (size_t)r0g * N + cg)       = v0;
            *(float2*)(C + (size_t)(r0g + 8) * N + cg) = v1;
        }
    }
}

// ---------------------------------------------------------------------------
// HMMA flash attention (fp16): 4 warps x 32 q-rows (Br=128, Bc=64).
// S = 1-term (q x k), PV = 1-term (P x V); fp32 accumulators throughout.
// Q fragments hoisted into registers across the whole KV loop.
// Stage: KH 8K | VH 8K = 16K, double-buffered. Smem 50K -> 2 CTAs/SM.
// ---------------------------------------------------------------------------
#define AT_Q_BYTES   16384
#define AT_STG_BYTES 16384
#define AT_SMEM      (1024 + AT_Q_BYTES + 2 * AT_STG_BYTES)

__global__ __launch_bounds__(128, 2)
void attn_mma(const __half* __restrict__ qkv, __half* __restrict__ goh)
{
    extern __shared__ char smraw[];
    const uint32_t b0a = smem_u32(smraw);
    const uint32_t sb = (b0a + 1023u) & ~1023u;

    const int tid = threadIdx.x;
    const int w = tid >> 5, lane = tid & 31;
    const int gq = lane >> 2, t4 = lane & 3;
    const int lm_row = lane & 15, lm_koc = (lane >> 4) * 8;
    const int vt = lane >> 3, vrl = lane & 7;
    const int b = blockIdx.y >> 4, h = blockIdx.y & 15;
    const int qt = gridDim.x - 1 - blockIdx.x;
    const int qstart = qt * 128;
    const int igmax = qstart + w * 32 + 31;

    const uint32_t QH = sb;
    const uint32_t ST0 = sb + AT_Q_BYTES;

    const size_t rowbase = (size_t)(b * SEQ) * QKVW + h * 64;

    // ---- Q fill (own cp.async group) ----
    #pragma unroll
    for (int it = 0; it < 8; it++) {
        int idx = tid + it * 128;                // 0..1023
        int r = idx >> 3, c = idx & 7;
        const __half* src = qkv + rowbase + (size_t)(qstart + r) * QKVW + c * 8;
        cp_async16(QH + (uint32_t)(r * 128 + ((c * 16) ^ ((r & 7) << 4))), src);
    }
    cp_commit();

    // ---- K/V stage fill: KH + VH ----
    auto fill_kv = [&](int s, int jstart) {
        const uint32_t st = ST0 + s * AT_STG_BYTES;
        #pragma unroll
        for (int it = 0; it < 8; it++) {
            int idx = tid + it * 128;            // 0..1023
            int tile = idx >> 9;                 // 0:KH 1:VH
            int r = (idx >> 3) & 63, c = idx & 7;
            int col = (tile ? 2048 : 1024) + c * 8;
            const __half* src = qkv + rowbase + (size_t)(jstart + r) * QKVW + col;
            cp_async16(st + (uint32_t)(tile * 8192 + r * 128 + ((c * 16) ^ ((r & 7) << 4))), src);
        }
    };

    fill_kv(0, 0);
    cp_commit();

    // ---- wait for Q (KV0 may stay pending), hoist Q frags ----
    cp_wait<1>();
    __syncthreads();

    uint32_t qa[2][4][4];                        // [mf][kd][reg]
    #pragma unroll
    for (int kd = 0; kd < 4; kd++) {
        const int cb = (kd * 16 + lm_koc) * 2;
        #pragma unroll
        for (int mf = 0; mf < 2; mf++) {
            int r = w * 32 + mf * 16 + lm_row;
            uint32_t off = (uint32_t)(r * 128 + (cb ^ ((r & 7) << 4)));
            ldmatrix_x4(qa[mf][kd][0], qa[mf][kd][1], qa[mf][kd][2], qa[mf][kd][3],
                        QH + off);
        }
    }

    float o[2][8][4];
    float m[4] = { -INFINITY, -INFINITY, -INFINITY, -INFINITY };
    float lsum[4] = { 0.f, 0.f, 0.f, 0.f };
    #pragma unroll
    for (int mf = 0; mf < 2; mf++)
        #pragma unroll
        for (int nd = 0; nd < 8; nd++)
            #pragma unroll
            for (int r = 0; r < 4; r++) o[mf][nd][r] = 0.f;

    const int nT = 2 * qt + 2;
    for (int jt = 0; jt < nT; jt++) {
        const int jstart = jt * 64;
        const uint32_t st = ST0 + (jt & 1) * AT_STG_BYTES;
        const uint32_t KH = st, VH = st + 8192;

        if (jt > 0) __syncthreads();
        if (jt + 1 < nT) {
            fill_kv((jt + 1) & 1, jstart + 64);
            cp_commit();
            cp_wait<1>();
        } else {
            cp_wait<0>();
        }
        __syncthreads();

        // ---- S = Q @ K^T (1-term) ----
        float s[2][8][4];
        #pragma unroll
        for (int mf = 0; mf < 2; mf++)
            #pragma unroll
            for (int nj = 0; nj < 8; nj++)
                #pragma unroll
                for (int r = 0; r < 4; r++) s[mf][nj][r] = 0.f;

        #pragma unroll
        for (int kd = 0; kd < 4; kd++) {
            const int cb = (kd * 16 + lm_koc) * 2;
            #pragma unroll
            for (int jp = 0; jp < 4; jp++) {
                if (jstart + jp * 16 > igmax) continue;
                int r = jp * 16 + lm_row;
                uint32_t off = (uint32_t)(r * 128 + (cb ^ ((r & 7) << 4)));
                uint32_t r0, r1, r2, r3;
                uint32_t bh0[2], bh1[2];
                ldmatrix_x4(r0, r1, r2, r3, KH + off);
                bh0[0] = r0; bh0[1] = r2; bh1[0] = r1; bh1[1] = r3;
                #pragma unroll
                for (int mf = 0; mf < 2; mf++) {
                    mma_f16(s[mf][2*jp],   qa[mf][kd], bh0);
                    mma_f16(s[mf][2*jp+1], qa[mf][kd], bh1);
                }
            }
        }

        // ---- online softmax ----
        float alpha[4];
        #pragma unroll
        for (int mf = 0; mf < 2; mf++) {
            #pragma unroll
            for (int hh = 0; hh < 2; hh++) {
                const int hr = 2 * mf + hh;
                float mx = -INFINITY;
                #pragma unroll
                for (int nj = 0; nj < 8; nj++)
                    mx = fmaxf(mx, fmaxf(s[mf][nj][2*hh], s[mf][nj][2*hh+1]));
                mx = fmaxf(mx, __shfl_xor_sync(0xffffffffu, mx, 1));
                mx = fmaxf(mx, __shfl_xor_sync(0xffffffffu, mx, 2));
                float mn = fmaxf(m[hr], mx);
                alpha[hr] = __expf(m[hr] - mn);
                m[hr] = mn;
                const int ig = qstart + w * 32 + mf * 16 + hh * 8 + gq;
                float rs = 0.f;
                #pragma unroll
                for (int nj = 0; nj < 8; nj++) {
                    int jg = jstart + nj * 8 + t4 * 2;
                    float p0 = (jg     <= ig) ? __expf(s[mf][nj][2*hh]   - mn) : 0.f;
                    float p1 = (jg + 1 <= ig) ? __expf(s[mf][nj][2*hh+1] - mn) : 0.f;
                    s[mf][nj][2*hh] = p0; s[mf][nj][2*hh+1] = p1;
                    rs += p0 + p1;
                }
                rs += __shfl_xor_sync(0xffffffffu, rs, 1);
                rs += __shfl_xor_sync(0xffffffffu, rs, 2);
                lsum[hr] = lsum[hr] * alpha[hr] + rs;
            }
            #pragma unroll
            for (int nd = 0; nd < 8; nd++) {
                o[mf][nd][0] *= alpha[2*mf];     o[mf][nd][1] *= alpha[2*mf];
                o[mf][nd][2] *= alpha[2*mf + 1]; o[mf][nd][3] *= alpha[2*mf + 1];
            }
        }

        // ---- O += P @ V (1-term) ----
        #pragma unroll
        for (int kj = 0; kj < 4; kj++) {
            if (jstart + kj * 16 > igmax) continue;
            uint32_t ph[2][4];
            #pragma unroll
            for (int mf = 0; mf < 2; mf++) {
                ph[mf][0] = pack2(s[mf][2*kj][0],   s[mf][2*kj][1]);
                ph[mf][1] = pack2(s[mf][2*kj][2],   s[mf][2*kj][3]);
                ph[mf][2] = pack2(s[mf][2*kj+1][0], s[mf][2*kj+1][1]);
                ph[mf][3] = pack2(s[mf][2*kj+1][2], s[mf][2*kj+1][3]);
            }
            const int j = kj * 16 + (vt & 1) * 8 + vrl;
            const uint32_t jsw = (uint32_t)(j * 128);
            const int ch = (vt >> 1);
            #pragma unroll
            for (int ndp = 0; ndp < 4; ndp++) {
                int c = ndp * 2 + ch;
                uint32_t off = jsw + (uint32_t)((c * 16) ^ ((j & 7) << 4));
                uint32_t r0, r1, r2, r3;
                uint32_t bh0[2], bh1[2];
                ldmatrix_x4_trans(r0, r1, r2, r3, VH + off);
                bh0[0] = r0; bh0[1] = r1; bh1[0] = r2; bh1[1] = r3;
                #pragma unroll
                for (int mf = 0; mf < 2; mf++) {
                    mma_f16(o[mf][2*ndp],   ph[mf], bh0);
                    mma_f16(o[mf][2*ndp+1], ph[mf], bh1);
                }
            }
        }
    }

    // ---- epilogue: normalize, fp16 store ----
    #pragma unroll
    for (int mf = 0; mf < 2; mf++) {
        const float inv0 = 1.0f / (lsum[2*mf]     + ATTN_EPS);
        const float inv1 = 1.0f / (lsum[2*mf + 1] + ATTN_EPS);
        const size_t base0 = (size_t)(b * SEQ + qstart + w * 32 + mf * 16 + gq) * INNER
                           + h * 64 + t4 * 2;
        const size_t base1 = base0 + (size_t)8 * INNER;
        #pragma unroll
        for (int nd = 0; nd < 8; nd++) {
            *(uint32_t*)(goh + base0 + nd * 8) = pack2(o[mf][nd][0] * inv0,
                                                       o[mf][nd][1] * inv0);
            *(uint32_t*)(goh + base1 + nd * 8) = pack2(o[mf][nd][2] * inv1,
                                                       o[mf][nd][3] * inv1);
        }
    }
}

// ---------------------------------------------------------------------------
// Launch
// ---------------------------------------------------------------------------
extern "C" void kernel_launch(void* const* d_in, const int* in_sizes, int n_in,
                              void* d_out, int out_size)
{
    const float* x   = (const float*)d_in[0];
    const float* Wq  = (const float*)d_in[1];
    const float* Wkv = (const float*)d_in[2];
    const float* Wo  = (const float*)d_in[3];
    const float* bo  = (const float*)d_in[4];
    float* out = (float*)d_out;

    __half *pxh, *pw1, *pwo, *pqkv, *path;
    cudaGetSymbolAddress((void**)&pxh,  g_xh);
    cudaGetSymbolAddress((void**)&pw1,  g_w1);
    cudaGetSymbolAddress((void**)&pwo,  g_wot);
    cudaGetSymbolAddress((void**)&pqkv, g_qkv);
    cudaGetSymbolAddress((void**)&path, g_ath);

    cudaFuncSetAttribute(gemm_qkv,
                         cudaFuncAttributeMaxDynamicSharedMemorySize, GEMM1_SMEM);
    cudaFuncSetAttribute(gemm_out,
                         cudaFuncAttributeMaxDynamicSharedMemorySize, GEMM1_SMEM);
    cudaFuncSetAttribute(attn_mma,
                         cudaFuncAttributeMaxDynamicSharedMemorySize, AT_SMEM);

    // --- fused prep: x -> fp16 + all three weight transposes, one launch ---
    prep_kernel<<<PREP_TOTAL_BLOCKS, 256>>>(x, pxh, Wq, Wkv, Wo, pw1, pwo);

    // --- merged projection: q|k|v fp16 (q pre-scaled by 0.125) ---
    gemm_qkv<<<dim3(QKVW / 128, ROWS / 128), 256, GEMM1_SMEM>>>(pxh, pw1, pqkv);

    // --- attention (S 1-term, PV 1-term, fp16 out) ---
    attn_mma<<<dim3(SEQ / 128, BATCH * HEADS), 128, AT_SMEM>>>(pqkv, path);

    // --- out = att @ Wo + bo (1-term) ---
    gemm_out<<<dim3(DMODEL / 128, ROWS / 128), 256, GEMM1_SMEM>>>(
        path, pwo, bo, out, DMODEL, INNER);
}